// round 1
// baseline (speedup 1.0000x reference)
#include <cuda_runtime.h>
#include <math.h>

#define CB 4
#define CT 2048
#define CD 1024
#define CK 512
#define CKR 16
#define CBT 8192   // CB*CT

// ---------------- scratch (static device globals; no allocs) ----------------
__device__ float g_Q[CBT*CD];
__device__ float g_V[CBT*CD];
__device__ float g_logits[CBT*CK];      // reused later for sim
__device__ float g_ctx[CBT*CD];
__device__ float g_scores[(size_t)CB*CT*CT];
__device__ float g_byp[CBT*CD];
__device__ float g_instr[CBT];
__device__ float g_nov[CBT];
__device__ float g_vnorm[CBT];
__device__ float g_rw[CBT*CK];
__device__ float g_Sn[CK*CD];
__device__ float g_Vagg[CB*CK*CD];
__device__ float g_T1[CB*CK*CK];
__device__ float g_cov[CK*CK];
__device__ float g_Mm[CK*CD];
__device__ float g_wt[CT];

// ---------------- generic SGEMM: C = beta*C + alpha*op(A)op(B) (+bias) ------
// BM=BN=128, BK=8, 256 threads, 8x8 per-thread tile. All M,N multiples of 128,
// K multiples of 8 (guaranteed by problem dims). causal: 1 = skip tiles fully
// above diagonal (scores), 2 = limit K loop to bm+128 (P@V).
template<bool TA, bool TB>
__global__ void __launch_bounds__(256) sgemm_kernel(
    const float* __restrict__ A, const float* __restrict__ B,
    float* __restrict__ C, const float* __restrict__ bias,
    int M, int N, int Kd, int lda, int ldb, int ldc,
    long long sA, long long sB, long long sC,
    float alpha, float beta, int causal)
{
    const int bm = blockIdx.y * 128;
    const int bn = blockIdx.x * 128;
    if (causal == 1 && bn > bm + 127) return;
    A += sA * blockIdx.z;
    B += sB * blockIdx.z;
    C += sC * blockIdx.z;
    const int kend = (causal == 2) ? min(Kd, bm + 128) : Kd;

    __shared__ float As[8][128];
    __shared__ float Bs[8][128];
    const int tid = threadIdx.x;
    const int tx = tid & 15, ty = tid >> 4;

    float acc[8][8];
#pragma unroll
    for (int i = 0; i < 8; i++)
#pragma unroll
        for (int j = 0; j < 8; j++) acc[i][j] = 0.f;

    for (int k0 = 0; k0 < kend; k0 += 8) {
        if (!TA) {
#pragma unroll
            for (int i = 0; i < 4; i++) {
                int e = tid + 256 * i;
                As[e & 7][e >> 3] = A[(size_t)(bm + (e >> 3)) * lda + k0 + (e & 7)];
            }
        } else {
#pragma unroll
            for (int i = 0; i < 4; i++) {
                int e = tid + 256 * i;
                As[e >> 7][e & 127] = A[(size_t)(k0 + (e >> 7)) * lda + bm + (e & 127)];
            }
        }
        if (!TB) {
#pragma unroll
            for (int i = 0; i < 4; i++) {
                int e = tid + 256 * i;
                Bs[e >> 7][e & 127] = B[(size_t)(k0 + (e >> 7)) * ldb + bn + (e & 127)];
            }
        } else {
#pragma unroll
            for (int i = 0; i < 4; i++) {
                int e = tid + 256 * i;
                Bs[e & 7][e >> 3] = B[(size_t)(bn + (e >> 3)) * ldb + k0 + (e & 7)];
            }
        }
        __syncthreads();
#pragma unroll
        for (int kk = 0; kk < 8; kk++) {
            float a[8], b[8];
#pragma unroll
            for (int i = 0; i < 8; i++) a[i] = As[kk][ty * 8 + i];
#pragma unroll
            for (int j = 0; j < 8; j++) b[j] = Bs[kk][tx * 8 + j];
#pragma unroll
            for (int i = 0; i < 8; i++)
#pragma unroll
                for (int j = 0; j < 8; j++)
                    acc[i][j] = fmaf(a[i], b[j], acc[i][j]);
        }
        __syncthreads();
    }
#pragma unroll
    for (int i = 0; i < 8; i++) {
        int m = bm + ty * 8 + i;
#pragma unroll
        for (int j = 0; j < 8; j++) {
            int n = bn + tx * 8 + j;
            float v = alpha * acc[i][j];
            if (beta != 0.f) v += beta * C[(size_t)m * ldc + n];
            if (bias) v += bias[n];
            C[(size_t)m * ldc + n] = v;
        }
    }
}

// ---------------- top-16 read + softmax + context (warp per row) ------------
__global__ void topk_ctx_kernel(const float* __restrict__ logits,
                                const float* __restrict__ S,
                                float* __restrict__ ctx)
{
    int m = blockIdx.x * 8 + threadIdx.y;
    int lane = threadIdx.x;
    const float* lrow = logits + (size_t)m * CK;
    float v[16];
#pragma unroll
    for (int i = 0; i < 16; i++) v[i] = lrow[i * 32 + lane];
    float topv[CKR]; int topi[CKR];
    for (int it = 0; it < CKR; it++) {
        float bv = -INFINITY; int bi = 0x7fffffff;
#pragma unroll
        for (int i = 0; i < 16; i++) {
            if (v[i] > bv) { bv = v[i]; bi = i * 32 + lane; }
        }
#pragma unroll
        for (int off = 16; off > 0; off >>= 1) {
            float ov = __shfl_xor_sync(0xffffffffu, bv, off);
            int   oi = __shfl_xor_sync(0xffffffffu, bi, off);
            if (ov > bv || (ov == bv && oi < bi)) { bv = ov; bi = oi; }
        }
        topv[it] = bv; topi[it] = bi;
        if ((bi & 31) == lane) v[bi >> 5] = -INFINITY;
    }
    float p[CKR]; float s = 0.f;
#pragma unroll
    for (int i = 0; i < CKR; i++) { p[i] = expf(topv[i] - topv[0]); s += p[i]; }
    float inv = 1.f / s;
    float* crow = ctx + (size_t)m * CD;
    for (int d = lane; d < CD; d += 32) {
        float acc = 0.f;
#pragma unroll
        for (int i = 0; i < CKR; i++)
            acc += p[i] * S[(size_t)topi[i] * CD + d];
        crow[d] = acc * inv;
    }
}

// ---------------- instruction gate: sigmoid(Q.Wm + bm) ----------------------
__global__ void instr_kernel(const float* __restrict__ Q,
                             const float* __restrict__ Wm,
                             const float* __restrict__ bm_,
                             float* __restrict__ instr)
{
    int m = blockIdx.x * 8 + threadIdx.y;
    int lane = threadIdx.x;
    const float* q = Q + (size_t)m * CD;
    float s = 0.f;
    for (int d = lane; d < CD; d += 32) s = fmaf(q[d], Wm[d], s);
#pragma unroll
    for (int off = 16; off > 0; off >>= 1) s += __shfl_xor_sync(0xffffffffu, s, off);
    if (lane == 0) instr[m] = 1.f / (1.f + expf(-(s + bm_[0])));
}

// ---------------- causal row softmax in place -------------------------------
__global__ void softmax_causal_kernel(float* __restrict__ P)
{
    int b = blockIdx.y, q = blockIdx.x;
    float* row = P + ((size_t)b * CT + q) * CT;
    int n = q + 1;
    int tid = threadIdx.x;
    __shared__ float red[256];
    float mx = -INFINITY;
    for (int k = tid; k < n; k += 256) mx = fmaxf(mx, row[k]);
    red[tid] = mx; __syncthreads();
    for (int s = 128; s > 0; s >>= 1) { if (tid < s) red[tid] = fmaxf(red[tid], red[tid + s]); __syncthreads(); }
    mx = red[0]; __syncthreads();
    float sum = 0.f;
    for (int k = tid; k < n; k += 256) { float e = expf(row[k] - mx); row[k] = e; sum += e; }
    red[tid] = sum; __syncthreads();
    for (int s = 128; s > 0; s >>= 1) { if (tid < s) red[tid] += red[tid + s]; __syncthreads(); }
    float inv = 1.f / red[0];
    for (int k = tid; k < n; k += 256) row[k] *= inv;
    for (int k = n + tid; k < CT; k += 256) row[k] = 0.f;
}

// ---------------- elementwise combine: out = (1-p)*ctx + p*byp --------------
__global__ void combine_kernel(const float* __restrict__ ctx, const float* __restrict__ byp,
                               const float* __restrict__ instr, float* __restrict__ out)
{
    size_t i = (size_t)blockIdx.x * blockDim.x + threadIdx.x;
    if (i >= (size_t)CBT * CD) return;
    float p = instr[i / CD];
    out[i] = (1.f - p) * ctx[i] + p * byp[i];
}

// ---------------- row-normalize S -> Sn -------------------------------------
__global__ void sn_kernel(const float* __restrict__ S, float* __restrict__ Sn)
{
    int r = blockIdx.x * 8 + threadIdx.y;
    int lane = threadIdx.x;
    const float* row = S + (size_t)r * CD;
    float s = 0.f;
    for (int d = lane; d < CD; d += 32) { float v = row[d]; s = fmaf(v, v, s); }
#pragma unroll
    for (int off = 16; off > 0; off >>= 1) s += __shfl_xor_sync(0xffffffffu, s, off);
    float inv = 1.f / fmaxf(sqrtf(s), 1e-8f);
    for (int d = lane; d < CD; d += 32) Sn[(size_t)r * CD + d] = row[d] * inv;
}

// ---------------- V row norms ------------------------------------------------
__global__ void vnorm_kernel(const float* __restrict__ V, float* __restrict__ vn)
{
    int m = blockIdx.x * 8 + threadIdx.y;
    int lane = threadIdx.x;
    const float* row = V + (size_t)m * CD;
    float s = 0.f;
    for (int d = lane; d < CD; d += 32) { float v = row[d]; s = fmaf(v, v, s); }
#pragma unroll
    for (int off = 16; off > 0; off >>= 1) s += __shfl_xor_sync(0xffffffffu, s, off);
    if (lane == 0) vn[m] = sqrtf(s);
}

// ---------------- novelty = 1 - rowmax(sim)/max(|V|,eps) --------------------
__global__ void novelty_kernel(const float* __restrict__ sim, const float* __restrict__ vn,
                               float* __restrict__ nov)
{
    int m = blockIdx.x * 8 + threadIdx.y;
    int lane = threadIdx.x;
    const float* row = sim + (size_t)m * CK;
    float mx = -INFINITY;
    for (int k = lane; k < CK; k += 32) mx = fmaxf(mx, row[k]);
#pragma unroll
    for (int off = 16; off > 0; off >>= 1) mx = fmaxf(mx, __shfl_xor_sync(0xffffffffu, mx, off));
    if (lane == 0) nov[m] = 1.f - mx / fmaxf(vn[m], 1e-8f);
}

// ---------------- decay weights ---------------------------------------------
__global__ void wt_kernel(float* __restrict__ wt)
{
    int t = blockIdx.x * 256 + threadIdx.x;
    if (t >= CT) return;
    float denom = 1.f - powf(0.99f, (float)CT);
    wt[t] = powf(0.99f, (float)(CT - 1 - t)) * (0.01f / denom);
}

// ---------------- r_write epilogue: sigmoid(lin + nov*w0 + b) * wt[t] -------
__global__ void rw_epi_kernel(float* __restrict__ rw, const float* __restrict__ nov,
                              const float* __restrict__ Wn, const float* __restrict__ bn,
                              const float* __restrict__ wt)
{
    size_t i = (size_t)blockIdx.x * blockDim.x + threadIdx.x;
    if (i >= (size_t)CBT * CK) return;
    int m = (int)(i / CK), k = (int)(i % CK);
    float x = rw[i] + nov[m] * Wn[(size_t)k * (CD + 1)] + bn[k];
    rw[i] = (1.f / (1.f + expf(-x))) * wt[m % CT];
}

// ---------------- add eps*I to S_cov ----------------------------------------
__global__ void diag_eps_kernel(float* __restrict__ cov)
{
    int k = blockIdx.x * 256 + threadIdx.x;
    if (k < CK) cov[(size_t)k * CK + k] += 1e-5f;
}

// ---------------- Cholesky diagonal block (in-place, global, 1 block) -------
__global__ void chol_diag_kernel(float* __restrict__ Am, int j)
{
    float* A = Am + (size_t)(j * 128) * CK + j * 128;   // ld = CK
    int tid = threadIdx.x;
    for (int p = 0; p < 128; p++) {
        if (tid == 0) A[(size_t)p * CK + p] = sqrtf(A[(size_t)p * CK + p]);
        __syncthreads();
        float d = A[(size_t)p * CK + p];
        for (int r = p + 1 + tid; r < 128; r += 256) A[(size_t)r * CK + p] /= d;
        __syncthreads();
        int w = 127 - p;
        for (int idx = tid; idx < w * w; idx += 256) {
            int r = p + 1 + idx / w;
            int c = p + 1 + idx % w;
            A[(size_t)r * CK + c] -= A[(size_t)r * CK + p] * A[(size_t)c * CK + p];
        }
        __syncthreads();
    }
}

// ---------------- panel solve: rows below solve x*L_jj^T = a (thread/row) ---
__global__ void chol_trsm_kernel(float* __restrict__ Am, int j)
{
    int i = (j + 1) * 128 + blockIdx.x * 128 + threadIdx.x;
    const float* L = Am + (size_t)(j * 128) * CK + j * 128;
    float* row = Am + (size_t)i * CK + j * 128;
    float x[128];
    for (int c = 0; c < 128; c++) {
        float v = row[c];
        float s0 = 0.f, s1 = 0.f, s2 = 0.f, s3 = 0.f;
        const float* Lr = L + (size_t)c * CK;
        int q = 0;
        for (; q + 4 <= c; q += 4) {
            s0 = fmaf(Lr[q], x[q], s0);   s1 = fmaf(Lr[q + 1], x[q + 1], s1);
            s2 = fmaf(Lr[q + 2], x[q + 2], s2); s3 = fmaf(Lr[q + 3], x[q + 3], s3);
        }
        for (; q < c; q++) s0 = fmaf(Lr[q], x[q], s0);
        v -= (s0 + s1) + (s2 + s3);
        x[c] = v / Lr[c];
        row[c] = x[c];
    }
}

// ---------------- forward substitution on 128-row block of Z (thread/col) ---
__global__ void trisolve_fwd_kernel(const float* __restrict__ Am, float* __restrict__ Zm, int j)
{
    int col = blockIdx.x * 128 + threadIdx.x;
    const float* L = Am + (size_t)(j * 128) * CK + j * 128;
    float* Z = Zm + (size_t)(j * 128) * CD;
    float x[128];
    for (int p = 0; p < 128; p++) {
        float v = Z[(size_t)p * CD + col];
        const float* Lr = L + (size_t)p * CK;
        float s0 = 0.f, s1 = 0.f, s2 = 0.f, s3 = 0.f;
        int q = 0;
        for (; q + 4 <= p; q += 4) {
            s0 = fmaf(Lr[q], x[q], s0);   s1 = fmaf(Lr[q + 1], x[q + 1], s1);
            s2 = fmaf(Lr[q + 2], x[q + 2], s2); s3 = fmaf(Lr[q + 3], x[q + 3], s3);
        }
        for (; q < p; q++) s0 = fmaf(Lr[q], x[q], s0);
        v -= (s0 + s1) + (s2 + s3);
        x[p] = v / Lr[p];
        Z[(size_t)p * CD + col] = x[p];
    }
}

// ---------------- backward substitution (L^T) on 128-row block --------------
__global__ void trisolve_bwd_kernel(const float* __restrict__ Am, float* __restrict__ Zm, int j)
{
    int col = blockIdx.x * 128 + threadIdx.x;
    const float* L = Am + (size_t)(j * 128) * CK + j * 128;
    float* Z = Zm + (size_t)(j * 128) * CD;
    float x[128];
    for (int p = 127; p >= 0; p--) {
        float v = Z[(size_t)p * CD + col];
        float s0 = 0.f, s1 = 0.f;
        int q = p + 1;
        for (; q + 2 <= 128; q += 2) {
            s0 = fmaf(L[(size_t)q * CK + p], x[q], s0);
            s1 = fmaf(L[(size_t)(q + 1) * CK + p], x[q + 1], s1);
        }
        for (; q < 128; q++) s0 = fmaf(L[(size_t)q * CK + p], x[q], s0);
        v -= s0 + s1;
        x[p] = v / L[(size_t)p * CK + p];
        Z[(size_t)p * CD + col] = x[p];
    }
}

// ---------------- misc small kernels ----------------------------------------
__global__ void copy_kernel(const float* __restrict__ a, float* __restrict__ b, int n)
{
    int i = blockIdx.x * 256 + threadIdx.x;
    if (i < n) b[i] = a[i];
}

__global__ void init_out2_kernel(const float* __restrict__ S, const float* __restrict__ Vagg,
                                 float* __restrict__ out2)
{
    size_t i = (size_t)blockIdx.x * blockDim.x + threadIdx.x;
    if (i >= (size_t)CB * CK * CD) return;
    size_t kd = i % ((size_t)CK * CD);
    out2[i] = 0.99f * S[kd] + 0.1f * Vagg[i];
}

// ---------------- host launcher ---------------------------------------------
static void sgemm(bool TA, bool TB, const float* A, const float* B, float* C, const float* bias,
                  int M, int N, int Kd, int lda, int ldb, int ldc,
                  long long sA, long long sB, long long sC, int batch,
                  float alpha, float beta, int causal)
{
    dim3 grid(N / 128, M / 128, batch), block(256);
    if (!TA && !TB) sgemm_kernel<false, false><<<grid, block>>>(A, B, C, bias, M, N, Kd, lda, ldb, ldc, sA, sB, sC, alpha, beta, causal);
    else if (!TA && TB) sgemm_kernel<false, true><<<grid, block>>>(A, B, C, bias, M, N, Kd, lda, ldb, ldc, sA, sB, sC, alpha, beta, causal);
    else if (TA && !TB) sgemm_kernel<true, false><<<grid, block>>>(A, B, C, bias, M, N, Kd, lda, ldb, ldc, sA, sB, sC, alpha, beta, causal);
    else sgemm_kernel<true, true><<<grid, block>>>(A, B, C, bias, M, N, Kd, lda, ldb, ldc, sA, sB, sC, alpha, beta, causal);
}

extern "C" void kernel_launch(void* const* d_in, const int* in_sizes, int n_in,
                              void* d_out, int out_size)
{
    const float* x    = (const float*)d_in[0];
    const float* S    = (const float*)d_in[1];
    const float* Wq_w = (const float*)d_in[2];
    const float* Wq_b = (const float*)d_in[3];
    const float* Wv_w = (const float*)d_in[4];
    const float* Wv_b = (const float*)d_in[5];
    const float* Wn_w = (const float*)d_in[6];
    const float* Wn_b = (const float*)d_in[7];
    const float* Wm_w = (const float*)d_in[8];
    const float* Wm_b = (const float*)d_in[9];
    float* out  = (float*)d_out;                 // [B,T,D]
    float* out2 = out + (size_t)CBT * CD;        // [B,K,D] = S_next

    float *Q, *V, *logits, *ctx, *scores, *byp, *instr, *nov, *vn, *rw, *Sn, *Vagg, *T1, *cov, *Mm, *wt;
    cudaGetSymbolAddress((void**)&Q,      g_Q);
    cudaGetSymbolAddress((void**)&V,      g_V);
    cudaGetSymbolAddress((void**)&logits, g_logits);
    cudaGetSymbolAddress((void**)&ctx,    g_ctx);
    cudaGetSymbolAddress((void**)&scores, g_scores);
    cudaGetSymbolAddress((void**)&byp,    g_byp);
    cudaGetSymbolAddress((void**)&instr,  g_instr);
    cudaGetSymbolAddress((void**)&nov,    g_nov);
    cudaGetSymbolAddress((void**)&vn,     g_vnorm);
    cudaGetSymbolAddress((void**)&rw,     g_rw);
    cudaGetSymbolAddress((void**)&Sn,     g_Sn);
    cudaGetSymbolAddress((void**)&Vagg,   g_Vagg);
    cudaGetSymbolAddress((void**)&T1,     g_T1);
    cudaGetSymbolAddress((void**)&cov,    g_cov);
    cudaGetSymbolAddress((void**)&Mm,     g_Mm);
    cudaGetSymbolAddress((void**)&wt,     g_wt);

    const float inv_sqrt_d = 0.03125f;   // 1/sqrt(1024)

    // 1. Q = x Wq^T + bq ; V = x Wv^T + bv
    sgemm(false, true, x, Wq_w, Q, Wq_b, CBT, CD, CD, CD, CD, CD, 0, 0, 0, 1, 1.f, 0.f, 0);
    sgemm(false, true, x, Wv_w, V, Wv_b, CBT, CD, CD, CD, CD, CD, 0, 0, 0, 1, 1.f, 0.f, 0);
    wt_kernel<<<CT / 256, 256>>>(wt);

    // 2. read logits = Q S^T / 32 ; top-16 softmax read -> context
    sgemm(false, true, Q, S, logits, nullptr, CBT, CK, CD, CD, CD, CK, 0, 0, 0, 1, inv_sqrt_d, 0.f, 0);
    topk_ctx_kernel<<<CBT / 8, dim3(32, 8)>>>(logits, S, ctx);
    instr_kernel<<<CBT / 8, dim3(32, 8)>>>(Q, Wm_w, Wm_b, instr);

    // 3. causal self-attention bypass (materialized P)
    sgemm(false, true, Q, Q, scores, nullptr, CT, CT, CD, CD, CD, CT,
          (long long)CT * CD, (long long)CT * CD, (long long)CT * CT, CB, inv_sqrt_d, 0.f, 1);
    softmax_causal_kernel<<<dim3(CT, CB), 256>>>(scores);
    sgemm(false, false, scores, V, byp, nullptr, CT, CD, CT, CT, CD, CD,
          (long long)CT * CT, (long long)CT * CD, (long long)CT * CD, CB, 1.f, 0.f, 2);
    combine_kernel<<<(CBT * CD + 255) / 256, 256>>>(ctx, byp, instr, out);

    // 4. novelty
    sn_kernel<<<CK / 8, dim3(32, 8)>>>(S, Sn);
    vnorm_kernel<<<CBT / 8, dim3(32, 8)>>>(V, vn);
    sgemm(false, true, V, Sn, logits, nullptr, CBT, CK, CD, CD, CD, CK, 0, 0, 0, 1, 1.f, 0.f, 0);
    novelty_kernel<<<CBT / 8, dim3(32, 8)>>>(logits, vn, nov);

    // 5. r_write (Q part via GEMM, novelty/bias/sigmoid/decay in epilogue)
    sgemm(false, true, Q, Wn_w + 1, rw, nullptr, CBT, CK, CD, CD, CD + 1, CK, 0, 0, 0, 1, 1.f, 0.f, 0);
    rw_epi_kernel<<<(CBT * CK + 255) / 256, 256>>>(rw, nov, Wn_w, Wn_b, wt);

    // 6. V_agg[b] = rw[b]^T V[b]
    sgemm(true, false, rw, V, Vagg, nullptr, CK, CD, CT, CK, CD, CD,
          (long long)CT * CK, (long long)CT * CD, (long long)CK * CD, CB, 1.f, 0.f, 0);

    // 7. S_cov = S S^T + eps I ; Cholesky (blocked NB=128)
    sgemm(false, true, S, S, cov, nullptr, CK, CK, CD, CD, CD, CK, 0, 0, 0, 1, 1.f, 0.f, 0);
    diag_eps_kernel<<<2, 256>>>(cov);
    for (int j = 0; j < 4; j++) {
        chol_diag_kernel<<<1, 256>>>(cov, j);
        if (j < 3) {
            chol_trsm_kernel<<<3 - j, 128>>>(cov, j);
            int s = (3 - j) * 128;
            float* Ct = cov + (size_t)(j + 1) * 128 * CK + (j + 1) * 128;
            const float* P = cov + (size_t)(j + 1) * 128 * CK + j * 128;
            sgemm(false, true, P, P, Ct, nullptr, s, s, 128, CK, CK, CK, 0, 0, 0, 1, -1.f, 1.f, 0);
        }
    }

    // 8. solve S_cov * Mm = S  (Mm = Cinv S)
    copy_kernel<<<(CK * CD + 255) / 256, 256>>>(S, Mm, CK * CD);
    for (int j = 0; j < 4; j++) {
        if (j > 0)
            sgemm(false, false, cov + (size_t)j * 128 * CK, Mm, Mm + (size_t)j * 128 * CD, nullptr,
                  128, CD, j * 128, CK, CD, CD, 0, 0, 0, 1, -1.f, 1.f, 0);
        trisolve_fwd_kernel<<<CD / 128, 128>>>(cov, Mm, j);
    }
    for (int j = 3; j >= 0; j--) {
        if (j < 3) {
            int s = (3 - j) * 128;
            sgemm(true, false, cov + (size_t)(j + 1) * 128 * CK + j * 128, Mm + (size_t)(j + 1) * 128 * CD,
                  Mm + (size_t)j * 128 * CD, nullptr, 128, CD, s, CK, CD, CD, 0, 0, 0, 1, -1.f, 1.f, 0);
        }
        trisolve_bwd_kernel<<<CD / 128, 128>>>(cov, Mm, j);
    }

    // 9. S_next = 0.99 S + 0.1 (V_agg - (V_agg S^T) Mm)
    sgemm(false, true, Vagg, S, T1, nullptr, CK, CK, CD, CD, CD, CK,
          (long long)CK * CD, 0, (long long)CK * CK, CB, 1.f, 0.f, 0);
    init_out2_kernel<<<(CB * CK * CD + 255) / 256, 256>>>(S, Vagg, out2);
    sgemm(false, false, T1, Mm, out2, nullptr, CK, CD, CK, CK, CD, CD,
          (long long)CK * CK, 0, (long long)CK * CD, CB, -0.1f, 1.f, 0);
}

// round 2
// speedup vs baseline: 1.2074x; 1.2074x over previous
#include <cuda_runtime.h>
#include <math.h>
#include <stdint.h>

#define CB 4
#define CT 2048
#define CD 1024
#define CK 512
#define CKR 16
#define CBT 8192   // CB*CT

// ---------------- scratch (static device globals; no allocs) ----------------
__device__ float g_Q[CBT*CD];
__device__ float g_V[CBT*CD];
__device__ float g_logits[CBT*CK];      // reused later for sim
__device__ float g_ctx[CBT*CD];
__device__ float g_scores[(size_t)CB*CT*CT];
__device__ float g_byp[CBT*CD];
__device__ float g_instr[CBT];
__device__ float g_nov[CBT];
__device__ float g_vnorm[CBT];
__device__ float g_rw[CBT*CK];
__device__ float g_Sn[CK*CD];
__device__ float g_Vagg[CB*CK*CD];
__device__ float g_T1[CB*CK*CK];
__device__ float g_cov[CK*CK];
__device__ float g_Mm[CK*CD];
__device__ float g_wt[CT];

// ---------------- tf32 helpers ----------------------------------------------
__device__ __forceinline__ uint32_t f2tf32(float x) {
    uint32_t r;
    asm("cvt.rna.tf32.f32 %0, %1;" : "=r"(r) : "f"(x));
    return r;
}

__device__ __forceinline__ void mma_tf32(float* c, const uint32_t* a, const uint32_t* b) {
    asm volatile(
        "mma.sync.aligned.m16n8k8.row.col.f32.tf32.tf32.f32 "
        "{%0,%1,%2,%3}, {%4,%5,%6,%7}, {%8,%9}, {%0,%1,%2,%3};"
        : "+f"(c[0]), "+f"(c[1]), "+f"(c[2]), "+f"(c[3])
        : "r"(a[0]), "r"(a[1]), "r"(a[2]), "r"(a[3]), "r"(b[0]), "r"(b[1]));
}

// ---------------- tensor-core GEMM: C = beta*C + alpha*op(A)op(B) (+bias) ---
// BM=BN=128, BK=16, 256 threads = 8 warps (2 M x 4 N), warp tile 64x32.
// PREC: split-tf32 (hi/lo, 3 mma passes) for ~fp32 accuracy.
// causal: 1 = skip blocks above diagonal (scores), 2 = limit K to bm+128 (P@V).
template<bool TA, bool TB, bool PREC>
__global__ void __launch_bounds__(256) tgemm_kernel(
    const float* __restrict__ A, const float* __restrict__ B,
    float* __restrict__ C, const float* __restrict__ bias,
    int M, int N, int Kd, int lda, int ldb, int ldc,
    long long sA, long long sB, long long sC,
    float alpha, float beta, int causal)
{
    const int bm = blockIdx.y * 128;
    const int bn = blockIdx.x * 128;
    if (causal == 1 && bn > bm + 127) return;
    A += sA * blockIdx.z;
    B += sB * blockIdx.z;
    C += sC * blockIdx.z;
    const int kend = (causal == 2) ? min(Kd, bm + 128) : Kd;

    __shared__ float Ah[16][136];
    __shared__ float Bh[16][136];
    __shared__ float Alo[16][136];
    __shared__ float Blo[16][136];

    const int tid = threadIdx.x;
    const int lane = tid & 31;
    const int wid = tid >> 5;
    const int warp_m = wid >> 2;      // 0..1
    const int warp_n = wid & 3;       // 0..3
    const int gid = lane >> 2;        // 0..7
    const int tig = lane & 3;         // 0..3
    const int mbase = warp_m * 64;
    const int nbase = warp_n * 32;

    float acc[4][4][4];
#pragma unroll
    for (int i = 0; i < 4; i++)
#pragma unroll
        for (int j = 0; j < 4; j++)
#pragma unroll
            for (int r = 0; r < 4; r++) acc[i][j][r] = 0.f;

    for (int k0 = 0; k0 < kend; k0 += 16) {
        // ---- global -> shared (with tf32 conversion; hi/lo split if PREC) ----
#pragma unroll
        for (int i = 0; i < 8; i++) {
            int e = tid + 256 * i;
            int m, k;
            float v;
            if (!TA) { m = e >> 4; k = e & 15; v = A[(size_t)(bm + m) * lda + k0 + k]; }
            else     { k = e >> 7; m = e & 127; v = A[(size_t)(k0 + k) * lda + bm + m]; }
            uint32_t hb = f2tf32(v);
            float hf = __uint_as_float(hb);
            Ah[k][m] = hf;
            if (PREC) Alo[k][m] = __uint_as_float(f2tf32(v - hf));
        }
#pragma unroll
        for (int i = 0; i < 8; i++) {
            int e = tid + 256 * i;
            int n, k;
            float v;
            if (!TB) { k = e >> 7; n = e & 127; v = B[(size_t)(k0 + k) * ldb + bn + n]; }
            else     { n = e >> 4; k = e & 15; v = B[(size_t)(bn + n) * ldb + k0 + k]; }
            uint32_t hb = f2tf32(v);
            float hf = __uint_as_float(hb);
            Bh[k][n] = hf;
            if (PREC) Blo[k][n] = __uint_as_float(f2tf32(v - hf));
        }
        __syncthreads();

#pragma unroll
        for (int ks = 0; ks < 2; ks++) {
            const int k8 = ks * 8;
            uint32_t af[4][4], bf[4][2];
            uint32_t afl[4][4], bfl[4][2];
#pragma unroll
            for (int mi = 0; mi < 4; mi++) {
                int r = mbase + mi * 16;
                af[mi][0] = __float_as_uint(Ah[k8 + tig][r + gid]);
                af[mi][1] = __float_as_uint(Ah[k8 + tig][r + gid + 8]);
                af[mi][2] = __float_as_uint(Ah[k8 + tig + 4][r + gid]);
                af[mi][3] = __float_as_uint(Ah[k8 + tig + 4][r + gid + 8]);
                if (PREC) {
                    afl[mi][0] = __float_as_uint(Alo[k8 + tig][r + gid]);
                    afl[mi][1] = __float_as_uint(Alo[k8 + tig][r + gid + 8]);
                    afl[mi][2] = __float_as_uint(Alo[k8 + tig + 4][r + gid]);
                    afl[mi][3] = __float_as_uint(Alo[k8 + tig + 4][r + gid + 8]);
                }
            }
#pragma unroll
            for (int ni = 0; ni < 4; ni++) {
                int c = nbase + ni * 8;
                bf[ni][0] = __float_as_uint(Bh[k8 + tig][c + gid]);
                bf[ni][1] = __float_as_uint(Bh[k8 + tig + 4][c + gid]);
                if (PREC) {
                    bfl[ni][0] = __float_as_uint(Blo[k8 + tig][c + gid]);
                    bfl[ni][1] = __float_as_uint(Blo[k8 + tig + 4][c + gid]);
                }
            }
#pragma unroll
            for (int mi = 0; mi < 4; mi++)
#pragma unroll
                for (int ni = 0; ni < 4; ni++) {
                    mma_tf32(acc[mi][ni], af[mi], bf[ni]);
                    if (PREC) {
                        mma_tf32(acc[mi][ni], af[mi], bfl[ni]);
                        mma_tf32(acc[mi][ni], afl[mi], bf[ni]);
                    }
                }
        }
        __syncthreads();
    }

    // ---- epilogue ----
#pragma unroll
    for (int mi = 0; mi < 4; mi++) {
        int row0 = bm + mbase + mi * 16 + gid;
        int row1 = row0 + 8;
#pragma unroll
        for (int ni = 0; ni < 4; ni++) {
            int col = bn + nbase + ni * 8 + 2 * tig;
            float v0 = alpha * acc[mi][ni][0];
            float v1 = alpha * acc[mi][ni][1];
            float v2 = alpha * acc[mi][ni][2];
            float v3 = alpha * acc[mi][ni][3];
            if (beta != 0.f) {
                v0 += beta * C[(size_t)row0 * ldc + col];
                v1 += beta * C[(size_t)row0 * ldc + col + 1];
                v2 += beta * C[(size_t)row1 * ldc + col];
                v3 += beta * C[(size_t)row1 * ldc + col + 1];
            }
            if (bias) {
                v0 += bias[col]; v1 += bias[col + 1];
                v2 += bias[col]; v3 += bias[col + 1];
            }
            C[(size_t)row0 * ldc + col]     = v0;
            C[(size_t)row0 * ldc + col + 1] = v1;
            C[(size_t)row1 * ldc + col]     = v2;
            C[(size_t)row1 * ldc + col + 1] = v3;
        }
    }
}

// ---------------- top-16 read + softmax + context (warp per row) ------------
__global__ void topk_ctx_kernel(const float* __restrict__ logits,
                                const float* __restrict__ S,
                                float* __restrict__ ctx)
{
    int m = blockIdx.x * 8 + threadIdx.y;
    int lane = threadIdx.x;
    const float* lrow = logits + (size_t)m * CK;
    float v[16];
#pragma unroll
    for (int i = 0; i < 16; i++) v[i] = lrow[i * 32 + lane];
    float topv[CKR]; int topi[CKR];
    for (int it = 0; it < CKR; it++) {
        float bv = -INFINITY; int bi = 0x7fffffff;
#pragma unroll
        for (int i = 0; i < 16; i++) {
            if (v[i] > bv) { bv = v[i]; bi = i * 32 + lane; }
        }
#pragma unroll
        for (int off = 16; off > 0; off >>= 1) {
            float ov = __shfl_xor_sync(0xffffffffu, bv, off);
            int   oi = __shfl_xor_sync(0xffffffffu, bi, off);
            if (ov > bv || (ov == bv && oi < bi)) { bv = ov; bi = oi; }
        }
        topv[it] = bv; topi[it] = bi;
        if ((bi & 31) == lane) v[bi >> 5] = -INFINITY;
    }
    float p[CKR]; float s = 0.f;
#pragma unroll
    for (int i = 0; i < CKR; i++) { p[i] = expf(topv[i] - topv[0]); s += p[i]; }
    float inv = 1.f / s;
    float* crow = ctx + (size_t)m * CD;
    for (int d = lane; d < CD; d += 32) {
        float acc = 0.f;
#pragma unroll
        for (int i = 0; i < CKR; i++)
            acc += p[i] * S[(size_t)topi[i] * CD + d];
        crow[d] = acc * inv;
    }
}

// ---------------- instruction gate: sigmoid(Q.Wm + bm) ----------------------
__global__ void instr_kernel(const float* __restrict__ Q,
                             const float* __restrict__ Wm,
                             const float* __restrict__ bm_,
                             float* __restrict__ instr)
{
    int m = blockIdx.x * 8 + threadIdx.y;
    int lane = threadIdx.x;
    const float* q = Q + (size_t)m * CD;
    float s = 0.f;
    for (int d = lane; d < CD; d += 32) s = fmaf(q[d], Wm[d], s);
#pragma unroll
    for (int off = 16; off > 0; off >>= 1) s += __shfl_xor_sync(0xffffffffu, s, off);
    if (lane == 0) instr[m] = 1.f / (1.f + expf(-(s + bm_[0])));
}

// ---------------- causal row softmax in place -------------------------------
__global__ void softmax_causal_kernel(float* __restrict__ P)
{
    int b = blockIdx.y, q = blockIdx.x;
    float* row = P + ((size_t)b * CT + q) * CT;
    int n = q + 1;
    int tid = threadIdx.x;
    __shared__ float red[256];
    float mx = -INFINITY;
    for (int k = tid; k < n; k += 256) mx = fmaxf(mx, row[k]);
    red[tid] = mx; __syncthreads();
    for (int s = 128; s > 0; s >>= 1) { if (tid < s) red[tid] = fmaxf(red[tid], red[tid + s]); __syncthreads(); }
    mx = red[0]; __syncthreads();
    float sum = 0.f;
    for (int k = tid; k < n; k += 256) { float e = expf(row[k] - mx); row[k] = e; sum += e; }
    red[tid] = sum; __syncthreads();
    for (int s = 128; s > 0; s >>= 1) { if (tid < s) red[tid] += red[tid + s]; __syncthreads(); }
    float inv = 1.f / red[0];
    for (int k = tid; k < n; k += 256) row[k] *= inv;
    for (int k = n + tid; k < CT; k += 256) row[k] = 0.f;
}

// ---------------- elementwise combine: out = (1-p)*ctx + p*byp --------------
__global__ void combine_kernel(const float* __restrict__ ctx, const float* __restrict__ byp,
                               const float* __restrict__ instr, float* __restrict__ out)
{
    size_t i = (size_t)blockIdx.x * blockDim.x + threadIdx.x;
    if (i >= (size_t)CBT * CD) return;
    float p = instr[i / CD];
    out[i] = (1.f - p) * ctx[i] + p * byp[i];
}

// ---------------- row-normalize S -> Sn -------------------------------------
__global__ void sn_kernel(const float* __restrict__ S, float* __restrict__ Sn)
{
    int r = blockIdx.x * 8 + threadIdx.y;
    int lane = threadIdx.x;
    const float* row = S + (size_t)r * CD;
    float s = 0.f;
    for (int d = lane; d < CD; d += 32) { float v = row[d]; s = fmaf(v, v, s); }
#pragma unroll
    for (int off = 16; off > 0; off >>= 1) s += __shfl_xor_sync(0xffffffffu, s, off);
    float inv = 1.f / fmaxf(sqrtf(s), 1e-8f);
    for (int d = lane; d < CD; d += 32) Sn[(size_t)r * CD + d] = row[d] * inv;
}

// ---------------- V row norms ------------------------------------------------
__global__ void vnorm_kernel(const float* __restrict__ V, float* __restrict__ vn)
{
    int m = blockIdx.x * 8 + threadIdx.y;
    int lane = threadIdx.x;
    const float* row = V + (size_t)m * CD;
    float s = 0.f;
    for (int d = lane; d < CD; d += 32) { float v = row[d]; s = fmaf(v, v, s); }
#pragma unroll
    for (int off = 16; off > 0; off >>= 1) s += __shfl_xor_sync(0xffffffffu, s, off);
    if (lane == 0) vn[m] = sqrtf(s);
}

// ---------------- novelty = 1 - rowmax(sim)/max(|V|,eps) --------------------
__global__ void novelty_kernel(const float* __restrict__ sim, const float* __restrict__ vn,
                               float* __restrict__ nov)
{
    int m = blockIdx.x * 8 + threadIdx.y;
    int lane = threadIdx.x;
    const float* row = sim + (size_t)m * CK;
    float mx = -INFINITY;
    for (int k = lane; k < CK; k += 32) mx = fmaxf(mx, row[k]);
#pragma unroll
    for (int off = 16; off > 0; off >>= 1) mx = fmaxf(mx, __shfl_xor_sync(0xffffffffu, mx, off));
    if (lane == 0) nov[m] = 1.f - mx / fmaxf(vn[m], 1e-8f);
}

// ---------------- decay weights ---------------------------------------------
__global__ void wt_kernel(float* __restrict__ wt)
{
    int t = blockIdx.x * 256 + threadIdx.x;
    if (t >= CT) return;
    float denom = 1.f - powf(0.99f, (float)CT);
    wt[t] = powf(0.99f, (float)(CT - 1 - t)) * (0.01f / denom);
}

// ---------------- r_write epilogue: sigmoid(lin + nov*w0 + b) * wt[t] -------
__global__ void rw_epi_kernel(float* __restrict__ rw, const float* __restrict__ nov,
                              const float* __restrict__ Wn, const float* __restrict__ bn,
                              const float* __restrict__ wt)
{
    size_t i = (size_t)blockIdx.x * blockDim.x + threadIdx.x;
    if (i >= (size_t)CBT * CK) return;
    int m = (int)(i / CK), k = (int)(i % CK);
    float x = rw[i] + nov[m] * Wn[(size_t)k * (CD + 1)] + bn[k];
    rw[i] = (1.f / (1.f + expf(-x))) * wt[m % CT];
}

// ---------------- add eps*I to S_cov ----------------------------------------
__global__ void diag_eps_kernel(float* __restrict__ cov)
{
    int k = blockIdx.x * 256 + threadIdx.x;
    if (k < CK) cov[(size_t)k * CK + k] += 1e-5f;
}

// ---------------- Cholesky diagonal block (in-place, global, 1 block) -------
__global__ void chol_diag_kernel(float* __restrict__ Am, int j)
{
    float* A = Am + (size_t)(j * 128) * CK + j * 128;   // ld = CK
    int tid = threadIdx.x;
    for (int p = 0; p < 128; p++) {
        if (tid == 0) A[(size_t)p * CK + p] = sqrtf(A[(size_t)p * CK + p]);
        __syncthreads();
        float d = A[(size_t)p * CK + p];
        for (int r = p + 1 + tid; r < 128; r += 256) A[(size_t)r * CK + p] /= d;
        __syncthreads();
        int w = 127 - p;
        for (int idx = tid; idx < w * w; idx += 256) {
            int r = p + 1 + idx / w;
            int c = p + 1 + idx % w;
            A[(size_t)r * CK + c] -= A[(size_t)r * CK + p] * A[(size_t)c * CK + p];
        }
        __syncthreads();
    }
}

// ---------------- panel solve: rows below solve x*L_jj^T = a (thread/row) ---
__global__ void chol_trsm_kernel(float* __restrict__ Am, int j)
{
    int i = (j + 1) * 128 + blockIdx.x * 128 + threadIdx.x;
    const float* L = Am + (size_t)(j * 128) * CK + j * 128;
    float* row = Am + (size_t)i * CK + j * 128;
    float x[128];
    for (int c = 0; c < 128; c++) {
        float v = row[c];
        float s0 = 0.f, s1 = 0.f, s2 = 0.f, s3 = 0.f;
        const float* Lr = L + (size_t)c * CK;
        int q = 0;
        for (; q + 4 <= c; q += 4) {
            s0 = fmaf(Lr[q], x[q], s0);   s1 = fmaf(Lr[q + 1], x[q + 1], s1);
            s2 = fmaf(Lr[q + 2], x[q + 2], s2); s3 = fmaf(Lr[q + 3], x[q + 3], s3);
        }
        for (; q < c; q++) s0 = fmaf(Lr[q], x[q], s0);
        v -= (s0 + s1) + (s2 + s3);
        x[c] = v / Lr[c];
        row[c] = x[c];
    }
}

// ---------------- forward substitution on 128-row block of Z (thread/col) ---
__global__ void trisolve_fwd_kernel(const float* __restrict__ Am, float* __restrict__ Zm, int j)
{
    int col = blockIdx.x * 128 + threadIdx.x;
    const float* L = Am + (size_t)(j * 128) * CK + j * 128;
    float* Z = Zm + (size_t)(j * 128) * CD;
    float x[128];
    for (int p = 0; p < 128; p++) {
        float v = Z[(size_t)p * CD + col];
        const float* Lr = L + (size_t)p * CK;
        float s0 = 0.f, s1 = 0.f, s2 = 0.f, s3 = 0.f;
        int q = 0;
        for (; q + 4 <= p; q += 4) {
            s0 = fmaf(Lr[q], x[q], s0);   s1 = fmaf(Lr[q + 1], x[q + 1], s1);
            s2 = fmaf(Lr[q + 2], x[q + 2], s2); s3 = fmaf(Lr[q + 3], x[q + 3], s3);
        }
        for (; q < p; q++) s0 = fmaf(Lr[q], x[q], s0);
        v -= (s0 + s1) + (s2 + s3);
        x[p] = v / Lr[p];
        Z[(size_t)p * CD + col] = x[p];
    }
}

// ---------------- backward substitution (L^T) on 128-row block --------------
__global__ void trisolve_bwd_kernel(const float* __restrict__ Am, float* __restrict__ Zm, int j)
{
    int col = blockIdx.x * 128 + threadIdx.x;
    const float* L = Am + (size_t)(j * 128) * CK + j * 128;
    float* Z = Zm + (size_t)(j * 128) * CD;
    float x[128];
    for (int p = 127; p >= 0; p--) {
        float v = Z[(size_t)p * CD + col];
        float s0 = 0.f, s1 = 0.f;
        int q = p + 1;
        for (; q + 2 <= 128; q += 2) {
            s0 = fmaf(L[(size_t)q * CK + p], x[q], s0);
            s1 = fmaf(L[(size_t)(q + 1) * CK + p], x[q + 1], s1);
        }
        for (; q < 128; q++) s0 = fmaf(L[(size_t)q * CK + p], x[q], s0);
        v -= s0 + s1;
        x[p] = v / L[(size_t)p * CK + p];
        Z[(size_t)p * CD + col] = x[p];
    }
}

// ---------------- misc small kernels ----------------------------------------
__global__ void copy_kernel(const float* __restrict__ a, float* __restrict__ b, int n)
{
    int i = blockIdx.x * 256 + threadIdx.x;
    if (i < n) b[i] = a[i];
}

__global__ void init_out2_kernel(const float* __restrict__ S, const float* __restrict__ Vagg,
                                 float* __restrict__ out2)
{
    size_t i = (size_t)blockIdx.x * blockDim.x + threadIdx.x;
    if (i >= (size_t)CB * CK * CD) return;
    size_t kd = i % ((size_t)CK * CD);
    out2[i] = 0.99f * S[kd] + 0.1f * Vagg[i];
}

// ---------------- host launcher ---------------------------------------------
static void tgemm(bool TA, bool TB, bool prec,
                  const float* A, const float* B, float* C, const float* bias,
                  int M, int N, int Kd, int lda, int ldb, int ldc,
                  long long sA, long long sB, long long sC, int batch,
                  float alpha, float beta, int causal)
{
    dim3 grid(N / 128, M / 128, batch), block(256);
#define DISP(ta, tb, pr) tgemm_kernel<ta, tb, pr><<<grid, block>>>(A, B, C, bias, M, N, Kd, lda, ldb, ldc, sA, sB, sC, alpha, beta, causal)
    if (!prec) {
        if (!TA && !TB) DISP(false, false, false);
        else if (!TA && TB) DISP(false, true, false);
        else if (TA && !TB) DISP(true, false, false);
        else DISP(true, true, false);
    } else {
        if (!TA && !TB) DISP(false, false, true);
        else if (!TA && TB) DISP(false, true, true);
        else if (TA && !TB) DISP(true, false, true);
        else DISP(true, true, true);
    }
#undef DISP
}

extern "C" void kernel_launch(void* const* d_in, const int* in_sizes, int n_in,
                              void* d_out, int out_size)
{
    const float* x    = (const float*)d_in[0];
    const float* S    = (const float*)d_in[1];
    const float* Wq_w = (const float*)d_in[2];
    const float* Wq_b = (const float*)d_in[3];
    const float* Wv_w = (const float*)d_in[4];
    const float* Wv_b = (const float*)d_in[5];
    const float* Wn_w = (const float*)d_in[6];
    const float* Wn_b = (const float*)d_in[7];
    const float* Wm_w = (const float*)d_in[8];
    const float* Wm_b = (const float*)d_in[9];
    float* out  = (float*)d_out;                 // [B,T,D]
    float* out2 = out + (size_t)CBT * CD;        // [B,K,D] = S_next

    float *Q, *V, *logits, *ctx, *scores, *byp, *instr, *nov, *vn, *rw, *Sn, *Vagg, *T1, *cov, *Mm, *wt;
    cudaGetSymbolAddress((void**)&Q,      g_Q);
    cudaGetSymbolAddress((void**)&V,      g_V);
    cudaGetSymbolAddress((void**)&logits, g_logits);
    cudaGetSymbolAddress((void**)&ctx,    g_ctx);
    cudaGetSymbolAddress((void**)&scores, g_scores);
    cudaGetSymbolAddress((void**)&byp,    g_byp);
    cudaGetSymbolAddress((void**)&instr,  g_instr);
    cudaGetSymbolAddress((void**)&nov,    g_nov);
    cudaGetSymbolAddress((void**)&vn,     g_vnorm);
    cudaGetSymbolAddress((void**)&rw,     g_rw);
    cudaGetSymbolAddress((void**)&Sn,     g_Sn);
    cudaGetSymbolAddress((void**)&Vagg,   g_Vagg);
    cudaGetSymbolAddress((void**)&T1,     g_T1);
    cudaGetSymbolAddress((void**)&cov,    g_cov);
    cudaGetSymbolAddress((void**)&Mm,     g_Mm);
    cudaGetSymbolAddress((void**)&wt,     g_wt);

    const float inv_sqrt_d = 0.03125f;   // 1/sqrt(1024)

    // 1. Q = x Wq^T + bq (precise: feeds top-k); V = x Wv^T + bv (fast)
    tgemm(false, true, true,  x, Wq_w, Q, Wq_b, CBT, CD, CD, CD, CD, CD, 0, 0, 0, 1, 1.f, 0.f, 0);
    tgemm(false, true, false, x, Wv_w, V, Wv_b, CBT, CD, CD, CD, CD, CD, 0, 0, 0, 1, 1.f, 0.f, 0);
    wt_kernel<<<CT / 256, 256>>>(wt);

    // 2. read logits = Q S^T / 32 (precise: top-k tie-breaks); top-16 read
    tgemm(false, true, true, Q, S, logits, nullptr, CBT, CK, CD, CD, CD, CK, 0, 0, 0, 1, inv_sqrt_d, 0.f, 0);
    topk_ctx_kernel<<<CBT / 8, dim3(32, 8)>>>(logits, S, ctx);
    instr_kernel<<<CBT / 8, dim3(32, 8)>>>(Q, Wm_w, Wm_b, instr);

    // 3. causal self-attention bypass (materialized P) — fast tf32
    tgemm(false, true, false, Q, Q, scores, nullptr, CT, CT, CD, CD, CD, CT,
          (long long)CT * CD, (long long)CT * CD, (long long)CT * CT, CB, inv_sqrt_d, 0.f, 1);
    softmax_causal_kernel<<<dim3(CT, CB), 256>>>(scores);
    tgemm(false, false, false, scores, V, byp, nullptr, CT, CD, CT, CT, CD, CD,
          (long long)CT * CT, (long long)CT * CD, (long long)CT * CD, CB, 1.f, 0.f, 2);
    combine_kernel<<<(CBT * CD + 255) / 256, 256>>>(ctx, byp, instr, out);

    // 4. novelty — fast tf32 (max is continuous)
    sn_kernel<<<CK / 8, dim3(32, 8)>>>(S, Sn);
    vnorm_kernel<<<CBT / 8, dim3(32, 8)>>>(V, vn);
    tgemm(false, true, false, V, Sn, logits, nullptr, CBT, CK, CD, CD, CD, CK, 0, 0, 0, 1, 1.f, 0.f, 0);
    novelty_kernel<<<CBT / 8, dim3(32, 8)>>>(logits, vn, nov);

    // 5. r_write — fast tf32 (sigmoid continuous)
    tgemm(false, true, false, Q, Wn_w + 1, rw, nullptr, CBT, CK, CD, CD, CD + 1, CK, 0, 0, 0, 1, 1.f, 0.f, 0);
    rw_epi_kernel<<<(CBT * CK + 255) / 256, 256>>>(rw, nov, Wn_w, Wn_b, wt);

    // 6. V_agg[b] = rw[b]^T V[b] — fast tf32
    tgemm(true, false, false, rw, V, Vagg, nullptr, CK, CD, CT, CK, CD, CD,
          (long long)CT * CK, (long long)CT * CD, (long long)CK * CD, CB, 1.f, 0.f, 0);

    // 7. S_cov = S S^T + eps I (precise); blocked Cholesky NB=128
    tgemm(false, true, true, S, S, cov, nullptr, CK, CK, CD, CD, CD, CK, 0, 0, 0, 1, 1.f, 0.f, 0);
    diag_eps_kernel<<<2, 256>>>(cov);
    for (int j = 0; j < 4; j++) {
        chol_diag_kernel<<<1, 256>>>(cov, j);
        if (j < 3) {
            chol_trsm_kernel<<<3 - j, 128>>>(cov, j);
            int s = (3 - j) * 128;
            float* Ct = cov + (size_t)(j + 1) * 128 * CK + (j + 1) * 128;
            const float* P = cov + (size_t)(j + 1) * 128 * CK + j * 128;
            tgemm(false, true, true, P, P, Ct, nullptr, s, s, 128, CK, CK, CK, 0, 0, 0, 1, -1.f, 1.f, 0);
        }
    }

    // 8. solve S_cov * Mm = S  (Mm = Cinv S) — precise updates
    copy_kernel<<<(CK * CD + 255) / 256, 256>>>(S, Mm, CK * CD);
    for (int j = 0; j < 4; j++) {
        if (j > 0)
            tgemm(false, false, true, cov + (size_t)j * 128 * CK, Mm, Mm + (size_t)j * 128 * CD, nullptr,
                  128, CD, j * 128, CK, CD, CD, 0, 0, 0, 1, -1.f, 1.f, 0);
        trisolve_fwd_kernel<<<CD / 128, 128>>>(cov, Mm, j);
    }
    for (int j = 3; j >= 0; j--) {
        if (j < 3) {
            int s = (3 - j) * 128;
            tgemm(true, false, true, cov + (size_t)(j + 1) * 128 * CK + j * 128, Mm + (size_t)(j + 1) * 128 * CD,
                  Mm + (size_t)j * 128 * CD, nullptr, 128, CD, s, CK, CD, CD, 0, 0, 0, 1, -1.f, 1.f, 0);
        }
        trisolve_bwd_kernel<<<CD / 128, 128>>>(cov, Mm, j);
    }

    // 9. S_next = 0.99 S + 0.1 (V_agg - (V_agg S^T) Mm) — precise
    tgemm(false, true, true, Vagg, S, T1, nullptr, CK, CK, CD, CD, CD, CK,
          (long long)CK * CD, 0, (long long)CK * CK, CB, 1.f, 0.f, 0);
    init_out2_kernel<<<(CB * CK * CD + 255) / 256, 256>>>(S, Vagg, out2);
    tgemm(false, false, true, T1, Mm, out2, nullptr, CK, CD, CK, CK, CD, CD,
          (long long)CK * CK, 0, (long long)CK * CD, CB, -0.1f, 1.f, 0);
}

// round 3
// speedup vs baseline: 1.7202x; 1.4248x over previous
#include <cuda_runtime.h>
#include <math.h>
#include <stdint.h>

#define CB 4
#define CT 2048
#define CD 1024
#define CK 512
#define CKR 16
#define CBT 8192   // CB*CT

// ---------------- scratch (static device globals; no allocs) ----------------
__device__ float g_Q[CBT*CD];
__device__ float g_V[CBT*CD];
__device__ float g_logits[CBT*CK];      // reused later for sim
__device__ float g_ctx[CBT*CD];
__device__ float g_scores[(size_t)CB*CT*CT];
__device__ float g_byp[CBT*CD];
__device__ float g_instr[CBT];
__device__ float g_nov[CBT];
__device__ float g_vnorm[CBT];
__device__ float g_rw[CBT*CK];
__device__ float g_Sn[CK*CD];
__device__ float g_Vagg[CB*CK*CD];
__device__ float g_T1[CB*CK*CK];
__device__ float g_cov[CK*CK];
__device__ float g_Mm[CK*CD];
__device__ float g_wt[CT];
__device__ float g_LT[4*128*128];       // transposed diagonal L blocks

// ---------------- tf32 / async helpers --------------------------------------
__device__ __forceinline__ uint32_t f2tf32(float x) {
    uint32_t r;
    asm("cvt.rna.tf32.f32 %0, %1;" : "=r"(r) : "f"(x));
    return r;
}

__device__ __forceinline__ void mma_tf32(float* c, const uint32_t* a, const uint32_t* b) {
    asm volatile(
        "mma.sync.aligned.m16n8k8.row.col.f32.tf32.tf32.f32 "
        "{%0,%1,%2,%3}, {%4,%5,%6,%7}, {%8,%9}, {%0,%1,%2,%3};"
        : "+f"(c[0]), "+f"(c[1]), "+f"(c[2]), "+f"(c[3])
        : "r"(a[0]), "r"(a[1]), "r"(a[2]), "r"(a[3]), "r"(b[0]), "r"(b[1]));
}

__device__ __forceinline__ void cp_async4(uint32_t dst, const void* src) {
    asm volatile("cp.async.ca.shared.global [%0], [%1], 4;" :: "r"(dst), "l"(src));
}

// ---------------- tensor-core GEMM: C = beta*C + alpha*op(A)op(B) (+bias) ---
// BM=BN=128, BK=16, 256 threads = 8 warps (2 M x 4 N), warp tile 64x32.
// 2-stage cp.async double buffer; fp32 in smem, tf32 hi/lo split at frag load.
// PREC: 3-pass split tf32 (~fp32 accuracy).
// causal: 1 = skip blocks above diagonal (scores), 2 = limit K to bm+128 (P@V).
template<bool TA, bool TB, bool PREC>
__global__ void __launch_bounds__(256) tgemm_kernel(
    const float* __restrict__ A, const float* __restrict__ B,
    float* __restrict__ C, const float* __restrict__ bias,
    int M, int N, int Kd, int lda, int ldb, int ldc,
    long long sA, long long sB, long long sC,
    float alpha, float beta, int causal)
{
    const int bm = blockIdx.y * 128;
    const int bn = blockIdx.x * 128;
    if (causal == 1 && bn > bm + 127) return;
    A += sA * blockIdx.z;
    B += sB * blockIdx.z;
    C += sC * blockIdx.z;
    const int kend = (causal == 2) ? min(Kd, bm + 128) : Kd;

    __shared__ float Ah[2][16][132];
    __shared__ float Bh[2][16][132];
    const uint32_t sAb = (uint32_t)__cvta_generic_to_shared(&Ah[0][0][0]);
    const uint32_t sBb = (uint32_t)__cvta_generic_to_shared(&Bh[0][0][0]);

    const int tid = threadIdx.x;
    const int lane = tid & 31;
    const int wid = tid >> 5;
    const int warp_m = wid >> 2;      // 0..1
    const int warp_n = wid & 3;       // 0..3
    const int gid = lane >> 2;        // 0..7
    const int tig = lane & 3;         // 0..3
    const int mbase = warp_m * 64;
    const int nbase = warp_n * 32;

    float acc[4][4][4];
#pragma unroll
    for (int i = 0; i < 4; i++)
#pragma unroll
        for (int j = 0; j < 4; j++)
#pragma unroll
            for (int r = 0; r < 4; r++) acc[i][j][r] = 0.f;

    auto load_stage = [&](int s, int k0) {
#pragma unroll
        for (int i = 0; i < 8; i++) {
            int e = tid + 256 * i;
            const float* src; int m, k;
            if (!TA) { m = e >> 4; k = e & 15; src = A + (size_t)(bm + m) * lda + k0 + k; }
            else     { k = e >> 7; m = e & 127; src = A + (size_t)(k0 + k) * lda + bm + m; }
            cp_async4(sAb + (((s * 16 + k) * 132 + m) << 2), src);
        }
#pragma unroll
        for (int i = 0; i < 8; i++) {
            int e = tid + 256 * i;
            const float* src; int n, k;
            if (!TB) { k = e >> 7; n = e & 127; src = B + (size_t)(k0 + k) * ldb + bn + n; }
            else     { n = e >> 4; k = e & 15; src = B + (size_t)(bn + n) * ldb + k0 + k; }
            cp_async4(sBb + (((s * 16 + k) * 132 + n) << 2), src);
        }
        asm volatile("cp.async.commit_group;");
    };

    auto compute_stage = [&](int s) {
#pragma unroll
        for (int ks = 0; ks < 2; ks++) {
            const int k8 = ks * 8;
            uint32_t af[4][4], bf[4][2];
            uint32_t afl[4][4], bfl[4][2];
#pragma unroll
            for (int mi = 0; mi < 4; mi++) {
                int r = mbase + mi * 16;
#pragma unroll
                for (int q = 0; q < 4; q++) {
                    int kk = k8 + tig + (q >> 1) * 4;
                    int mm = r + gid + (q & 1) * 8;
                    float v = Ah[s][kk][mm];
                    uint32_t h = f2tf32(v);
                    af[mi][q] = h;
                    if (PREC) afl[mi][q] = f2tf32(v - __uint_as_float(h));
                }
            }
#pragma unroll
            for (int ni = 0; ni < 4; ni++) {
                int c = nbase + ni * 8;
#pragma unroll
                for (int q = 0; q < 2; q++) {
                    float v = Bh[s][k8 + tig + q * 4][c + gid];
                    uint32_t h = f2tf32(v);
                    bf[ni][q] = h;
                    if (PREC) bfl[ni][q] = f2tf32(v - __uint_as_float(h));
                }
            }
#pragma unroll
            for (int mi = 0; mi < 4; mi++)
#pragma unroll
                for (int ni = 0; ni < 4; ni++) {
                    mma_tf32(acc[mi][ni], af[mi], bf[ni]);
                    if (PREC) {
                        mma_tf32(acc[mi][ni], af[mi], bfl[ni]);
                        mma_tf32(acc[mi][ni], afl[mi], bf[ni]);
                    }
                }
        }
    };

    const int niter = kend / 16;
    int st = 0;
    load_stage(0, 0);
    for (int it = 0; it < niter; it++) {
        if (it + 1 < niter) {
            load_stage(st ^ 1, (it + 1) * 16);
            asm volatile("cp.async.wait_group 1;");
        } else {
            asm volatile("cp.async.wait_group 0;");
        }
        __syncthreads();
        compute_stage(st);
        __syncthreads();
        st ^= 1;
    }

    // ---- epilogue ----
#pragma unroll
    for (int mi = 0; mi < 4; mi++) {
        int row0 = bm + mbase + mi * 16 + gid;
        int row1 = row0 + 8;
#pragma unroll
        for (int ni = 0; ni < 4; ni++) {
            int col = bn + nbase + ni * 8 + 2 * tig;
            float v0 = alpha * acc[mi][ni][0];
            float v1 = alpha * acc[mi][ni][1];
            float v2 = alpha * acc[mi][ni][2];
            float v3 = alpha * acc[mi][ni][3];
            if (beta != 0.f) {
                v0 += beta * C[(size_t)row0 * ldc + col];
                v1 += beta * C[(size_t)row0 * ldc + col + 1];
                v2 += beta * C[(size_t)row1 * ldc + col];
                v3 += beta * C[(size_t)row1 * ldc + col + 1];
            }
            if (bias) {
                v0 += bias[col]; v1 += bias[col + 1];
                v2 += bias[col]; v3 += bias[col + 1];
            }
            C[(size_t)row0 * ldc + col]     = v0;
            C[(size_t)row0 * ldc + col + 1] = v1;
            C[(size_t)row1 * ldc + col]     = v2;
            C[(size_t)row1 * ldc + col + 1] = v3;
        }
    }
}

// ---------------- top-16 read + softmax + context (warp per row) ------------
__global__ void topk_ctx_kernel(const float* __restrict__ logits,
                                const float* __restrict__ S,
                                float* __restrict__ ctx)
{
    int m = blockIdx.x * 8 + threadIdx.y;
    int lane = threadIdx.x;
    const float* lrow = logits + (size_t)m * CK;
    float v[16];
#pragma unroll
    for (int i = 0; i < 16; i++) v[i] = lrow[i * 32 + lane];
    float topv[CKR]; int topi[CKR];
    for (int it = 0; it < CKR; it++) {
        float bv = -INFINITY; int bi = 0x7fffffff;
#pragma unroll
        for (int i = 0; i < 16; i++) {
            if (v[i] > bv) { bv = v[i]; bi = i * 32 + lane; }
        }
#pragma unroll
        for (int off = 16; off > 0; off >>= 1) {
            float ov = __shfl_xor_sync(0xffffffffu, bv, off);
            int   oi = __shfl_xor_sync(0xffffffffu, bi, off);
            if (ov > bv || (ov == bv && oi < bi)) { bv = ov; bi = oi; }
        }
        topv[it] = bv; topi[it] = bi;
        if ((bi & 31) == lane) v[bi >> 5] = -INFINITY;
    }
    float p[CKR]; float s = 0.f;
#pragma unroll
    for (int i = 0; i < CKR; i++) { p[i] = expf(topv[i] - topv[0]); s += p[i]; }
    float inv = 1.f / s;
    float* crow = ctx + (size_t)m * CD;
    for (int d = lane; d < CD; d += 32) {
        float acc = 0.f;
#pragma unroll
        for (int i = 0; i < CKR; i++)
            acc += p[i] * S[(size_t)topi[i] * CD + d];
        crow[d] = acc * inv;
    }
}

// ---------------- instruction gate: sigmoid(Q.Wm + bm) ----------------------
__global__ void instr_kernel(const float* __restrict__ Q,
                             const float* __restrict__ Wm,
                             const float* __restrict__ bm_,
                             float* __restrict__ instr)
{
    int m = blockIdx.x * 8 + threadIdx.y;
    int lane = threadIdx.x;
    const float* q = Q + (size_t)m * CD;
    float s = 0.f;
    for (int d = lane; d < CD; d += 32) s = fmaf(q[d], Wm[d], s);
#pragma unroll
    for (int off = 16; off > 0; off >>= 1) s += __shfl_xor_sync(0xffffffffu, s, off);
    if (lane == 0) instr[m] = 1.f / (1.f + expf(-(s + bm_[0])));
}

// ---------------- causal row softmax in place -------------------------------
__global__ void softmax_causal_kernel(float* __restrict__ P)
{
    int b = blockIdx.y, q = blockIdx.x;
    float* row = P + ((size_t)b * CT + q) * CT;
    int n = q + 1;
    int tid = threadIdx.x;
    __shared__ float red[256];
    float mx = -INFINITY;
    for (int k = tid; k < n; k += 256) mx = fmaxf(mx, row[k]);
    red[tid] = mx; __syncthreads();
    for (int s = 128; s > 0; s >>= 1) { if (tid < s) red[tid] = fmaxf(red[tid], red[tid + s]); __syncthreads(); }
    mx = red[0]; __syncthreads();
    float sum = 0.f;
    for (int k = tid; k < n; k += 256) { float e = expf(row[k] - mx); row[k] = e; sum += e; }
    red[tid] = sum; __syncthreads();
    for (int s = 128; s > 0; s >>= 1) { if (tid < s) red[tid] += red[tid + s]; __syncthreads(); }
    float inv = 1.f / red[0];
    for (int k = tid; k < n; k += 256) row[k] *= inv;
    for (int k = n + tid; k < CT; k += 256) row[k] = 0.f;
}

// ---------------- elementwise combine: out = (1-p)*ctx + p*byp --------------
__global__ void combine_kernel(const float* __restrict__ ctx, const float* __restrict__ byp,
                               const float* __restrict__ instr, float* __restrict__ out)
{
    size_t i = (size_t)blockIdx.x * blockDim.x + threadIdx.x;
    if (i >= (size_t)CBT * CD) return;
    float p = instr[i / CD];
    out[i] = (1.f - p) * ctx[i] + p * byp[i];
}

// ---------------- row-normalize S -> Sn -------------------------------------
__global__ void sn_kernel(const float* __restrict__ S, float* __restrict__ Sn)
{
    int r = blockIdx.x * 8 + threadIdx.y;
    int lane = threadIdx.x;
    const float* row = S + (size_t)r * CD;
    float s = 0.f;
    for (int d = lane; d < CD; d += 32) { float v = row[d]; s = fmaf(v, v, s); }
#pragma unroll
    for (int off = 16; off > 0; off >>= 1) s += __shfl_xor_sync(0xffffffffu, s, off);
    float inv = 1.f / fmaxf(sqrtf(s), 1e-8f);
    for (int d = lane; d < CD; d += 32) Sn[(size_t)r * CD + d] = row[d] * inv;
}

// ---------------- V row norms ------------------------------------------------
__global__ void vnorm_kernel(const float* __restrict__ V, float* __restrict__ vn)
{
    int m = blockIdx.x * 8 + threadIdx.y;
    int lane = threadIdx.x;
    const float* row = V + (size_t)m * CD;
    float s = 0.f;
    for (int d = lane; d < CD; d += 32) { float v = row[d]; s = fmaf(v, v, s); }
#pragma unroll
    for (int off = 16; off > 0; off >>= 1) s += __shfl_xor_sync(0xffffffffu, s, off);
    if (lane == 0) vn[m] = sqrtf(s);
}

// ---------------- novelty = 1 - rowmax(sim)/max(|V|,eps) --------------------
__global__ void novelty_kernel(const float* __restrict__ sim, const float* __restrict__ vn,
                               float* __restrict__ nov)
{
    int m = blockIdx.x * 8 + threadIdx.y;
    int lane = threadIdx.x;
    const float* row = sim + (size_t)m * CK;
    float mx = -INFINITY;
    for (int k = lane; k < CK; k += 32) mx = fmaxf(mx, row[k]);
#pragma unroll
    for (int off = 16; off > 0; off >>= 1) mx = fmaxf(mx, __shfl_xor_sync(0xffffffffu, mx, off));
    if (lane == 0) nov[m] = 1.f - mx / fmaxf(vn[m], 1e-8f);
}

// ---------------- decay weights ---------------------------------------------
__global__ void wt_kernel(float* __restrict__ wt)
{
    int t = blockIdx.x * 256 + threadIdx.x;
    if (t >= CT) return;
    float denom = 1.f - powf(0.99f, (float)CT);
    wt[t] = powf(0.99f, (float)(CT - 1 - t)) * (0.01f / denom);
}

// ---------------- r_write epilogue: sigmoid(lin + nov*w0 + b) * wt[t] -------
__global__ void rw_epi_kernel(float* __restrict__ rw, const float* __restrict__ nov,
                              const float* __restrict__ Wn, const float* __restrict__ bn,
                              const float* __restrict__ wt)
{
    size_t i = (size_t)blockIdx.x * blockDim.x + threadIdx.x;
    if (i >= (size_t)CBT * CK) return;
    int m = (int)(i / CK), k = (int)(i % CK);
    float x = rw[i] + nov[m] * Wn[(size_t)k * (CD + 1)] + bn[k];
    rw[i] = (1.f / (1.f + expf(-x))) * wt[m % CT];
}

// ---------------- add eps*I to S_cov ----------------------------------------
__global__ void diag_eps_kernel(float* __restrict__ cov)
{
    int k = blockIdx.x * 256 + threadIdx.x;
    if (k < CK) cov[(size_t)k * CK + k] += 1e-5f;
}

// ---------------- Cholesky diagonal block (in-place, global, 1 block) -------
__global__ void chol_diag_kernel(float* __restrict__ Am, int j)
{
    float* A = Am + (size_t)(j * 128) * CK + j * 128;   // ld = CK
    int tid = threadIdx.x;
    for (int p = 0; p < 128; p++) {
        if (tid == 0) A[(size_t)p * CK + p] = sqrtf(A[(size_t)p * CK + p]);
        __syncthreads();
        float d = A[(size_t)p * CK + p];
        for (int r = p + 1 + tid; r < 128; r += 256) A[(size_t)r * CK + p] /= d;
        __syncthreads();
        int w = 127 - p;
        for (int idx = tid; idx < w * w; idx += 256) {
            int r = p + 1 + idx / w;
            int c = p + 1 + idx % w;
            A[(size_t)r * CK + c] -= A[(size_t)r * CK + p] * A[(size_t)c * CK + p];
        }
        __syncthreads();
    }
}

// ---------------- warp-per-row panel solve: X L_jj^T = panel ---------------
__global__ void chol_trsm_w(float* __restrict__ Am, int j)
{
    int w = blockIdx.x * (blockDim.x >> 5) + (threadIdx.x >> 5);
    int lane = threadIdx.x & 31;
    int i = (j + 1) * 128 + w;
    const float* L = Am + (size_t)(j * 128) * CK + j * 128;
    float* row = Am + (size_t)i * CK + j * 128;
    float f[4];
#pragma unroll
    for (int q = 0; q < 4; q++) f[q] = row[lane + 32 * q];
    for (int c = 0; c < 128; c++) {
        const float* Lr = L + (size_t)c * CK;
        float s = 0.f;
#pragma unroll
        for (int q = 0; q < 4; q++) {
            int qq = lane + 32 * q;
            if (qq < c) s = fmaf(Lr[qq], f[q], s);
        }
#pragma unroll
        for (int off = 16; off > 0; off >>= 1) s += __shfl_xor_sync(0xffffffffu, s, off);
        float rc = __shfl_sync(0xffffffffu, f[c >> 5], c & 31);
        float v = (rc - s) / Lr[c];
        if (lane == (c & 31)) f[c >> 5] = v;
    }
#pragma unroll
    for (int q = 0; q < 4; q++) row[lane + 32 * q] = f[q];
}

// ---------------- transpose diagonal L blocks for backward solve ------------
__global__ void transpose_diag_kernel(const float* __restrict__ cov, float* __restrict__ LT)
{
    int j = blockIdx.y;
    int idx = blockIdx.x * 256 + threadIdx.x;
    int p = idx >> 7, q = idx & 127;
    LT[j * 16384 + idx] = cov[(size_t)(j * 128 + q) * CK + j * 128 + p];
}

// ---------------- warp-per-column forward substitution ----------------------
__global__ void trisolve_fwd_w(const float* __restrict__ Am, float* __restrict__ Zm, int j)
{
    int w = blockIdx.x * (blockDim.x >> 5) + (threadIdx.x >> 5);   // column
    int lane = threadIdx.x & 31;
    const float* L = Am + (size_t)(j * 128) * CK + j * 128;
    float* Z = Zm + (size_t)(j * 128) * CD + w;
    float f[4];
#pragma unroll
    for (int q = 0; q < 4; q++) f[q] = Z[(size_t)(lane + 32 * q) * CD];
    for (int p = 0; p < 128; p++) {
        const float* Lr = L + (size_t)p * CK;
        float s = 0.f;
#pragma unroll
        for (int q = 0; q < 4; q++) {
            int qq = lane + 32 * q;
            if (qq < p) s = fmaf(Lr[qq], f[q], s);
        }
#pragma unroll
        for (int off = 16; off > 0; off >>= 1) s += __shfl_xor_sync(0xffffffffu, s, off);
        float zp = __shfl_sync(0xffffffffu, f[p >> 5], p & 31);
        float v = (zp - s) / Lr[p];
        if (lane == (p & 31)) f[p >> 5] = v;
    }
#pragma unroll
    for (int q = 0; q < 4; q++) Z[(size_t)(lane + 32 * q) * CD] = f[q];
}

// ---------------- warp-per-column backward substitution (uses LT) -----------
__global__ void trisolve_bwd_w(const float* __restrict__ LT, float* __restrict__ Zm, int j)
{
    int w = blockIdx.x * (blockDim.x >> 5) + (threadIdx.x >> 5);   // column
    int lane = threadIdx.x & 31;
    const float* Lt = LT + j * 16384;                  // Lt[p][q] = L[q][p]
    float* Z = Zm + (size_t)(j * 128) * CD + w;
    float f[4];
#pragma unroll
    for (int q = 0; q < 4; q++) f[q] = Z[(size_t)(lane + 32 * q) * CD];
    for (int p = 127; p >= 0; p--) {
        const float* Lr = Lt + p * 128;
        float s = 0.f;
#pragma unroll
        for (int q = 0; q < 4; q++) {
            int qq = lane + 32 * q;
            if (qq > p) s = fmaf(Lr[qq], f[q], s);
        }
#pragma unroll
        for (int off = 16; off > 0; off >>= 1) s += __shfl_xor_sync(0xffffffffu, s, off);
        float zp = __shfl_sync(0xffffffffu, f[p >> 5], p & 31);
        float v = (zp - s) / Lr[p];
        if (lane == (p & 31)) f[p >> 5] = v;
    }
#pragma unroll
    for (int q = 0; q < 4; q++) Z[(size_t)(lane + 32 * q) * CD] = f[q];
}

// ---------------- misc small kernels ----------------------------------------
__global__ void copy_kernel(const float* __restrict__ a, float* __restrict__ b, int n)
{
    int i = blockIdx.x * 256 + threadIdx.x;
    if (i < n) b[i] = a[i];
}

__global__ void init_out2_kernel(const float* __restrict__ S, const float* __restrict__ Vagg,
                                 float* __restrict__ out2)
{
    size_t i = (size_t)blockIdx.x * blockDim.x + threadIdx.x;
    if (i >= (size_t)CB * CK * CD) return;
    size_t kd = i % ((size_t)CK * CD);
    out2[i] = 0.99f * S[kd] + 0.1f * Vagg[i];
}

// ---------------- host launcher ---------------------------------------------
static void tgemm(bool TA, bool TB, bool prec,
                  const float* A, const float* B, float* C, const float* bias,
                  int M, int N, int Kd, int lda, int ldb, int ldc,
                  long long sA, long long sB, long long sC, int batch,
                  float alpha, float beta, int causal)
{
    dim3 grid(N / 128, M / 128, batch), block(256);
#define DISP(ta, tb, pr) tgemm_kernel<ta, tb, pr><<<grid, block>>>(A, B, C, bias, M, N, Kd, lda, ldb, ldc, sA, sB, sC, alpha, beta, causal)
    if (!prec) {
        if (!TA && !TB) DISP(false, false, false);
        else if (!TA && TB) DISP(false, true, false);
        else if (TA && !TB) DISP(true, false, false);
        else DISP(true, true, false);
    } else {
        if (!TA && !TB) DISP(false, false, true);
        else if (!TA && TB) DISP(false, true, true);
        else if (TA && !TB) DISP(true, false, true);
        else DISP(true, true, true);
    }
#undef DISP
}

extern "C" void kernel_launch(void* const* d_in, const int* in_sizes, int n_in,
                              void* d_out, int out_size)
{
    const float* x    = (const float*)d_in[0];
    const float* S    = (const float*)d_in[1];
    const float* Wq_w = (const float*)d_in[2];
    const float* Wq_b = (const float*)d_in[3];
    const float* Wv_w = (const float*)d_in[4];
    const float* Wv_b = (const float*)d_in[5];
    const float* Wn_w = (const float*)d_in[6];
    const float* Wn_b = (const float*)d_in[7];
    const float* Wm_w = (const float*)d_in[8];
    const float* Wm_b = (const float*)d_in[9];
    float* out  = (float*)d_out;                 // [B,T,D]
    float* out2 = out + (size_t)CBT * CD;        // [B,K,D] = S_next

    float *Q, *V, *logits, *ctx, *scores, *byp, *instr, *nov, *vn, *rw, *Sn, *Vagg, *T1, *cov, *Mm, *wt, *LT;
    cudaGetSymbolAddress((void**)&Q,      g_Q);
    cudaGetSymbolAddress((void**)&V,      g_V);
    cudaGetSymbolAddress((void**)&logits, g_logits);
    cudaGetSymbolAddress((void**)&ctx,    g_ctx);
    cudaGetSymbolAddress((void**)&scores, g_scores);
    cudaGetSymbolAddress((void**)&byp,    g_byp);
    cudaGetSymbolAddress((void**)&instr,  g_instr);
    cudaGetSymbolAddress((void**)&nov,    g_nov);
    cudaGetSymbolAddress((void**)&vn,     g_vnorm);
    cudaGetSymbolAddress((void**)&rw,     g_rw);
    cudaGetSymbolAddress((void**)&Sn,     g_Sn);
    cudaGetSymbolAddress((void**)&Vagg,   g_Vagg);
    cudaGetSymbolAddress((void**)&T1,     g_T1);
    cudaGetSymbolAddress((void**)&cov,    g_cov);
    cudaGetSymbolAddress((void**)&Mm,     g_Mm);
    cudaGetSymbolAddress((void**)&wt,     g_wt);
    cudaGetSymbolAddress((void**)&LT,     g_LT);

    const float inv_sqrt_d = 0.03125f;   // 1/sqrt(1024)

    // 1. Q = x Wq^T + bq (precise: feeds top-k); V = x Wv^T + bv (fast)
    tgemm(false, true, true,  x, Wq_w, Q, Wq_b, CBT, CD, CD, CD, CD, CD, 0, 0, 0, 1, 1.f, 0.f, 0);
    tgemm(false, true, false, x, Wv_w, V, Wv_b, CBT, CD, CD, CD, CD, CD, 0, 0, 0, 1, 1.f, 0.f, 0);
    wt_kernel<<<CT / 256, 256>>>(wt);

    // 2. read logits = Q S^T / 32 (precise: top-k tie-breaks); top-16 read
    tgemm(false, true, true, Q, S, logits, nullptr, CBT, CK, CD, CD, CD, CK, 0, 0, 0, 1, inv_sqrt_d, 0.f, 0);
    topk_ctx_kernel<<<CBT / 8, dim3(32, 8)>>>(logits, S, ctx);
    instr_kernel<<<CBT / 8, dim3(32, 8)>>>(Q, Wm_w, Wm_b, instr);

    // 3. causal self-attention bypass (materialized P) — fast tf32
    tgemm(false, true, false, Q, Q, scores, nullptr, CT, CT, CD, CD, CD, CT,
          (long long)CT * CD, (long long)CT * CD, (long long)CT * CT, CB, inv_sqrt_d, 0.f, 1);
    softmax_causal_kernel<<<dim3(CT, CB), 256>>>(scores);
    tgemm(false, false, false, scores, V, byp, nullptr, CT, CD, CT, CT, CD, CD,
          (long long)CT * CT, (long long)CT * CD, (long long)CT * CD, CB, 1.f, 0.f, 2);
    combine_kernel<<<(CBT * CD + 255) / 256, 256>>>(ctx, byp, instr, out);

    // 4. novelty — fast tf32 (max is continuous)
    sn_kernel<<<CK / 8, dim3(32, 8)>>>(S, Sn);
    vnorm_kernel<<<CBT / 8, dim3(32, 8)>>>(V, vn);
    tgemm(false, true, false, V, Sn, logits, nullptr, CBT, CK, CD, CD, CD, CK, 0, 0, 0, 1, 1.f, 0.f, 0);
    novelty_kernel<<<CBT / 8, dim3(32, 8)>>>(logits, vn, nov);

    // 5. r_write — fast tf32 (sigmoid continuous)
    tgemm(false, true, false, Q, Wn_w + 1, rw, nullptr, CBT, CK, CD, CD, CD + 1, CK, 0, 0, 0, 1, 1.f, 0.f, 0);
    rw_epi_kernel<<<(CBT * CK + 255) / 256, 256>>>(rw, nov, Wn_w, Wn_b, wt);

    // 6. V_agg[b] = rw[b]^T V[b] — fast tf32
    tgemm(true, false, false, rw, V, Vagg, nullptr, CK, CD, CT, CK, CD, CD,
          (long long)CT * CK, (long long)CT * CD, (long long)CK * CD, CB, 1.f, 0.f, 0);

    // 7. S_cov = S S^T + eps I (precise); blocked Cholesky NB=128
    tgemm(false, true, true, S, S, cov, nullptr, CK, CK, CD, CD, CD, CK, 0, 0, 0, 1, 1.f, 0.f, 0);
    diag_eps_kernel<<<2, 256>>>(cov);
    for (int j = 0; j < 4; j++) {
        chol_diag_kernel<<<1, 256>>>(cov, j);
        if (j < 3) {
            int rows = (3 - j) * 128;
            chol_trsm_w<<<rows / 8, 256>>>(cov, j);
            float* Ct = cov + (size_t)(j + 1) * 128 * CK + (j + 1) * 128;
            const float* P = cov + (size_t)(j + 1) * 128 * CK + j * 128;
            tgemm(false, true, true, P, P, Ct, nullptr, rows, rows, 128, CK, CK, CK, 0, 0, 0, 1, -1.f, 1.f, 0);
        }
    }
    transpose_diag_kernel<<<dim3(64, 4), 256>>>(cov, LT);

    // 8. solve S_cov * Mm = S  (Mm = Cinv S) — warp-cooperative substitutions
    copy_kernel<<<(CK * CD + 255) / 256, 256>>>(S, Mm, CK * CD);
    for (int j = 0; j < 4; j++) {
        if (j > 0)
            tgemm(false, false, true, cov + (size_t)j * 128 * CK, Mm, Mm + (size_t)j * 128 * CD, nullptr,
                  128, CD, j * 128, CK, CD, CD, 0, 0, 0, 1, -1.f, 1.f, 0);
        trisolve_fwd_w<<<CD / 8, 256>>>(cov, Mm, j);
    }
    for (int j = 3; j >= 0; j--) {
        if (j < 3) {
            int s = (3 - j) * 128;
            tgemm(true, false, true, cov + (size_t)(j + 1) * 128 * CK + j * 128, Mm + (size_t)(j + 1) * 128 * CD,
                  Mm + (size_t)j * 128 * CD, nullptr, 128, CD, s, CK, CD, CD, 0, 0, 0, 1, -1.f, 1.f, 0);
        }
        trisolve_bwd_w<<<CD / 8, 256>>>(LT, Mm, j);
    }

    // 9. S_next = 0.99 S + 0.1 (V_agg - (V_agg S^T) Mm) — precise
    tgemm(false, true, true, Vagg, S, T1, nullptr, CK, CK, CD, CD, CD, CK,
          (long long)CK * CD, 0, (long long)CK * CK, CB, 1.f, 0.f, 0);
    init_out2_kernel<<<(CB * CK * CD + 255) / 256, 256>>>(S, Vagg, out2);
    tgemm(false, false, true, T1, Mm, out2, nullptr, CK, CD, CK, CK, CD, CD,
          (long long)CK * CK, 0, (long long)CK * CD, CB, -0.1f, 1.f, 0);
}

// round 4
// speedup vs baseline: 2.1625x; 1.2571x over previous
#include <cuda_runtime.h>
#include <math.h>
#include <stdint.h>

#define CB 4
#define CT 2048
#define CD 1024
#define CK 512
#define CKR 16
#define CBT 8192   // CB*CT

// ---------------- scratch (static device globals; no allocs) ----------------
__device__ float g_Q[CBT*CD];
__device__ float g_V[CBT*CD];
__device__ float g_logits[CBT*CK];      // reused later for sim
__device__ float g_ctx[CBT*CD];
__device__ float g_scores[(size_t)CB*CT*CT];
__device__ float g_byp[CBT*CD];
__device__ float g_instr[CBT];
__device__ float g_nov[CBT];
__device__ float g_vnorm[CBT];
__device__ float g_rw[CBT*CK];
__device__ float g_Sn[CK*CD];
__device__ float g_Vagg[CB*CK*CD];
__device__ float g_T1[CB*CK*CK];
__device__ float g_cov[CK*CK];
__device__ float g_Mm[CK*CD];
__device__ float g_wt[CT];
__device__ float g_LT[4*128*128];       // transposed diagonal L blocks

// ---------------- tf32 helpers ----------------------------------------------
__device__ __forceinline__ uint32_t f2tf32(float x) {
    uint32_t r;
    asm("cvt.rna.tf32.f32 %0, %1;" : "=r"(r) : "f"(x));
    return r;
}

__device__ __forceinline__ void mma_tf32(float* c, const uint32_t* a, const uint32_t* b) {
    asm volatile(
        "mma.sync.aligned.m16n8k8.row.col.f32.tf32.tf32.f32 "
        "{%0,%1,%2,%3}, {%4,%5,%6,%7}, {%8,%9}, {%0,%1,%2,%3};"
        : "+f"(c[0]), "+f"(c[1]), "+f"(c[2]), "+f"(c[3])
        : "r"(a[0]), "r"(a[1]), "r"(a[2]), "r"(a[3]), "r"(b[0]), "r"(b[1]));
}

// ---------------- tensor-core GEMM: C = beta*C + alpha*op(A)op(B) (+bias) ---
// BM=BN=128, BK=16, 256 threads = 8 warps (2 M x 4 N), warp tile 64x32.
// Global->reg->convert->packed smem (fragment-ready float4/float2), double
// buffered via registers + 2 smem stages. Hot loop: LDS.128 + mma only.
// PREC: 3-pass split tf32 (~fp32 accuracy).
// causal: 1 = skip blocks above diagonal (scores), 2 = limit K to bm+128 (P@V).
template<bool TA, bool TB, bool PREC>
__global__ void __launch_bounds__(256) tgemm_kernel(
    const float* __restrict__ A, const float* __restrict__ B,
    float* __restrict__ C, const float* __restrict__ bias,
    int M, int N, int Kd, int lda, int ldb, int ldc,
    long long sA, long long sB, long long sC,
    float alpha, float beta, int causal)
{
    constexpr int PK = PREC ? 4 : 2;      // floats per pack
    const int bm = blockIdx.y * 128;
    const int bn = blockIdx.x * 128;
    if (causal == 1 && bn > bm + 127) return;
    A += sA * blockIdx.z;
    B += sB * blockIdx.z;
    C += sC * blockIdx.z;
    const int kend = (causal == 2) ? min(Kd, bm + 128) : Kd;

    extern __shared__ float sm[];
    float* Ap = sm;                        // [2 st][2 ks][128 m][4 tig][PK]
    float* Bp = sm + 2 * 2 * 128 * 4 * PK;

    const int tid = threadIdx.x;
    const int lane = tid & 31;
    const int wid = tid >> 5;
    const int warp_m = wid >> 2;      // 0..1
    const int warp_n = wid & 3;       // 0..3
    const int gid = lane >> 2;        // 0..7
    const int tig = lane & 3;         // 0..3
    const int mbase = warp_m * 64;
    const int nbase = warp_n * 32;

    float acc[4][4][4];
#pragma unroll
    for (int i = 0; i < 4; i++)
#pragma unroll
        for (int j = 0; j < 4; j++)
#pragma unroll
            for (int r = 0; r < 4; r++) acc[i][j][r] = 0.f;

    float ra[4][2], rb[4][2];

    auto gload = [&](int k0) {
#pragma unroll
        for (int i = 0; i < 4; i++) {
            int e = tid + 256 * i;
            int tg = e & 3, ks = (e >> 2) & 1, m = e >> 3;
            int k = ks * 8 + tg;
            if (!TA) {
                ra[i][0] = A[(size_t)(bm + m) * lda + k0 + k];
                ra[i][1] = A[(size_t)(bm + m) * lda + k0 + k + 4];
            } else {
                ra[i][0] = A[(size_t)(k0 + k) * lda + bm + m];
                ra[i][1] = A[(size_t)(k0 + k + 4) * lda + bm + m];
            }
            if (!TB) {
                rb[i][0] = B[(size_t)(k0 + k) * ldb + bn + m];
                rb[i][1] = B[(size_t)(k0 + k + 4) * ldb + bn + m];
            } else {
                rb[i][0] = B[(size_t)(bn + m) * ldb + k0 + k];
                rb[i][1] = B[(size_t)(bn + m) * ldb + k0 + k + 4];
            }
        }
    };

    auto sstore = [&](int st) {
#pragma unroll
        for (int i = 0; i < 4; i++) {
            int e = tid + 256 * i;
            int tg = e & 3, ks = (e >> 2) & 1, m = e >> 3;
            int idx = (((st * 2 + ks) * 128 + m) * 4 + tg) * PK;
            uint32_t ah0 = f2tf32(ra[i][0]), ah1 = f2tf32(ra[i][1]);
            uint32_t bh0 = f2tf32(rb[i][0]), bh1 = f2tf32(rb[i][1]);
            if constexpr (PREC) {
                float4 va, vb;
                va.x = __uint_as_float(ah0); va.y = __uint_as_float(ah1);
                va.z = __uint_as_float(f2tf32(ra[i][0] - __uint_as_float(ah0)));
                va.w = __uint_as_float(f2tf32(ra[i][1] - __uint_as_float(ah1)));
                vb.x = __uint_as_float(bh0); vb.y = __uint_as_float(bh1);
                vb.z = __uint_as_float(f2tf32(rb[i][0] - __uint_as_float(bh0)));
                vb.w = __uint_as_float(f2tf32(rb[i][1] - __uint_as_float(bh1)));
                *reinterpret_cast<float4*>(Ap + idx) = va;
                *reinterpret_cast<float4*>(Bp + idx) = vb;
            } else {
                float2 va, vb;
                va.x = __uint_as_float(ah0); va.y = __uint_as_float(ah1);
                vb.x = __uint_as_float(bh0); vb.y = __uint_as_float(bh1);
                *reinterpret_cast<float2*>(Ap + idx) = va;
                *reinterpret_cast<float2*>(Bp + idx) = vb;
            }
        }
    };

    auto compute_stage = [&](int st) {
#pragma unroll
        for (int ks = 0; ks < 2; ks++) {
            uint32_t af[4][4], bf[4][2];
            uint32_t afl[4][4], bfl[4][2];
            const int base = (st * 2 + ks) * 128;
#pragma unroll
            for (int mi = 0; mi < 4; mi++) {
                int m0 = mbase + mi * 16 + gid;
                if constexpr (PREC) {
                    float4 v0 = reinterpret_cast<const float4*>(Ap)[(base + m0) * 4 + tig];
                    float4 v1 = reinterpret_cast<const float4*>(Ap)[(base + m0 + 8) * 4 + tig];
                    af[mi][0] = __float_as_uint(v0.x); af[mi][2] = __float_as_uint(v0.y);
                    afl[mi][0] = __float_as_uint(v0.z); afl[mi][2] = __float_as_uint(v0.w);
                    af[mi][1] = __float_as_uint(v1.x); af[mi][3] = __float_as_uint(v1.y);
                    afl[mi][1] = __float_as_uint(v1.z); afl[mi][3] = __float_as_uint(v1.w);
                } else {
                    float2 v0 = reinterpret_cast<const float2*>(Ap)[(base + m0) * 4 + tig];
                    float2 v1 = reinterpret_cast<const float2*>(Ap)[(base + m0 + 8) * 4 + tig];
                    af[mi][0] = __float_as_uint(v0.x); af[mi][2] = __float_as_uint(v0.y);
                    af[mi][1] = __float_as_uint(v1.x); af[mi][3] = __float_as_uint(v1.y);
                }
            }
#pragma unroll
            for (int ni = 0; ni < 4; ni++) {
                int n0 = nbase + ni * 8 + gid;
                if constexpr (PREC) {
                    float4 v = reinterpret_cast<const float4*>(Bp)[(base + n0) * 4 + tig];
                    bf[ni][0] = __float_as_uint(v.x); bf[ni][1] = __float_as_uint(v.y);
                    bfl[ni][0] = __float_as_uint(v.z); bfl[ni][1] = __float_as_uint(v.w);
                } else {
                    float2 v = reinterpret_cast<const float2*>(Bp)[(base + n0) * 4 + tig];
                    bf[ni][0] = __float_as_uint(v.x); bf[ni][1] = __float_as_uint(v.y);
                }
            }
#pragma unroll
            for (int mi = 0; mi < 4; mi++)
#pragma unroll
                for (int ni = 0; ni < 4; ni++) {
                    mma_tf32(acc[mi][ni], af[mi], bf[ni]);
                    if constexpr (PREC) {
                        mma_tf32(acc[mi][ni], af[mi], bfl[ni]);
                        mma_tf32(acc[mi][ni], afl[mi], bf[ni]);
                    }
                }
        }
    };

    const int niter = kend / 16;
    gload(0);
    int st = 0;
    for (int it = 0; it < niter; it++) {
        sstore(st);
        __syncthreads();
        if (it + 1 < niter) gload((it + 1) * 16);
        compute_stage(st);
        __syncthreads();
        st ^= 1;
    }

    // ---- epilogue ----
#pragma unroll
    for (int mi = 0; mi < 4; mi++) {
        int row0 = bm + mbase + mi * 16 + gid;
        int row1 = row0 + 8;
#pragma unroll
        for (int ni = 0; ni < 4; ni++) {
            int col = bn + nbase + ni * 8 + 2 * tig;
            float v0 = alpha * acc[mi][ni][0];
            float v1 = alpha * acc[mi][ni][1];
            float v2 = alpha * acc[mi][ni][2];
            float v3 = alpha * acc[mi][ni][3];
            if (beta != 0.f) {
                v0 += beta * C[(size_t)row0 * ldc + col];
                v1 += beta * C[(size_t)row0 * ldc + col + 1];
                v2 += beta * C[(size_t)row1 * ldc + col];
                v3 += beta * C[(size_t)row1 * ldc + col + 1];
            }
            if (bias) {
                v0 += bias[col]; v1 += bias[col + 1];
                v2 += bias[col]; v3 += bias[col + 1];
            }
            C[(size_t)row0 * ldc + col]     = v0;
            C[(size_t)row0 * ldc + col + 1] = v1;
            C[(size_t)row1 * ldc + col]     = v2;
            C[(size_t)row1 * ldc + col + 1] = v3;
        }
    }
}

// ---------------- top-16 read + softmax + context (warp per row) ------------
__global__ void topk_ctx_kernel(const float* __restrict__ logits,
                                const float* __restrict__ S,
                                float* __restrict__ ctx)
{
    int m = blockIdx.x * 8 + threadIdx.y;
    int lane = threadIdx.x;
    const float* lrow = logits + (size_t)m * CK;
    float v[16];
#pragma unroll
    for (int i = 0; i < 16; i++) v[i] = lrow[i * 32 + lane];
    float topv[CKR]; int topi[CKR];
    for (int it = 0; it < CKR; it++) {
        float bv = -INFINITY; int bi = 0x7fffffff;
#pragma unroll
        for (int i = 0; i < 16; i++) {
            if (v[i] > bv) { bv = v[i]; bi = i * 32 + lane; }
        }
#pragma unroll
        for (int off = 16; off > 0; off >>= 1) {
            float ov = __shfl_xor_sync(0xffffffffu, bv, off);
            int   oi = __shfl_xor_sync(0xffffffffu, bi, off);
            if (ov > bv || (ov == bv && oi < bi)) { bv = ov; bi = oi; }
        }
        topv[it] = bv; topi[it] = bi;
        if ((bi & 31) == lane) v[bi >> 5] = -INFINITY;
    }
    float p[CKR]; float s = 0.f;
#pragma unroll
    for (int i = 0; i < CKR; i++) { p[i] = expf(topv[i] - topv[0]); s += p[i]; }
    float inv = 1.f / s;
    float* crow = ctx + (size_t)m * CD;
    for (int d = lane; d < CD; d += 32) {
        float acc = 0.f;
#pragma unroll
        for (int i = 0; i < CKR; i++)
            acc += p[i] * S[(size_t)topi[i] * CD + d];
        crow[d] = acc * inv;
    }
}

// ---------------- instruction gate: sigmoid(Q.Wm + bm) ----------------------
__global__ void instr_kernel(const float* __restrict__ Q,
                             const float* __restrict__ Wm,
                             const float* __restrict__ bm_,
                             float* __restrict__ instr)
{
    int m = blockIdx.x * 8 + threadIdx.y;
    int lane = threadIdx.x;
    const float* q = Q + (size_t)m * CD;
    float s = 0.f;
    for (int d = lane; d < CD; d += 32) s = fmaf(q[d], Wm[d], s);
#pragma unroll
    for (int off = 16; off > 0; off >>= 1) s += __shfl_xor_sync(0xffffffffu, s, off);
    if (lane == 0) instr[m] = 1.f / (1.f + expf(-(s + bm_[0])));
}

// ---------------- causal row softmax in place -------------------------------
__global__ void softmax_causal_kernel(float* __restrict__ P)
{
    int b = blockIdx.y, q = blockIdx.x;
    float* row = P + ((size_t)b * CT + q) * CT;
    int n = q + 1;
    int tid = threadIdx.x;
    __shared__ float red[256];
    float mx = -INFINITY;
    for (int k = tid; k < n; k += 256) mx = fmaxf(mx, row[k]);
    red[tid] = mx; __syncthreads();
    for (int s = 128; s > 0; s >>= 1) { if (tid < s) red[tid] = fmaxf(red[tid], red[tid + s]); __syncthreads(); }
    mx = red[0]; __syncthreads();
    float sum = 0.f;
    for (int k = tid; k < n; k += 256) { float e = expf(row[k] - mx); row[k] = e; sum += e; }
    red[tid] = sum; __syncthreads();
    for (int s = 128; s > 0; s >>= 1) { if (tid < s) red[tid] += red[tid + s]; __syncthreads(); }
    float inv = 1.f / red[0];
    for (int k = tid; k < n; k += 256) row[k] *= inv;
    for (int k = n + tid; k < CT; k += 256) row[k] = 0.f;
}

// ---------------- elementwise combine: out = (1-p)*ctx + p*byp --------------
__global__ void combine_kernel(const float* __restrict__ ctx, const float* __restrict__ byp,
                               const float* __restrict__ instr, float* __restrict__ out)
{
    size_t i = (size_t)blockIdx.x * blockDim.x + threadIdx.x;
    if (i >= (size_t)CBT * CD) return;
    float p = instr[i / CD];
    out[i] = (1.f - p) * ctx[i] + p * byp[i];
}

// ---------------- row-normalize S -> Sn -------------------------------------
__global__ void sn_kernel(const float* __restrict__ S, float* __restrict__ Sn)
{
    int r = blockIdx.x * 8 + threadIdx.y;
    int lane = threadIdx.x;
    const float* row = S + (size_t)r * CD;
    float s = 0.f;
    for (int d = lane; d < CD; d += 32) { float v = row[d]; s = fmaf(v, v, s); }
#pragma unroll
    for (int off = 16; off > 0; off >>= 1) s += __shfl_xor_sync(0xffffffffu, s, off);
    float inv = 1.f / fmaxf(sqrtf(s), 1e-8f);
    for (int d = lane; d < CD; d += 32) Sn[(size_t)r * CD + d] = row[d] * inv;
}

// ---------------- V row norms ------------------------------------------------
__global__ void vnorm_kernel(const float* __restrict__ V, float* __restrict__ vn)
{
    int m = blockIdx.x * 8 + threadIdx.y;
    int lane = threadIdx.x;
    const float* row = V + (size_t)m * CD;
    float s = 0.f;
    for (int d = lane; d < CD; d += 32) { float v = row[d]; s = fmaf(v, v, s); }
#pragma unroll
    for (int off = 16; off > 0; off >>= 1) s += __shfl_xor_sync(0xffffffffu, s, off);
    if (lane == 0) vn[m] = sqrtf(s);
}

// ---------------- novelty = 1 - rowmax(sim)/max(|V|,eps) --------------------
__global__ void novelty_kernel(const float* __restrict__ sim, const float* __restrict__ vn,
                               float* __restrict__ nov)
{
    int m = blockIdx.x * 8 + threadIdx.y;
    int lane = threadIdx.x;
    const float* row = sim + (size_t)m * CK;
    float mx = -INFINITY;
    for (int k = lane; k < CK; k += 32) mx = fmaxf(mx, row[k]);
#pragma unroll
    for (int off = 16; off > 0; off >>= 1) mx = fmaxf(mx, __shfl_xor_sync(0xffffffffu, mx, off));
    if (lane == 0) nov[m] = 1.f - mx / fmaxf(vn[m], 1e-8f);
}

// ---------------- decay weights ---------------------------------------------
__global__ void wt_kernel(float* __restrict__ wt)
{
    int t = blockIdx.x * 256 + threadIdx.x;
    if (t >= CT) return;
    float denom = 1.f - powf(0.99f, (float)CT);
    wt[t] = powf(0.99f, (float)(CT - 1 - t)) * (0.01f / denom);
}

// ---------------- r_write epilogue: sigmoid(lin + nov*w0 + b) * wt[t] -------
__global__ void rw_epi_kernel(float* __restrict__ rw, const float* __restrict__ nov,
                              const float* __restrict__ Wn, const float* __restrict__ bn,
                              const float* __restrict__ wt)
{
    size_t i = (size_t)blockIdx.x * blockDim.x + threadIdx.x;
    if (i >= (size_t)CBT * CK) return;
    int m = (int)(i / CK), k = (int)(i % CK);
    float x = rw[i] + nov[m] * Wn[(size_t)k * (CD + 1)] + bn[k];
    rw[i] = (1.f / (1.f + expf(-x))) * wt[m % CT];
}

// ---------------- add eps*I to S_cov ----------------------------------------
__global__ void diag_eps_kernel(float* __restrict__ cov)
{
    int k = blockIdx.x * 256 + threadIdx.x;
    if (k < CK) cov[(size_t)k * CK + k] += 1e-5f;
}

// ---------------- Cholesky diagonal block (smem-resident, 1 block) ----------
__global__ void chol_diag_kernel(float* __restrict__ Am, int j)
{
    extern __shared__ float As[];           // 128x128 + col[128]
    float* col = As + 128 * 128;
    float* A = Am + (size_t)(j * 128) * CK + j * 128;   // ld = CK
    int tid = threadIdx.x;
    for (int i = tid; i < 128 * 128; i += 256)
        As[i] = A[(size_t)(i >> 7) * CK + (i & 127)];
    __syncthreads();
    for (int p = 0; p < 128; p++) {
        if (tid == 0) As[p * 128 + p] = sqrtf(As[p * 128 + p]);
        __syncthreads();
        float d = As[p * 128 + p];
        for (int r = p + 1 + tid; r < 128; r += 256) {
            float v = As[r * 128 + p] / d;
            As[r * 128 + p] = v;
            col[r] = v;
        }
        __syncthreads();
        int w = 127 - p;
        for (int idx = tid; idx < w * w; idx += 256) {
            int r = p + 1 + idx / w;
            int c = p + 1 + idx % w;
            As[r * 128 + c] -= col[r] * col[c];
        }
        __syncthreads();
    }
    for (int i = tid; i < 128 * 128; i += 256)
        A[(size_t)(i >> 7) * CK + (i & 127)] = As[i];
}

// ---------------- warp-per-row panel solve: X L_jj^T = panel ---------------
__global__ void chol_trsm_w(float* __restrict__ Am, int j)
{
    int w = blockIdx.x * (blockDim.x >> 5) + (threadIdx.x >> 5);
    int lane = threadIdx.x & 31;
    int i = (j + 1) * 128 + w;
    const float* L = Am + (size_t)(j * 128) * CK + j * 128;
    float* row = Am + (size_t)i * CK + j * 128;
    float f[4];
#pragma unroll
    for (int q = 0; q < 4; q++) f[q] = row[lane + 32 * q];
    for (int c = 0; c < 128; c++) {
        const float* Lr = L + (size_t)c * CK;
        float s = 0.f;
#pragma unroll
        for (int q = 0; q < 4; q++) {
            int qq = lane + 32 * q;
            if (qq < c) s = fmaf(Lr[qq], f[q], s);
        }
#pragma unroll
        for (int off = 16; off > 0; off >>= 1) s += __shfl_xor_sync(0xffffffffu, s, off);
        float rc = __shfl_sync(0xffffffffu, f[c >> 5], c & 31);
        float v = (rc - s) / Lr[c];
        if (lane == (c & 31)) f[c >> 5] = v;
    }
#pragma unroll
    for (int q = 0; q < 4; q++) row[lane + 32 * q] = f[q];
}

// ---------------- transpose diagonal L blocks for backward solve ------------
__global__ void transpose_diag_kernel(const float* __restrict__ cov, float* __restrict__ LT)
{
    int j = blockIdx.y;
    int idx = blockIdx.x * 256 + threadIdx.x;
    int p = idx >> 7, q = idx & 127;
    LT[j * 16384 + idx] = cov[(size_t)(j * 128 + q) * CK + j * 128 + p];
}

// ---------------- warp-per-column forward substitution ----------------------
__global__ void trisolve_fwd_w(const float* __restrict__ Am, float* __restrict__ Zm, int j)
{
    int w = blockIdx.x * (blockDim.x >> 5) + (threadIdx.x >> 5);   // column
    int lane = threadIdx.x & 31;
    const float* L = Am + (size_t)(j * 128) * CK + j * 128;
    float* Z = Zm + (size_t)(j * 128) * CD + w;
    float f[4];
#pragma unroll
    for (int q = 0; q < 4; q++) f[q] = Z[(size_t)(lane + 32 * q) * CD];
    for (int p = 0; p < 128; p++) {
        const float* Lr = L + (size_t)p * CK;
        float s = 0.f;
#pragma unroll
        for (int q = 0; q < 4; q++) {
            int qq = lane + 32 * q;
            if (qq < p) s = fmaf(Lr[qq], f[q], s);
        }
#pragma unroll
        for (int off = 16; off > 0; off >>= 1) s += __shfl_xor_sync(0xffffffffu, s, off);
        float zp = __shfl_sync(0xffffffffu, f[p >> 5], p & 31);
        float v = (zp - s) / Lr[p];
        if (lane == (p & 31)) f[p >> 5] = v;
    }
#pragma unroll
    for (int q = 0; q < 4; q++) Z[(size_t)(lane + 32 * q) * CD] = f[q];
}

// ---------------- warp-per-column backward substitution (uses LT) -----------
__global__ void trisolve_bwd_w(const float* __restrict__ LT, float* __restrict__ Zm, int j)
{
    int w = blockIdx.x * (blockDim.x >> 5) + (threadIdx.x >> 5);   // column
    int lane = threadIdx.x & 31;
    const float* Lt = LT + j * 16384;                  // Lt[p][q] = L[q][p]
    float* Z = Zm + (size_t)(j * 128) * CD + w;
    float f[4];
#pragma unroll
    for (int q = 0; q < 4; q++) f[q] = Z[(size_t)(lane + 32 * q) * CD];
    for (int p = 127; p >= 0; p--) {
        const float* Lr = Lt + p * 128;
        float s = 0.f;
#pragma unroll
        for (int q = 0; q < 4; q++) {
            int qq = lane + 32 * q;
            if (qq > p) s = fmaf(Lr[qq], f[q], s);
        }
#pragma unroll
        for (int off = 16; off > 0; off >>= 1) s += __shfl_xor_sync(0xffffffffu, s, off);
        float zp = __shfl_sync(0xffffffffu, f[p >> 5], p & 31);
        float v = (zp - s) / Lr[p];
        if (lane == (p & 31)) f[p >> 5] = v;
    }
#pragma unroll
    for (int q = 0; q < 4; q++) Z[(size_t)(lane + 32 * q) * CD] = f[q];
}

// ---------------- misc small kernels ----------------------------------------
__global__ void copy_kernel(const float* __restrict__ a, float* __restrict__ b, int n)
{
    int i = blockIdx.x * 256 + threadIdx.x;
    if (i < n) b[i] = a[i];
}

__global__ void init_out2_kernel(const float* __restrict__ S, const float* __restrict__ Vagg,
                                 float* __restrict__ out2)
{
    size_t i = (size_t)blockIdx.x * blockDim.x + threadIdx.x;
    if (i >= (size_t)CB * CK * CD) return;
    size_t kd = i % ((size_t)CK * CD);
    out2[i] = 0.99f * S[kd] + 0.1f * Vagg[i];
}

// ---------------- host launcher ---------------------------------------------
static void tgemm(bool TA, bool TB, bool prec,
                  const float* A, const float* B, float* C, const float* bias,
                  int M, int N, int Kd, int lda, int ldb, int ldc,
                  long long sA, long long sB, long long sC, int batch,
                  float alpha, float beta, int causal)
{
    dim3 grid(N / 128, M / 128, batch), block(256);
    int smem = prec ? (2 * 2 * 2 * 128 * 4 * 4 * 4) : (2 * 2 * 2 * 128 * 4 * 2 * 4);
#define DISP(ta, tb, pr) do { \
    cudaFuncSetAttribute(tgemm_kernel<ta, tb, pr>, cudaFuncAttributeMaxDynamicSharedMemorySize, smem); \
    tgemm_kernel<ta, tb, pr><<<grid, block, smem>>>(A, B, C, bias, M, N, Kd, lda, ldb, ldc, sA, sB, sC, alpha, beta, causal); \
} while (0)
    if (!prec) {
        if (!TA && !TB) DISP(false, false, false);
        else if (!TA && TB) DISP(false, true, false);
        else if (TA && !TB) DISP(true, false, false);
        else DISP(true, true, false);
    } else {
        if (!TA && !TB) DISP(false, false, true);
        else if (!TA && TB) DISP(false, true, true);
        else if (TA && !TB) DISP(true, false, true);
        else DISP(true, true, true);
    }
#undef DISP
}

extern "C" void kernel_launch(void* const* d_in, const int* in_sizes, int n_in,
                              void* d_out, int out_size)
{
    const float* x    = (const float*)d_in[0];
    const float* S    = (const float*)d_in[1];
    const float* Wq_w = (const float*)d_in[2];
    const float* Wq_b = (const float*)d_in[3];
    const float* Wv_w = (const float*)d_in[4];
    const float* Wv_b = (const float*)d_in[5];
    const float* Wn_w = (const float*)d_in[6];
    const float* Wn_b = (const float*)d_in[7];
    const float* Wm_w = (const float*)d_in[8];
    const float* Wm_b = (const float*)d_in[9];
    float* out  = (float*)d_out;                 // [B,T,D]
    float* out2 = out + (size_t)CBT * CD;        // [B,K,D] = S_next

    float *Q, *V, *logits, *ctx, *scores, *byp, *instr, *nov, *vn, *rw, *Sn, *Vagg, *T1, *cov, *Mm, *wt, *LT;
    cudaGetSymbolAddress((void**)&Q,      g_Q);
    cudaGetSymbolAddress((void**)&V,      g_V);
    cudaGetSymbolAddress((void**)&logits, g_logits);
    cudaGetSymbolAddress((void**)&ctx,    g_ctx);
    cudaGetSymbolAddress((void**)&scores, g_scores);
    cudaGetSymbolAddress((void**)&byp,    g_byp);
    cudaGetSymbolAddress((void**)&instr,  g_instr);
    cudaGetSymbolAddress((void**)&nov,    g_nov);
    cudaGetSymbolAddress((void**)&vn,     g_vnorm);
    cudaGetSymbolAddress((void**)&rw,     g_rw);
    cudaGetSymbolAddress((void**)&Sn,     g_Sn);
    cudaGetSymbolAddress((void**)&Vagg,   g_Vagg);
    cudaGetSymbolAddress((void**)&T1,     g_T1);
    cudaGetSymbolAddress((void**)&cov,    g_cov);
    cudaGetSymbolAddress((void**)&Mm,     g_Mm);
    cudaGetSymbolAddress((void**)&wt,     g_wt);
    cudaGetSymbolAddress((void**)&LT,     g_LT);

    const float inv_sqrt_d = 0.03125f;   // 1/sqrt(1024)

    // 1. Q = x Wq^T + bq (precise: feeds top-k); V = x Wv^T + bv (fast)
    tgemm(false, true, true,  x, Wq_w, Q, Wq_b, CBT, CD, CD, CD, CD, CD, 0, 0, 0, 1, 1.f, 0.f, 0);
    tgemm(false, true, false, x, Wv_w, V, Wv_b, CBT, CD, CD, CD, CD, CD, 0, 0, 0, 1, 1.f, 0.f, 0);
    wt_kernel<<<CT / 256, 256>>>(wt);

    // 2. read logits = Q S^T / 32 (precise: top-k tie-breaks); top-16 read
    tgemm(false, true, true, Q, S, logits, nullptr, CBT, CK, CD, CD, CD, CK, 0, 0, 0, 1, inv_sqrt_d, 0.f, 0);
    topk_ctx_kernel<<<CBT / 8, dim3(32, 8)>>>(logits, S, ctx);
    instr_kernel<<<CBT / 8, dim3(32, 8)>>>(Q, Wm_w, Wm_b, instr);

    // 3. causal self-attention bypass (materialized P) — fast tf32
    tgemm(false, true, false, Q, Q, scores, nullptr, CT, CT, CD, CD, CD, CT,
          (long long)CT * CD, (long long)CT * CD, (long long)CT * CT, CB, inv_sqrt_d, 0.f, 1);
    softmax_causal_kernel<<<dim3(CT, CB), 256>>>(scores);
    tgemm(false, false, false, scores, V, byp, nullptr, CT, CD, CT, CT, CD, CD,
          (long long)CT * CT, (long long)CT * CD, (long long)CT * CD, CB, 1.f, 0.f, 2);
    combine_kernel<<<(CBT * CD + 255) / 256, 256>>>(ctx, byp, instr, out);

    // 4. novelty — fast tf32 (max is continuous)
    sn_kernel<<<CK / 8, dim3(32, 8)>>>(S, Sn);
    vnorm_kernel<<<CBT / 8, dim3(32, 8)>>>(V, vn);
    tgemm(false, true, false, V, Sn, logits, nullptr, CBT, CK, CD, CD, CD, CK, 0, 0, 0, 1, 1.f, 0.f, 0);
    novelty_kernel<<<CBT / 8, dim3(32, 8)>>>(logits, vn, nov);

    // 5. r_write — fast tf32 (sigmoid continuous)
    tgemm(false, true, false, Q, Wn_w + 1, rw, nullptr, CBT, CK, CD, CD, CD + 1, CK, 0, 0, 0, 1, 1.f, 0.f, 0);
    rw_epi_kernel<<<(CBT * CK + 255) / 256, 256>>>(rw, nov, Wn_w, Wn_b, wt);

    // 6. V_agg[b] = rw[b]^T V[b] — fast tf32
    tgemm(true, false, false, rw, V, Vagg, nullptr, CK, CD, CT, CK, CD, CD,
          (long long)CT * CK, (long long)CT * CD, (long long)CK * CD, CB, 1.f, 0.f, 0);

    // 7. S_cov = S S^T + eps I (precise); blocked Cholesky NB=128
    tgemm(false, true, true, S, S, cov, nullptr, CK, CK, CD, CD, CD, CK, 0, 0, 0, 1, 1.f, 0.f, 0);
    diag_eps_kernel<<<2, 256>>>(cov);
    {
        int chol_smem = 128 * 128 * 4 + 128 * 4;
        cudaFuncSetAttribute(chol_diag_kernel, cudaFuncAttributeMaxDynamicSharedMemorySize, chol_smem);
        for (int j = 0; j < 4; j++) {
            chol_diag_kernel<<<1, 256, chol_smem>>>(cov, j);
            if (j < 3) {
                int rows = (3 - j) * 128;
                chol_trsm_w<<<rows / 8, 256>>>(cov, j);
                float* Ct = cov + (size_t)(j + 1) * 128 * CK + (j + 1) * 128;
                const float* P = cov + (size_t)(j + 1) * 128 * CK + j * 128;
                tgemm(false, true, true, P, P, Ct, nullptr, rows, rows, 128, CK, CK, CK, 0, 0, 0, 1, -1.f, 1.f, 0);
            }
        }
    }
    transpose_diag_kernel<<<dim3(64, 4), 256>>>(cov, LT);

    // 8. solve S_cov * Mm = S  (Mm = Cinv S) — warp-cooperative substitutions
    copy_kernel<<<(CK * CD + 255) / 256, 256>>>(S, Mm, CK * CD);
    for (int j = 0; j < 4; j++) {
        if (j > 0)
            tgemm(false, false, true, cov + (size_t)j * 128 * CK, Mm, Mm + (size_t)j * 128 * CD, nullptr,
                  128, CD, j * 128, CK, CD, CD, 0, 0, 0, 1, -1.f, 1.f, 0);
        trisolve_fwd_w<<<CD / 8, 256>>>(cov, Mm, j);
    }
    for (int j = 3; j >= 0; j--) {
        if (j < 3) {
            int s = (3 - j) * 128;
            tgemm(true, false, true, cov + (size_t)(j + 1) * 128 * CK + j * 128, Mm + (size_t)(j + 1) * 128 * CD,
                  Mm + (size_t)j * 128 * CD, nullptr, 128, CD, s, CK, CD, CD, 0, 0, 0, 1, -1.f, 1.f, 0);
        }
        trisolve_bwd_w<<<CD / 8, 256>>>(LT, Mm, j);
    }

    // 9. S_next = 0.99 S + 0.1 (V_agg - (V_agg S^T) Mm) — precise
    tgemm(false, true, true, Vagg, S, T1, nullptr, CK, CK, CD, CD, CD, CK,
          (long long)CK * CD, 0, (long long)CK * CK, CB, 1.f, 0.f, 0);
    init_out2_kernel<<<(CB * CK * CD + 255) / 256, 256>>>(S, Vagg, out2);
    tgemm(false, false, true, T1, Mm, out2, nullptr, CK, CD, CK, CK, CD, CD,
          (long long)CK * CK, 0, (long long)CK * CD, CB, -0.1f, 1.f, 0);
}

// round 5
// speedup vs baseline: 2.8364x; 1.3117x over previous
#include <cuda_runtime.h>
#include <math.h>
#include <stdint.h>

#define CB 4
#define CT 2048
#define CD 1024
#define CK 512
#define CKR 16
#define CBT 8192   // CB*CT

// ---------------- scratch (static device globals; no allocs) ----------------
__device__ float g_Q[CBT*CD];
__device__ float g_V[CBT*CD];
__device__ float g_logits[CBT*CK];
__device__ float g_sim[CBT*CK];
__device__ float g_ctx[CBT*CD];
__device__ float g_scores[(size_t)CB*CT*CT];
__device__ float g_byp[CBT*CD];
__device__ float g_instr[CBT];
__device__ float g_nov[CBT];
__device__ float g_vnorm[CBT];
__device__ float g_rw[CBT*CK];
__device__ float g_Sn[CK*CD];
__device__ float g_Vagg[CB*CK*CD];
__device__ float g_T1[CB*CK*CK];
__device__ float g_cov[CK*CK];
__device__ float g_Mm[CK*CD];
__device__ float g_wt[CT];
__device__ float g_LT[4*128*128];       // transposed diagonal L blocks

// ---------------- tf32 helpers ----------------------------------------------
__device__ __forceinline__ uint32_t f2tf32(float x) {
    uint32_t r;
    asm("cvt.rna.tf32.f32 %0, %1;" : "=r"(r) : "f"(x));
    return r;
}

__device__ __forceinline__ void mma_tf32(float* c, const uint32_t* a, const uint32_t* b) {
    asm volatile(
        "mma.sync.aligned.m16n8k8.row.col.f32.tf32.tf32.f32 "
        "{%0,%1,%2,%3}, {%4,%5,%6,%7}, {%8,%9}, {%0,%1,%2,%3};"
        : "+f"(c[0]), "+f"(c[1]), "+f"(c[2]), "+f"(c[3])
        : "r"(a[0]), "r"(a[1]), "r"(a[2]), "r"(a[3]), "r"(b[0]), "r"(b[1]));
}

// ---------------- tensor-core GEMM: C = beta*C + alpha*op(A)op(B) (+bias) ---
template<bool TA, bool TB, bool PREC>
__global__ void __launch_bounds__(256) tgemm_kernel(
    const float* __restrict__ A, const float* __restrict__ B,
    float* __restrict__ C, const float* __restrict__ bias,
    int M, int N, int Kd, int lda, int ldb, int ldc,
    long long sA, long long sB, long long sC,
    float alpha, float beta, int causal)
{
    constexpr int PK = PREC ? 4 : 2;      // floats per pack
    const int bm = blockIdx.y * 128;
    const int bn = blockIdx.x * 128;
    if (causal == 1 && bn > bm + 127) return;
    A += sA * blockIdx.z;
    B += sB * blockIdx.z;
    C += sC * blockIdx.z;
    const int kend = (causal == 2) ? min(Kd, bm + 128) : Kd;

    extern __shared__ float sm[];
    float* Ap = sm;                        // [2 st][2 ks][128 m][4 tig][PK]
    float* Bp = sm + 2 * 2 * 128 * 4 * PK;

    const int tid = threadIdx.x;
    const int lane = tid & 31;
    const int wid = tid >> 5;
    const int warp_m = wid >> 2;
    const int warp_n = wid & 3;
    const int gid = lane >> 2;
    const int tig = lane & 3;
    const int mbase = warp_m * 64;
    const int nbase = warp_n * 32;

    float acc[4][4][4];
#pragma unroll
    for (int i = 0; i < 4; i++)
#pragma unroll
        for (int j = 0; j < 4; j++)
#pragma unroll
            for (int r = 0; r < 4; r++) acc[i][j][r] = 0.f;

    // precomputed per-thread global pointers (increment by fixed stride)
    const float *pA[4], *pB[4];
    const int offA = (!TA) ? 4 : 4 * lda;
    const int offB = (!TB) ? 4 * ldb : 4;
    const long long stepA = (!TA) ? 16 : (long long)16 * lda;
    const long long stepB = (!TB) ? (long long)16 * ldb : 16;
#pragma unroll
    for (int i = 0; i < 4; i++) {
        int e = tid + 256 * i;
        int tg = e & 3, ks = (e >> 2) & 1, m = e >> 3;
        int k = ks * 8 + tg;
        pA[i] = (!TA) ? (A + (size_t)(bm + m) * lda + k) : (A + (size_t)k * lda + bm + m);
        pB[i] = (!TB) ? (B + (size_t)k * ldb + bn + m) : (B + (size_t)(bn + m) * ldb + k);
    }

    float ra[4][2], rb[4][2];

    auto gload = [&]() {
#pragma unroll
        for (int i = 0; i < 4; i++) {
            ra[i][0] = pA[i][0]; ra[i][1] = pA[i][offA]; pA[i] += stepA;
            rb[i][0] = pB[i][0]; rb[i][1] = pB[i][offB]; pB[i] += stepB;
        }
    };

    auto sstore = [&](int st) {
#pragma unroll
        for (int i = 0; i < 4; i++) {
            int e = tid + 256 * i;
            int tg = e & 3, ks = (e >> 2) & 1, m = e >> 3;
            int idx = (((st * 2 + ks) * 128 + m) * 4 + tg) * PK;
            uint32_t ah0 = f2tf32(ra[i][0]), ah1 = f2tf32(ra[i][1]);
            uint32_t bh0 = f2tf32(rb[i][0]), bh1 = f2tf32(rb[i][1]);
            if constexpr (PREC) {
                float4 va, vb;
                va.x = __uint_as_float(ah0); va.y = __uint_as_float(ah1);
                va.z = __uint_as_float(f2tf32(ra[i][0] - __uint_as_float(ah0)));
                va.w = __uint_as_float(f2tf32(ra[i][1] - __uint_as_float(ah1)));
                vb.x = __uint_as_float(bh0); vb.y = __uint_as_float(bh1);
                vb.z = __uint_as_float(f2tf32(rb[i][0] - __uint_as_float(bh0)));
                vb.w = __uint_as_float(f2tf32(rb[i][1] - __uint_as_float(bh1)));
                *reinterpret_cast<float4*>(Ap + idx) = va;
                *reinterpret_cast<float4*>(Bp + idx) = vb;
            } else {
                float2 va, vb;
                va.x = __uint_as_float(ah0); va.y = __uint_as_float(ah1);
                vb.x = __uint_as_float(bh0); vb.y = __uint_as_float(bh1);
                *reinterpret_cast<float2*>(Ap + idx) = va;
                *reinterpret_cast<float2*>(Bp + idx) = vb;
            }
        }
    };

    auto compute_stage = [&](int st) {
#pragma unroll
        for (int ks = 0; ks < 2; ks++) {
            uint32_t af[4][4], bf[4][2];
            uint32_t afl[4][4], bfl[4][2];
            const int base = (st * 2 + ks) * 128;
#pragma unroll
            for (int mi = 0; mi < 4; mi++) {
                int m0 = mbase + mi * 16 + gid;
                if constexpr (PREC) {
                    float4 v0 = reinterpret_cast<const float4*>(Ap)[(base + m0) * 4 + tig];
                    float4 v1 = reinterpret_cast<const float4*>(Ap)[(base + m0 + 8) * 4 + tig];
                    af[mi][0] = __float_as_uint(v0.x); af[mi][2] = __float_as_uint(v0.y);
                    afl[mi][0] = __float_as_uint(v0.z); afl[mi][2] = __float_as_uint(v0.w);
                    af[mi][1] = __float_as_uint(v1.x); af[mi][3] = __float_as_uint(v1.y);
                    afl[mi][1] = __float_as_uint(v1.z); afl[mi][3] = __float_as_uint(v1.w);
                } else {
                    float2 v0 = reinterpret_cast<const float2*>(Ap)[(base + m0) * 4 + tig];
                    float2 v1 = reinterpret_cast<const float2*>(Ap)[(base + m0 + 8) * 4 + tig];
                    af[mi][0] = __float_as_uint(v0.x); af[mi][2] = __float_as_uint(v0.y);
                    af[mi][1] = __float_as_uint(v1.x); af[mi][3] = __float_as_uint(v1.y);
                }
            }
#pragma unroll
            for (int ni = 0; ni < 4; ni++) {
                int n0 = nbase + ni * 8 + gid;
                if constexpr (PREC) {
                    float4 v = reinterpret_cast<const float4*>(Bp)[(base + n0) * 4 + tig];
                    bf[ni][0] = __float_as_uint(v.x); bf[ni][1] = __float_as_uint(v.y);
                    bfl[ni][0] = __float_as_uint(v.z); bfl[ni][1] = __float_as_uint(v.w);
                } else {
                    float2 v = reinterpret_cast<const float2*>(Bp)[(base + n0) * 4 + tig];
                    bf[ni][0] = __float_as_uint(v.x); bf[ni][1] = __float_as_uint(v.y);
                }
            }
#pragma unroll
            for (int mi = 0; mi < 4; mi++)
#pragma unroll
                for (int ni = 0; ni < 4; ni++) {
                    mma_tf32(acc[mi][ni], af[mi], bf[ni]);
                    if constexpr (PREC) {
                        mma_tf32(acc[mi][ni], af[mi], bfl[ni]);
                        mma_tf32(acc[mi][ni], afl[mi], bf[ni]);
                    }
                }
        }
    };

    const int niter = kend / 16;
    gload();
    int st = 0;
    for (int it = 0; it < niter; it++) {
        sstore(st);
        __syncthreads();
        if (it + 1 < niter) gload();
        compute_stage(st);
        __syncthreads();
        st ^= 1;
    }

    // ---- epilogue ----
#pragma unroll
    for (int mi = 0; mi < 4; mi++) {
        int row0 = bm + mbase + mi * 16 + gid;
        int row1 = row0 + 8;
#pragma unroll
        for (int ni = 0; ni < 4; ni++) {
            int col = bn + nbase + ni * 8 + 2 * tig;
            float v0 = alpha * acc[mi][ni][0];
            float v1 = alpha * acc[mi][ni][1];
            float v2 = alpha * acc[mi][ni][2];
            float v3 = alpha * acc[mi][ni][3];
            if (beta != 0.f) {
                v0 += beta * C[(size_t)row0 * ldc + col];
                v1 += beta * C[(size_t)row0 * ldc + col + 1];
                v2 += beta * C[(size_t)row1 * ldc + col];
                v3 += beta * C[(size_t)row1 * ldc + col + 1];
            }
            if (bias) {
                v0 += bias[col]; v1 += bias[col + 1];
                v2 += bias[col]; v3 += bias[col + 1];
            }
            C[(size_t)row0 * ldc + col]     = v0;
            C[(size_t)row0 * ldc + col + 1] = v1;
            C[(size_t)row1 * ldc + col]     = v2;
            C[(size_t)row1 * ldc + col + 1] = v3;
        }
    }
}

// ---------------- top-16 read + softmax + context (warp per row) ------------
__global__ void topk_ctx_kernel(const float* __restrict__ logits,
                                const float* __restrict__ S,
                                float* __restrict__ ctx)
{
    int m = blockIdx.x * 8 + threadIdx.y;
    int lane = threadIdx.x;
    const float* lrow = logits + (size_t)m * CK;
    float v[16];
#pragma unroll
    for (int i = 0; i < 16; i++) v[i] = lrow[i * 32 + lane];
    float topv[CKR]; int topi[CKR];
    for (int it = 0; it < CKR; it++) {
        float bv = -INFINITY; int bi = 0x7fffffff;
#pragma unroll
        for (int i = 0; i < 16; i++) {
            if (v[i] > bv) { bv = v[i]; bi = i * 32 + lane; }
        }
#pragma unroll
        for (int off = 16; off > 0; off >>= 1) {
            float ov = __shfl_xor_sync(0xffffffffu, bv, off);
            int   oi = __shfl_xor_sync(0xffffffffu, bi, off);
            if (ov > bv || (ov == bv && oi < bi)) { bv = ov; bi = oi; }
        }
        topv[it] = bv; topi[it] = bi;
        if ((bi & 31) == lane) v[bi >> 5] = -INFINITY;
    }
    float p[CKR]; float s = 0.f;
#pragma unroll
    for (int i = 0; i < CKR; i++) { p[i] = expf(topv[i] - topv[0]); s += p[i]; }
    float inv = 1.f / s;
    float* crow = ctx + (size_t)m * CD;
    for (int d = lane; d < CD; d += 32) {
        float acc = 0.f;
#pragma unroll
        for (int i = 0; i < CKR; i++)
            acc += p[i] * S[(size_t)topi[i] * CD + d];
        crow[d] = acc * inv;
    }
}

// ---------------- instruction gate: sigmoid(Q.Wm + bm) ----------------------
__global__ void instr_kernel(const float* __restrict__ Q,
                             const float* __restrict__ Wm,
                             const float* __restrict__ bm_,
                             float* __restrict__ instr)
{
    int m = blockIdx.x * 8 + threadIdx.y;
    int lane = threadIdx.x;
    const float* q = Q + (size_t)m * CD;
    float s = 0.f;
    for (int d = lane; d < CD; d += 32) s = fmaf(q[d], Wm[d], s);
#pragma unroll
    for (int off = 16; off > 0; off >>= 1) s += __shfl_xor_sync(0xffffffffu, s, off);
    if (lane == 0) instr[m] = 1.f / (1.f + expf(-(s + bm_[0])));
}

// ---------------- causal row softmax in place -------------------------------
__global__ void softmax_causal_kernel(float* __restrict__ P)
{
    int b = blockIdx.y, q = blockIdx.x;
    float* row = P + ((size_t)b * CT + q) * CT;
    int n = q + 1;
    int kmax = ((q >> 7) + 1) << 7;      // only fill zeros read by P@V
    int tid = threadIdx.x;
    __shared__ float red[256];
    float mx = -INFINITY;
    for (int k = tid; k < n; k += 256) mx = fmaxf(mx, row[k]);
    red[tid] = mx; __syncthreads();
    for (int s = 128; s > 0; s >>= 1) { if (tid < s) red[tid] = fmaxf(red[tid], red[tid + s]); __syncthreads(); }
    mx = red[0]; __syncthreads();
    float sum = 0.f;
    for (int k = tid; k < n; k += 256) { float e = expf(row[k] - mx); row[k] = e; sum += e; }
    red[tid] = sum; __syncthreads();
    for (int s = 128; s > 0; s >>= 1) { if (tid < s) red[tid] += red[tid + s]; __syncthreads(); }
    float inv = 1.f / red[0];
    for (int k = tid; k < n; k += 256) row[k] *= inv;
    for (int k = n + tid; k < kmax; k += 256) row[k] = 0.f;
}

// ---------------- elementwise combine: out = (1-p)*ctx + p*byp --------------
__global__ void combine_kernel(const float* __restrict__ ctx, const float* __restrict__ byp,
                               const float* __restrict__ instr, float* __restrict__ out)
{
    size_t i = (size_t)blockIdx.x * blockDim.x + threadIdx.x;
    if (i >= (size_t)CBT * CD) return;
    float p = instr[i / CD];
    out[i] = (1.f - p) * ctx[i] + p * byp[i];
}

// ---------------- row-normalize S -> Sn -------------------------------------
__global__ void sn_kernel(const float* __restrict__ S, float* __restrict__ Sn)
{
    int r = blockIdx.x * 8 + threadIdx.y;
    int lane = threadIdx.x;
    const float* row = S + (size_t)r * CD;
    float s = 0.f;
    for (int d = lane; d < CD; d += 32) { float v = row[d]; s = fmaf(v, v, s); }
#pragma unroll
    for (int off = 16; off > 0; off >>= 1) s += __shfl_xor_sync(0xffffffffu, s, off);
    float inv = 1.f / fmaxf(sqrtf(s), 1e-8f);
    for (int d = lane; d < CD; d += 32) Sn[(size_t)r * CD + d] = row[d] * inv;
}

// ---------------- V row norms ------------------------------------------------
__global__ void vnorm_kernel(const float* __restrict__ V, float* __restrict__ vn)
{
    int m = blockIdx.x * 8 + threadIdx.y;
    int lane = threadIdx.x;
    const float* row = V + (size_t)m * CD;
    float s = 0.f;
    for (int d = lane; d < CD; d += 32) { float v = row[d]; s = fmaf(v, v, s); }
#pragma unroll
    for (int off = 16; off > 0; off >>= 1) s += __shfl_xor_sync(0xffffffffu, s, off);
    if (lane == 0) vn[m] = sqrtf(s);
}

// ---------------- novelty = 1 - rowmax(sim)/max(|V|,eps) --------------------
__global__ void novelty_kernel(const float* __restrict__ sim, const float* __restrict__ vn,
                               float* __restrict__ nov)
{
    int m = blockIdx.x * 8 + threadIdx.y;
    int lane = threadIdx.x;
    const float* row = sim + (size_t)m * CK;
    float mx = -INFINITY;
    for (int k = lane; k < CK; k += 32) mx = fmaxf(mx, row[k]);
#pragma unroll
    for (int off = 16; off > 0; off >>= 1) mx = fmaxf(mx, __shfl_xor_sync(0xffffffffu, mx, off));
    if (lane == 0) nov[m] = 1.f - mx / fmaxf(vn[m], 1e-8f);
}

// ---------------- decay weights ---------------------------------------------
__global__ void wt_kernel(float* __restrict__ wt)
{
    int t = blockIdx.x * 256 + threadIdx.x;
    if (t >= CT) return;
    float denom = 1.f - powf(0.99f, (float)CT);
    wt[t] = powf(0.99f, (float)(CT - 1 - t)) * (0.01f / denom);
}

// ---------------- r_write epilogue: sigmoid(lin + nov*w0 + b) * wt[t] -------
__global__ void rw_epi_kernel(float* __restrict__ rw, const float* __restrict__ nov,
                              const float* __restrict__ Wn, const float* __restrict__ bn,
                              const float* __restrict__ wt)
{
    size_t i = (size_t)blockIdx.x * blockDim.x + threadIdx.x;
    if (i >= (size_t)CBT * CK) return;
    int m = (int)(i / CK), k = (int)(i % CK);
    float x = rw[i] + nov[m] * Wn[(size_t)k * (CD + 1)] + bn[k];
    rw[i] = (1.f / (1.f + expf(-x))) * wt[m % CT];
}

// ---------------- add eps*I to S_cov ----------------------------------------
__global__ void diag_eps_kernel(float* __restrict__ cov)
{
    int k = blockIdx.x * 256 + threadIdx.x;
    if (k < CK) cov[(size_t)k * CK + k] += 1e-5f;
}

// ---------------- Cholesky diagonal block (smem-resident, 1 block) ----------
__global__ void chol_diag_kernel(float* __restrict__ Am, int j)
{
    extern __shared__ float As[];           // 128x128 + col[128]
    float* col = As + 128 * 128;
    float* A = Am + (size_t)(j * 128) * CK + j * 128;   // ld = CK
    int tid = threadIdx.x;
    for (int i = tid; i < 128 * 128; i += 256)
        As[i] = A[(size_t)(i >> 7) * CK + (i & 127)];
    __syncthreads();
    for (int p = 0; p < 128; p++) {
        if (tid == 0) As[p * 128 + p] = sqrtf(As[p * 128 + p]);
        __syncthreads();
        float d = As[p * 128 + p];
        for (int r = p + 1 + tid; r < 128; r += 256) {
            float v = As[r * 128 + p] / d;
            As[r * 128 + p] = v;
            col[r] = v;
        }
        __syncthreads();
        int w = 127 - p;
        for (int idx = tid; idx < w * w; idx += 256) {
            int r = p + 1 + idx / w;
            int c = p + 1 + idx % w;
            As[r * 128 + c] -= col[r] * col[c];
        }
        __syncthreads();
    }
    for (int i = tid; i < 128 * 128; i += 256)
        A[(size_t)(i >> 7) * CK + (i & 127)] = As[i];
}

// ---------------- warp-per-row panel solve: X L_jj^T = panel ---------------
__global__ void chol_trsm_w(float* __restrict__ Am, int j)
{
    int w = blockIdx.x * (blockDim.x >> 5) + (threadIdx.x >> 5);
    int lane = threadIdx.x & 31;
    int i = (j + 1) * 128 + w;
    const float* L = Am + (size_t)(j * 128) * CK + j * 128;
    float* row = Am + (size_t)i * CK + j * 128;
    float f[4];
#pragma unroll
    for (int q = 0; q < 4; q++) f[q] = row[lane + 32 * q];
    for (int c = 0; c < 128; c++) {
        const float* Lr = L + (size_t)c * CK;
        float s = 0.f;
#pragma unroll
        for (int q = 0; q < 4; q++) {
            int qq = lane + 32 * q;
            if (qq < c) s = fmaf(Lr[qq], f[q], s);
        }
#pragma unroll
        for (int off = 16; off > 0; off >>= 1) s += __shfl_xor_sync(0xffffffffu, s, off);
        float rc = __shfl_sync(0xffffffffu, f[c >> 5], c & 31);
        float v = (rc - s) / Lr[c];
        if (lane == (c & 31)) f[c >> 5] = v;
    }
#pragma unroll
    for (int q = 0; q < 4; q++) row[lane + 32 * q] = f[q];
}

// ---------------- transpose diagonal L blocks for backward solve ------------
__global__ void transpose_diag_kernel(const float* __restrict__ cov, float* __restrict__ LT)
{
    int j = blockIdx.y;
    int idx = blockIdx.x * 256 + threadIdx.x;
    int p = idx >> 7, q = idx & 127;
    LT[j * 16384 + idx] = cov[(size_t)(j * 128 + q) * CK + j * 128 + p];
}

// ---------------- warp-per-column forward substitution ----------------------
__global__ void trisolve_fwd_w(const float* __restrict__ Am, float* __restrict__ Zm, int j)
{
    int w = blockIdx.x * (blockDim.x >> 5) + (threadIdx.x >> 5);   // column
    int lane = threadIdx.x & 31;
    const float* L = Am + (size_t)(j * 128) * CK + j * 128;
    float* Z = Zm + (size_t)(j * 128) * CD + w;
    float f[4];
#pragma unroll
    for (int q = 0; q < 4; q++) f[q] = Z[(size_t)(lane + 32 * q) * CD];
    for (int p = 0; p < 128; p++) {
        const float* Lr = L + (size_t)p * CK;
        float s = 0.f;
#pragma unroll
        for (int q = 0; q < 4; q++) {
            int qq = lane + 32 * q;
            if (qq < p) s = fmaf(Lr[qq], f[q], s);
        }
#pragma unroll
        for (int off = 16; off > 0; off >>= 1) s += __shfl_xor_sync(0xffffffffu, s, off);
        float zp = __shfl_sync(0xffffffffu, f[p >> 5], p & 31);
        float v = (zp - s) / Lr[p];
        if (lane == (p & 31)) f[p >> 5] = v;
    }
#pragma unroll
    for (int q = 0; q < 4; q++) Z[(size_t)(lane + 32 * q) * CD] = f[q];
}

// ---------------- warp-per-column backward substitution (uses LT) -----------
__global__ void trisolve_bwd_w(const float* __restrict__ LT, float* __restrict__ Zm, int j)
{
    int w = blockIdx.x * (blockDim.x >> 5) + (threadIdx.x >> 5);   // column
    int lane = threadIdx.x & 31;
    const float* Lt = LT + j * 16384;                  // Lt[p][q] = L[q][p]
    float* Z = Zm + (size_t)(j * 128) * CD + w;
    float f[4];
#pragma unroll
    for (int q = 0; q < 4; q++) f[q] = Z[(size_t)(lane + 32 * q) * CD];
    for (int p = 127; p >= 0; p--) {
        const float* Lr = Lt + p * 128;
        float s = 0.f;
#pragma unroll
        for (int q = 0; q < 4; q++) {
            int qq = lane + 32 * q;
            if (qq > p) s = fmaf(Lr[qq], f[q], s);
        }
#pragma unroll
        for (int off = 16; off > 0; off >>= 1) s += __shfl_xor_sync(0xffffffffu, s, off);
        float zp = __shfl_sync(0xffffffffu, f[p >> 5], p & 31);
        float v = (zp - s) / Lr[p];
        if (lane == (p & 31)) f[p >> 5] = v;
    }
#pragma unroll
    for (int q = 0; q < 4; q++) Z[(size_t)(lane + 32 * q) * CD] = f[q];
}

// ---------------- misc small kernels ----------------------------------------
__global__ void copy_kernel(const float* __restrict__ a, float* __restrict__ b, int n)
{
    int i = blockIdx.x * 256 + threadIdx.x;
    if (i < n) b[i] = a[i];
}

__global__ void init_out2_kernel(const float* __restrict__ S, const float* __restrict__ Vagg,
                                 float* __restrict__ out2)
{
    size_t i = (size_t)blockIdx.x * blockDim.x + threadIdx.x;
    if (i >= (size_t)CB * CK * CD) return;
    size_t kd = i % ((size_t)CK * CD);
    out2[i] = 0.99f * S[kd] + 0.1f * Vagg[i];
}

// ---------------- host launcher ---------------------------------------------
static void tgemm(cudaStream_t st, bool TA, bool TB, bool prec,
                  const float* A, const float* B, float* C, const float* bias,
                  int M, int N, int Kd, int lda, int ldb, int ldc,
                  long long sA, long long sB, long long sC, int batch,
                  float alpha, float beta, int causal)
{
    dim3 grid(N / 128, M / 128, batch), block(256);
    int smem = prec ? (2 * 2 * 2 * 128 * 4 * 4 * 4) : (2 * 2 * 2 * 128 * 4 * 2 * 4);
#define DISP(ta, tb, pr) do { \
    cudaFuncSetAttribute(tgemm_kernel<ta, tb, pr>, cudaFuncAttributeMaxDynamicSharedMemorySize, smem); \
    tgemm_kernel<ta, tb, pr><<<grid, block, smem, st>>>(A, B, C, bias, M, N, Kd, lda, ldb, ldc, sA, sB, sC, alpha, beta, causal); \
} while (0)
    if (!prec) {
        if (!TA && !TB) DISP(false, false, false);
        else if (!TA && TB) DISP(false, true, false);
        else if (TA && !TB) DISP(true, false, false);
        else DISP(true, true, false);
    } else {
        if (!TA && !TB) DISP(false, false, true);
        else if (!TA && TB) DISP(false, true, true);
        else if (TA && !TB) DISP(true, false, true);
        else DISP(true, true, true);
    }
#undef DISP
}

extern "C" void kernel_launch(void* const* d_in, const int* in_sizes, int n_in,
                              void* d_out, int out_size)
{
    const float* x    = (const float*)d_in[0];
    const float* S    = (const float*)d_in[1];
    const float* Wq_w = (const float*)d_in[2];
    const float* Wq_b = (const float*)d_in[3];
    const float* Wv_w = (const float*)d_in[4];
    const float* Wv_b = (const float*)d_in[5];
    const float* Wn_w = (const float*)d_in[6];
    const float* Wn_b = (const float*)d_in[7];
    const float* Wm_w = (const float*)d_in[8];
    const float* Wm_b = (const float*)d_in[9];
    float* out  = (float*)d_out;                 // [B,T,D]
    float* out2 = out + (size_t)CBT * CD;        // [B,K,D] = S_next

    float *Q, *V, *logits, *sim, *ctx, *scores, *byp, *instr, *nov, *vn, *rw, *Sn, *Vagg, *T1, *cov, *Mm, *wt, *LT;
    cudaGetSymbolAddress((void**)&Q,      g_Q);
    cudaGetSymbolAddress((void**)&V,      g_V);
    cudaGetSymbolAddress((void**)&logits, g_logits);
    cudaGetSymbolAddress((void**)&sim,    g_sim);
    cudaGetSymbolAddress((void**)&ctx,    g_ctx);
    cudaGetSymbolAddress((void**)&scores, g_scores);
    cudaGetSymbolAddress((void**)&byp,    g_byp);
    cudaGetSymbolAddress((void**)&instr,  g_instr);
    cudaGetSymbolAddress((void**)&nov,    g_nov);
    cudaGetSymbolAddress((void**)&vn,     g_vnorm);
    cudaGetSymbolAddress((void**)&rw,     g_rw);
    cudaGetSymbolAddress((void**)&Sn,     g_Sn);
    cudaGetSymbolAddress((void**)&Vagg,   g_Vagg);
    cudaGetSymbolAddress((void**)&T1,     g_T1);
    cudaGetSymbolAddress((void**)&cov,    g_cov);
    cudaGetSymbolAddress((void**)&Mm,     g_Mm);
    cudaGetSymbolAddress((void**)&wt,     g_wt);
    cudaGetSymbolAddress((void**)&LT,     g_LT);

    // ---- streams / events (created once; handles only, no device allocs) ----
    static cudaStream_t sV = nullptr, sS = nullptr;
    static cudaEvent_t eFork = nullptr, eV = nullptr, eSn = nullptr, eNov = nullptr, eMm = nullptr;
    if (!sV) {
        cudaStreamCreateWithFlags(&sV, cudaStreamNonBlocking);
        cudaStreamCreateWithFlags(&sS, cudaStreamNonBlocking);
        cudaEventCreateWithFlags(&eFork, cudaEventDisableTiming);
        cudaEventCreateWithFlags(&eV,    cudaEventDisableTiming);
        cudaEventCreateWithFlags(&eSn,   cudaEventDisableTiming);
        cudaEventCreateWithFlags(&eNov,  cudaEventDisableTiming);
        cudaEventCreateWithFlags(&eMm,   cudaEventDisableTiming);
    }

    const float inv_sqrt_d = 0.03125f;   // 1/sqrt(1024)
    const cudaStream_t M0 = 0;

    // ================= fork =================
    cudaEventRecord(eFork, M0);
    cudaStreamWaitEvent(sV, eFork, 0);
    cudaStreamWaitEvent(sS, eFork, 0);

    // ---- stream sS: everything that depends only on S (Sn, cov, chol, Mm) ---
    sn_kernel<<<CK / 8, dim3(32, 8), 0, sS>>>(S, Sn);
    cudaEventRecord(eSn, sS);
    tgemm(sS, false, true, true, S, S, cov, nullptr, CK, CK, CD, CD, CD, CK, 0, 0, 0, 1, 1.f, 0.f, 0);
    diag_eps_kernel<<<2, 256, 0, sS>>>(cov);
    {
        int chol_smem = 128 * 128 * 4 + 128 * 4;
        cudaFuncSetAttribute(chol_diag_kernel, cudaFuncAttributeMaxDynamicSharedMemorySize, chol_smem);
        for (int j = 0; j < 4; j++) {
            chol_diag_kernel<<<1, 256, chol_smem, sS>>>(cov, j);
            if (j < 3) {
                int rows = (3 - j) * 128;
                chol_trsm_w<<<rows / 8, 256, 0, sS>>>(cov, j);
                float* Ct = cov + (size_t)(j + 1) * 128 * CK + (j + 1) * 128;
                const float* P = cov + (size_t)(j + 1) * 128 * CK + j * 128;
                tgemm(sS, false, true, true, P, P, Ct, nullptr, rows, rows, 128, CK, CK, CK, 0, 0, 0, 1, -1.f, 1.f, 0);
            }
        }
    }
    transpose_diag_kernel<<<dim3(64, 4), 256, 0, sS>>>(cov, LT);
    copy_kernel<<<(CK * CD + 255) / 256, 256, 0, sS>>>(S, Mm, CK * CD);
    for (int j = 0; j < 4; j++) {
        if (j > 0)
            tgemm(sS, false, false, true, cov + (size_t)j * 128 * CK, Mm, Mm + (size_t)j * 128 * CD, nullptr,
                  128, CD, j * 128, CK, CD, CD, 0, 0, 0, 1, -1.f, 1.f, 0);
        trisolve_fwd_w<<<CD / 8, 256, 0, sS>>>(cov, Mm, j);
    }
    for (int j = 3; j >= 0; j--) {
        if (j < 3) {
            int s = (3 - j) * 128;
            tgemm(sS, true, false, true, cov + (size_t)(j + 1) * 128 * CK + j * 128, Mm + (size_t)(j + 1) * 128 * CD,
                  Mm + (size_t)j * 128 * CD, nullptr, 128, CD, s, CK, CD, CD, 0, 0, 0, 1, -1.f, 1.f, 0);
        }
        trisolve_bwd_w<<<CD / 8, 256, 0, sS>>>(LT, Mm, j);
    }
    cudaEventRecord(eMm, sS);

    // ---- stream sV: V projection + novelty chain ----------------------------
    tgemm(sV, false, true, false, x, Wv_w, V, Wv_b, CBT, CD, CD, CD, CD, CD, 0, 0, 0, 1, 1.f, 0.f, 0);
    cudaEventRecord(eV, sV);
    vnorm_kernel<<<CBT / 8, dim3(32, 8), 0, sV>>>(V, vn);
    cudaStreamWaitEvent(sV, eSn, 0);
    tgemm(sV, false, true, false, V, Sn, sim, nullptr, CBT, CK, CD, CD, CD, CK, 0, 0, 0, 1, 1.f, 0.f, 0);
    novelty_kernel<<<CBT / 8, dim3(32, 8), 0, sV>>>(sim, vn, nov);
    cudaEventRecord(eNov, sV);

    // ---- main stream: Q chain, attention, write path ------------------------
    wt_kernel<<<CT / 256, 256, 0, M0>>>(wt);
    tgemm(M0, false, true, true, x, Wq_w, Q, Wq_b, CBT, CD, CD, CD, CD, CD, 0, 0, 0, 1, 1.f, 0.f, 0);
    instr_kernel<<<CBT / 8, dim3(32, 8), 0, M0>>>(Q, Wm_w, Wm_b, instr);
    tgemm(M0, false, true, true, Q, S, logits, nullptr, CBT, CK, CD, CD, CD, CK, 0, 0, 0, 1, inv_sqrt_d, 0.f, 0);
    topk_ctx_kernel<<<CBT / 8, dim3(32, 8), 0, M0>>>(logits, S, ctx);
    tgemm(M0, false, true, false, Q, Q, scores, nullptr, CT, CT, CD, CD, CD, CT,
          (long long)CT * CD, (long long)CT * CD, (long long)CT * CT, CB, inv_sqrt_d, 0.f, 1);
    softmax_causal_kernel<<<dim3(CT, CB), 256, 0, M0>>>(scores);
    tgemm(M0, false, true, false, Q, Wn_w + 1, rw, nullptr, CBT, CK, CD, CD, CD + 1, CK, 0, 0, 0, 1, 1.f, 0.f, 0);
    cudaStreamWaitEvent(M0, eV, 0);
    tgemm(M0, false, false, false, scores, V, byp, nullptr, CT, CD, CT, CT, CD, CD,
          (long long)CT * CT, (long long)CT * CD, (long long)CT * CD, CB, 1.f, 0.f, 2);
    combine_kernel<<<(CBT * CD + 255) / 256, 256, 0, M0>>>(ctx, byp, instr, out);
    cudaStreamWaitEvent(M0, eNov, 0);
    rw_epi_kernel<<<(CBT * CK + 255) / 256, 256, 0, M0>>>(rw, nov, Wn_w, Wn_b, wt);
    tgemm(M0, true, false, false, rw, V, Vagg, nullptr, CK, CD, CT, CK, CD, CD,
          (long long)CT * CK, (long long)CT * CD, (long long)CK * CD, CB, 1.f, 0.f, 0);
    tgemm(M0, false, true, true, Vagg, S, T1, nullptr, CK, CK, CD, CD, CD, CK,
          (long long)CK * CD, 0, (long long)CK * CK, CB, 1.f, 0.f, 0);
    init_out2_kernel<<<(CB * CK * CD + 255) / 256, 256, 0, M0>>>(S, Vagg, out2);
    cudaStreamWaitEvent(M0, eMm, 0);
    tgemm(M0, false, false, true, T1, Mm, out2, nullptr, CK, CD, CK, CK, CD, CD,
          (long long)CK * CK, 0, (long long)CK * CD, CB, -0.1f, 1.f, 0);
}

// round 6
// speedup vs baseline: 3.0312x; 1.0686x over previous
#include <cuda_runtime.h>
#include <math.h>
#include <stdint.h>

#define CB 4
#define CT 2048
#define CD 1024
#define CK 512
#define CKR 16
#define CBT 8192   // CB*CT

// ---------------- scratch (static device globals; no allocs) ----------------
__device__ float g_Q[CBT*CD];
__device__ float g_V[CBT*CD];
__device__ float g_logits[CBT*CK];
__device__ float g_sim[CBT*CK];
__device__ float g_ctx[CBT*CD];
__device__ float g_scores[(size_t)CB*CT*CT];
__device__ float g_byp[CBT*CD];
__device__ float g_instr[CBT];
__device__ float g_nov[CBT];
__device__ float g_vnorm[CBT];
__device__ float g_rw[CBT*CK];
__device__ float g_Sn[CK*CD];
__device__ float g_Vagg[CB*CK*CD];
__device__ float g_T1[CB*CK*CK];
__device__ float g_cov[CK*CK];
__device__ float g_Mm[CK*CD];
__device__ float g_wt[CT];
__device__ float g_LT[4*128*128];       // transposed diagonal L blocks

// ---------------- tf32 helpers ----------------------------------------------
__device__ __forceinline__ uint32_t f2tf32(float x) {
    uint32_t r;
    asm("cvt.rna.tf32.f32 %0, %1;" : "=r"(r) : "f"(x));
    return r;
}

__device__ __forceinline__ void mma_tf32(float* c, const uint32_t* a, const uint32_t* b) {
    asm volatile(
        "mma.sync.aligned.m16n8k8.row.col.f32.tf32.tf32.f32 "
        "{%0,%1,%2,%3}, {%4,%5,%6,%7}, {%8,%9}, {%0,%1,%2,%3};"
        : "+f"(c[0]), "+f"(c[1]), "+f"(c[2]), "+f"(c[3])
        : "r"(a[0]), "r"(a[1]), "r"(a[2]), "r"(a[3]), "r"(b[0]), "r"(b[1]));
}

// ---------------- tensor-core GEMM: C = beta*C + alpha*op(A)op(B) (+bias) ---
template<bool TA, bool TB, bool PREC>
__global__ void __launch_bounds__(256) tgemm_kernel(
    const float* __restrict__ A, const float* __restrict__ B,
    float* __restrict__ C, const float* __restrict__ bias,
    int M, int N, int Kd, int lda, int ldb, int ldc,
    long long sA, long long sB, long long sC,
    float alpha, float beta, int causal)
{
    constexpr int PK = PREC ? 4 : 2;      // floats per pack
    const int bm = blockIdx.y * 128;
    const int bn = blockIdx.x * 128;
    if (causal == 1 && bn > bm + 127) return;
    A += sA * blockIdx.z;
    B += sB * blockIdx.z;
    C += sC * blockIdx.z;
    const int kend = (causal == 2) ? min(Kd, bm + 128) : Kd;

    extern __shared__ float sm[];
    float* Ap = sm;                        // [2 st][2 ks][128 m][4 tig][PK]
    float* Bp = sm + 2 * 2 * 128 * 4 * PK;

    const int tid = threadIdx.x;
    const int lane = tid & 31;
    const int wid = tid >> 5;
    const int warp_m = wid >> 2;
    const int warp_n = wid & 3;
    const int gid = lane >> 2;
    const int tig = lane & 3;
    const int mbase = warp_m * 64;
    const int nbase = warp_n * 32;

    float acc[4][4][4];
#pragma unroll
    for (int i = 0; i < 4; i++)
#pragma unroll
        for (int j = 0; j < 4; j++)
#pragma unroll
            for (int r = 0; r < 4; r++) acc[i][j][r] = 0.f;

    const float *pA[4], *pB[4];
    const int offA = (!TA) ? 4 : 4 * lda;
    const int offB = (!TB) ? 4 * ldb : 4;
    const long long stepA = (!TA) ? 16 : (long long)16 * lda;
    const long long stepB = (!TB) ? (long long)16 * ldb : 16;
#pragma unroll
    for (int i = 0; i < 4; i++) {
        int e = tid + 256 * i;
        int tg = e & 3, ks = (e >> 2) & 1, m = e >> 3;
        int k = ks * 8 + tg;
        pA[i] = (!TA) ? (A + (size_t)(bm + m) * lda + k) : (A + (size_t)k * lda + bm + m);
        pB[i] = (!TB) ? (B + (size_t)k * ldb + bn + m) : (B + (size_t)(bn + m) * ldb + k);
    }

    float ra[4][2], rb[4][2];

    auto gload = [&]() {
#pragma unroll
        for (int i = 0; i < 4; i++) {
            ra[i][0] = pA[i][0]; ra[i][1] = pA[i][offA]; pA[i] += stepA;
            rb[i][0] = pB[i][0]; rb[i][1] = pB[i][offB]; pB[i] += stepB;
        }
    };

    auto sstore = [&](int st) {
#pragma unroll
        for (int i = 0; i < 4; i++) {
            int e = tid + 256 * i;
            int tg = e & 3, ks = (e >> 2) & 1, m = e >> 3;
            int idx = (((st * 2 + ks) * 128 + m) * 4 + tg) * PK;
            uint32_t ah0 = f2tf32(ra[i][0]), ah1 = f2tf32(ra[i][1]);
            uint32_t bh0 = f2tf32(rb[i][0]), bh1 = f2tf32(rb[i][1]);
            if constexpr (PREC) {
                float4 va, vb;
                va.x = __uint_as_float(ah0); va.y = __uint_as_float(ah1);
                va.z = __uint_as_float(f2tf32(ra[i][0] - __uint_as_float(ah0)));
                va.w = __uint_as_float(f2tf32(ra[i][1] - __uint_as_float(ah1)));
                vb.x = __uint_as_float(bh0); vb.y = __uint_as_float(bh1);
                vb.z = __uint_as_float(f2tf32(rb[i][0] - __uint_as_float(bh0)));
                vb.w = __uint_as_float(f2tf32(rb[i][1] - __uint_as_float(bh1)));
                *reinterpret_cast<float4*>(Ap + idx) = va;
                *reinterpret_cast<float4*>(Bp + idx) = vb;
            } else {
                float2 va, vb;
                va.x = __uint_as_float(ah0); va.y = __uint_as_float(ah1);
                vb.x = __uint_as_float(bh0); vb.y = __uint_as_float(bh1);
                *reinterpret_cast<float2*>(Ap + idx) = va;
                *reinterpret_cast<float2*>(Bp + idx) = vb;
            }
        }
    };

    auto compute_stage = [&](int st) {
#pragma unroll
        for (int ks = 0; ks < 2; ks++) {
            uint32_t af[4][4], bf[4][2];
            uint32_t afl[4][4], bfl[4][2];
            const int base = (st * 2 + ks) * 128;
#pragma unroll
            for (int mi = 0; mi < 4; mi++) {
                int m0 = mbase + mi * 16 + gid;
                if constexpr (PREC) {
                    float4 v0 = reinterpret_cast<const float4*>(Ap)[(base + m0) * 4 + tig];
                    float4 v1 = reinterpret_cast<const float4*>(Ap)[(base + m0 + 8) * 4 + tig];
                    af[mi][0] = __float_as_uint(v0.x); af[mi][2] = __float_as_uint(v0.y);
                    afl[mi][0] = __float_as_uint(v0.z); afl[mi][2] = __float_as_uint(v0.w);
                    af[mi][1] = __float_as_uint(v1.x); af[mi][3] = __float_as_uint(v1.y);
                    afl[mi][1] = __float_as_uint(v1.z); afl[mi][3] = __float_as_uint(v1.w);
                } else {
                    float2 v0 = reinterpret_cast<const float2*>(Ap)[(base + m0) * 4 + tig];
                    float2 v1 = reinterpret_cast<const float2*>(Ap)[(base + m0 + 8) * 4 + tig];
                    af[mi][0] = __float_as_uint(v0.x); af[mi][2] = __float_as_uint(v0.y);
                    af[mi][1] = __float_as_uint(v1.x); af[mi][3] = __float_as_uint(v1.y);
                }
            }
#pragma unroll
            for (int ni = 0; ni < 4; ni++) {
                int n0 = nbase + ni * 8 + gid;
                if constexpr (PREC) {
                    float4 v = reinterpret_cast<const float4*>(Bp)[(base + n0) * 4 + tig];
                    bf[ni][0] = __float_as_uint(v.x); bf[ni][1] = __float_as_uint(v.y);
                    bfl[ni][0] = __float_as_uint(v.z); bfl[ni][1] = __float_as_uint(v.w);
                } else {
                    float2 v = reinterpret_cast<const float2*>(Bp)[(base + n0) * 4 + tig];
                    bf[ni][0] = __float_as_uint(v.x); bf[ni][1] = __float_as_uint(v.y);
                }
            }
#pragma unroll
            for (int mi = 0; mi < 4; mi++)
#pragma unroll
                for (int ni = 0; ni < 4; ni++) {
                    mma_tf32(acc[mi][ni], af[mi], bf[ni]);
                    if constexpr (PREC) {
                        mma_tf32(acc[mi][ni], af[mi], bfl[ni]);
                        mma_tf32(acc[mi][ni], afl[mi], bf[ni]);
                    }
                }
        }
    };

    const int niter = kend / 16;
    gload();
    int st = 0;
    for (int it = 0; it < niter; it++) {
        sstore(st);
        __syncthreads();
        if (it + 1 < niter) gload();
        compute_stage(st);
        __syncthreads();
        st ^= 1;
    }

#pragma unroll
    for (int mi = 0; mi < 4; mi++) {
        int row0 = bm + mbase + mi * 16 + gid;
        int row1 = row0 + 8;
#pragma unroll
        for (int ni = 0; ni < 4; ni++) {
            int col = bn + nbase + ni * 8 + 2 * tig;
            float v0 = alpha * acc[mi][ni][0];
            float v1 = alpha * acc[mi][ni][1];
            float v2 = alpha * acc[mi][ni][2];
            float v3 = alpha * acc[mi][ni][3];
            if (beta != 0.f) {
                v0 += beta * C[(size_t)row0 * ldc + col];
                v1 += beta * C[(size_t)row0 * ldc + col + 1];
                v2 += beta * C[(size_t)row1 * ldc + col];
                v3 += beta * C[(size_t)row1 * ldc + col + 1];
            }
            if (bias) {
                v0 += bias[col]; v1 += bias[col + 1];
                v2 += bias[col]; v3 += bias[col + 1];
            }
            C[(size_t)row0 * ldc + col]     = v0;
            C[(size_t)row0 * ldc + col + 1] = v1;
            C[(size_t)row1 * ldc + col]     = v2;
            C[(size_t)row1 * ldc + col + 1] = v3;
        }
    }
}

// ---------------- top-16 read + softmax + context (warp per row) ------------
__global__ void topk_ctx_kernel(const float* __restrict__ logits,
                                const float* __restrict__ S,
                                float* __restrict__ ctx)
{
    int m = blockIdx.x * 8 + threadIdx.y;
    int lane = threadIdx.x;
    const float* lrow = logits + (size_t)m * CK;
    float v[16];
#pragma unroll
    for (int i = 0; i < 16; i++) v[i] = lrow[i * 32 + lane];
    float topv[CKR]; int topi[CKR];
    for (int it = 0; it < CKR; it++) {
        float bv = -INFINITY; int bi = 0x7fffffff;
#pragma unroll
        for (int i = 0; i < 16; i++) {
            if (v[i] > bv) { bv = v[i]; bi = i * 32 + lane; }
        }
#pragma unroll
        for (int off = 16; off > 0; off >>= 1) {
            float ov = __shfl_xor_sync(0xffffffffu, bv, off);
            int   oi = __shfl_xor_sync(0xffffffffu, bi, off);
            if (ov > bv || (ov == bv && oi < bi)) { bv = ov; bi = oi; }
        }
        topv[it] = bv; topi[it] = bi;
        if ((bi & 31) == lane) v[bi >> 5] = -INFINITY;
    }
    float p[CKR]; float s = 0.f;
#pragma unroll
    for (int i = 0; i < CKR; i++) { p[i] = expf(topv[i] - topv[0]); s += p[i]; }
    float inv = 1.f / s;
    float* crow = ctx + (size_t)m * CD;
    for (int d = lane; d < CD; d += 32) {
        float acc = 0.f;
#pragma unroll
        for (int i = 0; i < CKR; i++)
            acc += p[i] * S[(size_t)topi[i] * CD + d];
        crow[d] = acc * inv;
    }
}

// ---------------- instruction gate ------------------------------------------
__global__ void instr_kernel(const float* __restrict__ Q,
                             const float* __restrict__ Wm,
                             const float* __restrict__ bm_,
                             float* __restrict__ instr)
{
    int m = blockIdx.x * 8 + threadIdx.y;
    int lane = threadIdx.x;
    const float* q = Q + (size_t)m * CD;
    float s = 0.f;
    for (int d = lane; d < CD; d += 32) s = fmaf(q[d], Wm[d], s);
#pragma unroll
    for (int off = 16; off > 0; off >>= 1) s += __shfl_xor_sync(0xffffffffu, s, off);
    if (lane == 0) instr[m] = 1.f / (1.f + expf(-(s + bm_[0])));
}

// ---------------- causal row softmax in place -------------------------------
__global__ void softmax_causal_kernel(float* __restrict__ P)
{
    int b = blockIdx.y, q = blockIdx.x;
    float* row = P + ((size_t)b * CT + q) * CT;
    int n = q + 1;
    int kmax = ((q >> 7) + 1) << 7;
    int tid = threadIdx.x;
    __shared__ float red[256];
    float mx = -INFINITY;
    for (int k = tid; k < n; k += 256) mx = fmaxf(mx, row[k]);
    red[tid] = mx; __syncthreads();
    for (int s = 128; s > 0; s >>= 1) { if (tid < s) red[tid] = fmaxf(red[tid], red[tid + s]); __syncthreads(); }
    mx = red[0]; __syncthreads();
    float sum = 0.f;
    for (int k = tid; k < n; k += 256) { float e = expf(row[k] - mx); row[k] = e; sum += e; }
    red[tid] = sum; __syncthreads();
    for (int s = 128; s > 0; s >>= 1) { if (tid < s) red[tid] += red[tid + s]; __syncthreads(); }
    float inv = 1.f / red[0];
    for (int k = tid; k < n; k += 256) row[k] *= inv;
    for (int k = n + tid; k < kmax; k += 256) row[k] = 0.f;
}

// ---------------- elementwise combine ---------------------------------------
__global__ void combine_kernel(const float* __restrict__ ctx, const float* __restrict__ byp,
                               const float* __restrict__ instr, float* __restrict__ out)
{
    size_t i = (size_t)blockIdx.x * blockDim.x + threadIdx.x;
    if (i >= (size_t)CBT * CD) return;
    float p = instr[i / CD];
    out[i] = (1.f - p) * ctx[i] + p * byp[i];
}

// ---------------- row-normalize S -> Sn -------------------------------------
__global__ void sn_kernel(const float* __restrict__ S, float* __restrict__ Sn)
{
    int r = blockIdx.x * 8 + threadIdx.y;
    int lane = threadIdx.x;
    const float* row = S + (size_t)r * CD;
    float s = 0.f;
    for (int d = lane; d < CD; d += 32) { float v = row[d]; s = fmaf(v, v, s); }
#pragma unroll
    for (int off = 16; off > 0; off >>= 1) s += __shfl_xor_sync(0xffffffffu, s, off);
    float inv = 1.f / fmaxf(sqrtf(s), 1e-8f);
    for (int d = lane; d < CD; d += 32) Sn[(size_t)r * CD + d] = row[d] * inv;
}

// ---------------- V row norms ------------------------------------------------
__global__ void vnorm_kernel(const float* __restrict__ V, float* __restrict__ vn)
{
    int m = blockIdx.x * 8 + threadIdx.y;
    int lane = threadIdx.x;
    const float* row = V + (size_t)m * CD;
    float s = 0.f;
    for (int d = lane; d < CD; d += 32) { float v = row[d]; s = fmaf(v, v, s); }
#pragma unroll
    for (int off = 16; off > 0; off >>= 1) s += __shfl_xor_sync(0xffffffffu, s, off);
    if (lane == 0) vn[m] = sqrtf(s);
}

// ---------------- novelty ----------------------------------------------------
__global__ void novelty_kernel(const float* __restrict__ sim, const float* __restrict__ vn,
                               float* __restrict__ nov)
{
    int m = blockIdx.x * 8 + threadIdx.y;
    int lane = threadIdx.x;
    const float* row = sim + (size_t)m * CK;
    float mx = -INFINITY;
    for (int k = lane; k < CK; k += 32) mx = fmaxf(mx, row[k]);
#pragma unroll
    for (int off = 16; off > 0; off >>= 1) mx = fmaxf(mx, __shfl_xor_sync(0xffffffffu, mx, off));
    if (lane == 0) nov[m] = 1.f - mx / fmaxf(vn[m], 1e-8f);
}

// ---------------- decay weights ---------------------------------------------
__global__ void wt_kernel(float* __restrict__ wt)
{
    int t = blockIdx.x * 256 + threadIdx.x;
    if (t >= CT) return;
    float denom = 1.f - powf(0.99f, (float)CT);
    wt[t] = powf(0.99f, (float)(CT - 1 - t)) * (0.01f / denom);
}

// ---------------- r_write epilogue ------------------------------------------
__global__ void rw_epi_kernel(float* __restrict__ rw, const float* __restrict__ nov,
                              const float* __restrict__ Wn, const float* __restrict__ bn,
                              const float* __restrict__ wt)
{
    size_t i = (size_t)blockIdx.x * blockDim.x + threadIdx.x;
    if (i >= (size_t)CBT * CK) return;
    int m = (int)(i / CK), k = (int)(i % CK);
    float x = rw[i] + nov[m] * Wn[(size_t)k * (CD + 1)] + bn[k];
    rw[i] = (1.f / (1.f + expf(-x))) * wt[m % CT];
}

// ---------------- add eps*I to S_cov ----------------------------------------
__global__ void diag_eps_kernel(float* __restrict__ cov)
{
    int k = blockIdx.x * 256 + threadIdx.x;
    if (k < CK) cov[(size_t)k * CK + k] += 1e-5f;
}

// ---------------- Cholesky diag 128x128: blocked-32 smem-resident ------------
__global__ void chol_diag_kernel(float* __restrict__ Am, int j)
{
    extern __shared__ float As[];           // 128*128
    float* A = Am + (size_t)(j * 128) * CK + j * 128;   // ld = CK
    const int tid = threadIdx.x;
    const int lane = tid & 31;
    const int wid = tid >> 5;
    for (int i = tid; i < 128 * 128; i += 256)
        As[i] = A[(size_t)(i >> 7) * CK + (i & 127)];
    __syncthreads();

#pragma unroll
    for (int jb = 0; jb < 4; jb++) {
        const int base = jb * 32;
        // --- 1. warp 0: factor 32x32 diagonal block via shfl (no barriers) ---
        if (wid == 0) {
            float a[32];
#pragma unroll
            for (int c = 0; c < 32; c++) a[c] = As[(base + lane) * 128 + base + c];
#pragma unroll
            for (int p = 0; p < 32; p++) {
                float d = sqrtf(__shfl_sync(0xffffffffu, a[p], p));
                if (lane > p) a[p] /= d;
                else if (lane == p) a[p] = d;
                float lp = a[p];
#pragma unroll
                for (int c = p + 1; c < 32; c++) {
                    float lcp = __shfl_sync(0xffffffffu, lp, c);
                    if (lane >= c) a[c] -= lp * lcp;
                }
            }
#pragma unroll
            for (int c = 0; c < 32; c++) As[(base + lane) * 128 + base + c] = a[c];
        }
        __syncthreads();

        if (jb < 3) {
            // --- 2. panel TRSM: rows base+32..127, 8 warps x 4 rows ILP ---
            for (int r0 = base + 32 + wid * 4; r0 < 128; r0 += 32) {
                float f0 = As[(r0 + 0) * 128 + base + lane];
                float f1 = As[(r0 + 1) * 128 + base + lane];
                float f2 = As[(r0 + 2) * 128 + base + lane];
                float f3 = As[(r0 + 3) * 128 + base + lane];
#pragma unroll
                for (int c = 0; c < 32; c++) {
                    float Lc = As[(base + c) * 128 + base + lane];
                    float dcc = __shfl_sync(0xffffffffu, Lc, c);
                    bool m = lane < c;
                    float s0 = m ? Lc * f0 : 0.f;
                    float s1 = m ? Lc * f1 : 0.f;
                    float s2 = m ? Lc * f2 : 0.f;
                    float s3 = m ? Lc * f3 : 0.f;
#pragma unroll
                    for (int off = 16; off > 0; off >>= 1) {
                        s0 += __shfl_xor_sync(0xffffffffu, s0, off);
                        s1 += __shfl_xor_sync(0xffffffffu, s1, off);
                        s2 += __shfl_xor_sync(0xffffffffu, s2, off);
                        s3 += __shfl_xor_sync(0xffffffffu, s3, off);
                    }
                    float v0 = (__shfl_sync(0xffffffffu, f0, c) - s0) / dcc;
                    float v1 = (__shfl_sync(0xffffffffu, f1, c) - s1) / dcc;
                    float v2 = (__shfl_sync(0xffffffffu, f2, c) - s2) / dcc;
                    float v3 = (__shfl_sync(0xffffffffu, f3, c) - s3) / dcc;
                    if (lane == c) { f0 = v0; f1 = v1; f2 = v2; f3 = v3; }
                }
                As[(r0 + 0) * 128 + base + lane] = f0;
                As[(r0 + 1) * 128 + base + lane] = f1;
                As[(r0 + 2) * 128 + base + lane] = f2;
                As[(r0 + 3) * 128 + base + lane] = f3;
            }
            __syncthreads();

            // --- 3. trailing update (4x4 register tiles, compile-time w) ---
            const int w = 96 - base;          // 96 / 64 / 32 (const per unrolled jb)
            const int wt = w / 4;
            for (int t = tid; t < wt * wt; t += 256) {
                int tr = t / wt, tc = t % wt;
                int r = base + 32 + tr * 4, c = base + 32 + tc * 4;
                float acc[4][4];
#pragma unroll
                for (int ii = 0; ii < 4; ii++)
#pragma unroll
                    for (int jj = 0; jj < 4; jj++) acc[ii][jj] = 0.f;
#pragma unroll
                for (int q = 0; q < 32; q++) {
                    float lr0 = As[(r + 0) * 128 + base + q];
                    float lr1 = As[(r + 1) * 128 + base + q];
                    float lr2 = As[(r + 2) * 128 + base + q];
                    float lr3 = As[(r + 3) * 128 + base + q];
                    float lc0 = As[(c + 0) * 128 + base + q];
                    float lc1 = As[(c + 1) * 128 + base + q];
                    float lc2 = As[(c + 2) * 128 + base + q];
                    float lc3 = As[(c + 3) * 128 + base + q];
                    acc[0][0] = fmaf(lr0, lc0, acc[0][0]); acc[0][1] = fmaf(lr0, lc1, acc[0][1]);
                    acc[0][2] = fmaf(lr0, lc2, acc[0][2]); acc[0][3] = fmaf(lr0, lc3, acc[0][3]);
                    acc[1][0] = fmaf(lr1, lc0, acc[1][0]); acc[1][1] = fmaf(lr1, lc1, acc[1][1]);
                    acc[1][2] = fmaf(lr1, lc2, acc[1][2]); acc[1][3] = fmaf(lr1, lc3, acc[1][3]);
                    acc[2][0] = fmaf(lr2, lc0, acc[2][0]); acc[2][1] = fmaf(lr2, lc1, acc[2][1]);
                    acc[2][2] = fmaf(lr2, lc2, acc[2][2]); acc[2][3] = fmaf(lr2, lc3, acc[2][3]);
                    acc[3][0] = fmaf(lr3, lc0, acc[3][0]); acc[3][1] = fmaf(lr3, lc1, acc[3][1]);
                    acc[3][2] = fmaf(lr3, lc2, acc[3][2]); acc[3][3] = fmaf(lr3, lc3, acc[3][3]);
                }
#pragma unroll
                for (int ii = 0; ii < 4; ii++)
#pragma unroll
                    for (int jj = 0; jj < 4; jj++)
                        As[(r + ii) * 128 + c + jj] -= acc[ii][jj];
            }
            __syncthreads();
        }
    }

    for (int i = tid; i < 128 * 128; i += 256)
        A[(size_t)(i >> 7) * CK + (i & 127)] = As[i];
}

// ---------------- warp-per-row panel solve (smem-cached L) ------------------
__global__ void chol_trsm_w(float* __restrict__ Am, int j)
{
    extern __shared__ float Ls[];           // 128*128
    const float* L = Am + (size_t)(j * 128) * CK + j * 128;
    int tid = threadIdx.x;
    for (int i = tid; i < 128 * 128; i += 256)
        Ls[i] = L[(size_t)(i >> 7) * CK + (i & 127)];
    __syncthreads();

    int w = blockIdx.x * (blockDim.x >> 5) + (tid >> 5);
    int lane = tid & 31;
    int i = (j + 1) * 128 + w;
    float* row = Am + (size_t)i * CK + j * 128;
    float f[4];
#pragma unroll
    for (int q = 0; q < 4; q++) f[q] = row[lane + 32 * q];
    for (int c = 0; c < 128; c++) {
        const float* Lr = Ls + c * 128;
        float s = 0.f;
#pragma unroll
        for (int q = 0; q < 4; q++) {
            int qq = lane + 32 * q;
            if (qq < c) s = fmaf(Lr[qq], f[q], s);
        }
#pragma unroll
        for (int off = 16; off > 0; off >>= 1) s += __shfl_xor_sync(0xffffffffu, s, off);
        float rc = __shfl_sync(0xffffffffu, f[c >> 5], c & 31);
        float v = (rc - s) / Lr[c];
        if (lane == (c & 31)) f[c >> 5] = v;
    }
#pragma unroll
    for (int q = 0; q < 4; q++) row[lane + 32 * q] = f[q];
}

// ---------------- transpose diagonal L blocks -------------------------------
__global__ void transpose_diag_kernel(const float* __restrict__ cov, float* __restrict__ LT)
{
    int j = blockIdx.y;
    int idx = blockIdx.x * 256 + threadIdx.x;
    int p = idx >> 7, q = idx & 127;
    LT[j * 16384 + idx] = cov[(size_t)(j * 128 + q) * CK + j * 128 + p];
}

// ---------------- warp-per-column forward substitution (smem L) -------------
__global__ void trisolve_fwd_w(const float* __restrict__ Am, float* __restrict__ Zm, int j)
{
    extern __shared__ float Ls[];           // 128*128
    const float* L = Am + (size_t)(j * 128) * CK + j * 128;
    int tid = threadIdx.x;
    for (int i = tid; i < 128 * 128; i += 256)
        Ls[i] = L[(size_t)(i >> 7) * CK + (i & 127)];
    __syncthreads();

    int w = blockIdx.x * (blockDim.x >> 5) + (tid >> 5);   // column
    int lane = tid & 31;
    float* Z = Zm + (size_t)(j * 128) * CD + w;
    float f[4];
#pragma unroll
    for (int q = 0; q < 4; q++) f[q] = Z[(size_t)(lane + 32 * q) * CD];
    for (int p = 0; p < 128; p++) {
        const float* Lr = Ls + p * 128;
        float s = 0.f;
#pragma unroll
        for (int q = 0; q < 4; q++) {
            int qq = lane + 32 * q;
            if (qq < p) s = fmaf(Lr[qq], f[q], s);
        }
#pragma unroll
        for (int off = 16; off > 0; off >>= 1) s += __shfl_xor_sync(0xffffffffu, s, off);
        float zp = __shfl_sync(0xffffffffu, f[p >> 5], p & 31);
        float v = (zp - s) / Lr[p];
        if (lane == (p & 31)) f[p >> 5] = v;
    }
#pragma unroll
    for (int q = 0; q < 4; q++) Z[(size_t)(lane + 32 * q) * CD] = f[q];
}

// ---------------- warp-per-column backward substitution (smem LT) -----------
__global__ void trisolve_bwd_w(const float* __restrict__ LT, float* __restrict__ Zm, int j)
{
    extern __shared__ float Ls[];           // 128*128
    const float* Lt = LT + j * 16384;
    int tid = threadIdx.x;
    for (int i = tid; i < 128 * 128; i += 256) Ls[i] = Lt[i];
    __syncthreads();

    int w = blockIdx.x * (blockDim.x >> 5) + (tid >> 5);   // column
    int lane = tid & 31;
    float* Z = Zm + (size_t)(j * 128) * CD + w;
    float f[4];
#pragma unroll
    for (int q = 0; q < 4; q++) f[q] = Z[(size_t)(lane + 32 * q) * CD];
    for (int p = 127; p >= 0; p--) {
        const float* Lr = Ls + p * 128;
        float s = 0.f;
#pragma unroll
        for (int q = 0; q < 4; q++) {
            int qq = lane + 32 * q;
            if (qq > p) s = fmaf(Lr[qq], f[q], s);
        }
#pragma unroll
        for (int off = 16; off > 0; off >>= 1) s += __shfl_xor_sync(0xffffffffu, s, off);
        float zp = __shfl_sync(0xffffffffu, f[p >> 5], p & 31);
        float v = (zp - s) / Lr[p];
        if (lane == (p & 31)) f[p >> 5] = v;
    }
#pragma unroll
    for (int q = 0; q < 4; q++) Z[(size_t)(lane + 32 * q) * CD] = f[q];
}

// ---------------- misc small kernels ----------------------------------------
__global__ void copy_kernel(const float* __restrict__ a, float* __restrict__ b, int n)
{
    int i = blockIdx.x * 256 + threadIdx.x;
    if (i < n) b[i] = a[i];
}

__global__ void init_out2_kernel(const float* __restrict__ S, const float* __restrict__ Vagg,
                                 float* __restrict__ out2)
{
    size_t i = (size_t)blockIdx.x * blockDim.x + threadIdx.x;
    if (i >= (size_t)CB * CK * CD) return;
    size_t kd = i % ((size_t)CK * CD);
    out2[i] = 0.99f * S[kd] + 0.1f * Vagg[i];
}

// ---------------- host launcher ---------------------------------------------
static void tgemm(cudaStream_t st, bool TA, bool TB, bool prec,
                  const float* A, const float* B, float* C, const float* bias,
                  int M, int N, int Kd, int lda, int ldb, int ldc,
                  long long sA, long long sB, long long sC, int batch,
                  float alpha, float beta, int causal)
{
    dim3 grid(N / 128, M / 128, batch), block(256);
    int smem = prec ? (2 * 2 * 2 * 128 * 4 * 4 * 4) : (2 * 2 * 2 * 128 * 4 * 2 * 4);
#define DISP(ta, tb, pr) do { \
    cudaFuncSetAttribute(tgemm_kernel<ta, tb, pr>, cudaFuncAttributeMaxDynamicSharedMemorySize, smem); \
    tgemm_kernel<ta, tb, pr><<<grid, block, smem, st>>>(A, B, C, bias, M, N, Kd, lda, ldb, ldc, sA, sB, sC, alpha, beta, causal); \
} while (0)
    if (!prec) {
        if (!TA && !TB) DISP(false, false, false);
        else if (!TA && TB) DISP(false, true, false);
        else if (TA && !TB) DISP(true, false, false);
        else DISP(true, true, false);
    } else {
        if (!TA && !TB) DISP(false, false, true);
        else if (!TA && TB) DISP(false, true, true);
        else if (TA && !TB) DISP(true, false, true);
        else DISP(true, true, true);
    }
#undef DISP
}

extern "C" void kernel_launch(void* const* d_in, const int* in_sizes, int n_in,
                              void* d_out, int out_size)
{
    const float* x    = (const float*)d_in[0];
    const float* S    = (const float*)d_in[1];
    const float* Wq_w = (const float*)d_in[2];
    const float* Wq_b = (const float*)d_in[3];
    const float* Wv_w = (const float*)d_in[4];
    const float* Wv_b = (const float*)d_in[5];
    const float* Wn_w = (const float*)d_in[6];
    const float* Wn_b = (const float*)d_in[7];
    const float* Wm_w = (const float*)d_in[8];
    const float* Wm_b = (const float*)d_in[9];
    float* out  = (float*)d_out;                 // [B,T,D]
    float* out2 = out + (size_t)CBT * CD;        // [B,K,D] = S_next

    float *Q, *V, *logits, *sim, *ctx, *scores, *byp, *instr, *nov, *vn, *rw, *Sn, *Vagg, *T1, *cov, *Mm, *wt, *LT;
    cudaGetSymbolAddress((void**)&Q,      g_Q);
    cudaGetSymbolAddress((void**)&V,      g_V);
    cudaGetSymbolAddress((void**)&logits, g_logits);
    cudaGetSymbolAddress((void**)&sim,    g_sim);
    cudaGetSymbolAddress((void**)&ctx,    g_ctx);
    cudaGetSymbolAddress((void**)&scores, g_scores);
    cudaGetSymbolAddress((void**)&byp,    g_byp);
    cudaGetSymbolAddress((void**)&instr,  g_instr);
    cudaGetSymbolAddress((void**)&nov,    g_nov);
    cudaGetSymbolAddress((void**)&vn,     g_vnorm);
    cudaGetSymbolAddress((void**)&rw,     g_rw);
    cudaGetSymbolAddress((void**)&Sn,     g_Sn);
    cudaGetSymbolAddress((void**)&Vagg,   g_Vagg);
    cudaGetSymbolAddress((void**)&T1,     g_T1);
    cudaGetSymbolAddress((void**)&cov,    g_cov);
    cudaGetSymbolAddress((void**)&Mm,     g_Mm);
    cudaGetSymbolAddress((void**)&wt,     g_wt);
    cudaGetSymbolAddress((void**)&LT,     g_LT);

    static cudaStream_t sV = nullptr, sS = nullptr;
    static cudaEvent_t eFork = nullptr, eV = nullptr, eSn = nullptr, eNov = nullptr, eMm = nullptr;
    if (!sV) {
        cudaStreamCreateWithFlags(&sV, cudaStreamNonBlocking);
        cudaStreamCreateWithFlags(&sS, cudaStreamNonBlocking);
        cudaEventCreateWithFlags(&eFork, cudaEventDisableTiming);
        cudaEventCreateWithFlags(&eV,    cudaEventDisableTiming);
        cudaEventCreateWithFlags(&eSn,   cudaEventDisableTiming);
        cudaEventCreateWithFlags(&eNov,  cudaEventDisableTiming);
        cudaEventCreateWithFlags(&eMm,   cudaEventDisableTiming);
    }

    const float inv_sqrt_d = 0.03125f;   // 1/sqrt(1024)
    const cudaStream_t M0 = 0;
    const int SOLVE_SMEM = 128 * 128 * 4;
    cudaFuncSetAttribute(chol_diag_kernel,  cudaFuncAttributeMaxDynamicSharedMemorySize, SOLVE_SMEM);
    cudaFuncSetAttribute(chol_trsm_w,       cudaFuncAttributeMaxDynamicSharedMemorySize, SOLVE_SMEM);
    cudaFuncSetAttribute(trisolve_fwd_w,    cudaFuncAttributeMaxDynamicSharedMemorySize, SOLVE_SMEM);
    cudaFuncSetAttribute(trisolve_bwd_w,    cudaFuncAttributeMaxDynamicSharedMemorySize, SOLVE_SMEM);

    // ================= fork =================
    cudaEventRecord(eFork, M0);
    cudaStreamWaitEvent(sV, eFork, 0);
    cudaStreamWaitEvent(sS, eFork, 0);

    // ---- stream sS: S-only chain (Sn, cov, chol, Mm) ------------------------
    sn_kernel<<<CK / 8, dim3(32, 8), 0, sS>>>(S, Sn);
    cudaEventRecord(eSn, sS);
    tgemm(sS, false, true, true, S, S, cov, nullptr, CK, CK, CD, CD, CD, CK, 0, 0, 0, 1, 1.f, 0.f, 0);
    diag_eps_kernel<<<2, 256, 0, sS>>>(cov);
    for (int j = 0; j < 4; j++) {
        chol_diag_kernel<<<1, 256, SOLVE_SMEM, sS>>>(cov, j);
        if (j < 3) {
            int rows = (3 - j) * 128;
            chol_trsm_w<<<rows / 8, 256, SOLVE_SMEM, sS>>>(cov, j);
            float* Ct = cov + (size_t)(j + 1) * 128 * CK + (j + 1) * 128;
            const float* P = cov + (size_t)(j + 1) * 128 * CK + j * 128;
            tgemm(sS, false, true, true, P, P, Ct, nullptr, rows, rows, 128, CK, CK, CK, 0, 0, 0, 1, -1.f, 1.f, 0);
        }
    }
    transpose_diag_kernel<<<dim3(64, 4), 256, 0, sS>>>(cov, LT);
    copy_kernel<<<(CK * CD + 255) / 256, 256, 0, sS>>>(S, Mm, CK * CD);
    for (int j = 0; j < 4; j++) {
        if (j > 0)
            tgemm(sS, false, false, true, cov + (size_t)j * 128 * CK, Mm, Mm + (size_t)j * 128 * CD, nullptr,
                  128, CD, j * 128, CK, CD, CD, 0, 0, 0, 1, -1.f, 1.f, 0);
        trisolve_fwd_w<<<CD / 8, 256, SOLVE_SMEM, sS>>>(cov, Mm, j);
    }
    for (int j = 3; j >= 0; j--) {
        if (j < 3) {
            int s = (3 - j) * 128;
            tgemm(sS, true, false, true, cov + (size_t)(j + 1) * 128 * CK + j * 128, Mm + (size_t)(j + 1) * 128 * CD,
                  Mm + (size_t)j * 128 * CD, nullptr, 128, CD, s, CK, CD, CD, 0, 0, 0, 1, -1.f, 1.f, 0);
        }
        trisolve_bwd_w<<<CD / 8, 256, SOLVE_SMEM, sS>>>(LT, Mm, j);
    }
    cudaEventRecord(eMm, sS);

    // ---- stream sV: V projection + novelty chain ----------------------------
    tgemm(sV, false, true, false, x, Wv_w, V, Wv_b, CBT, CD, CD, CD, CD, CD, 0, 0, 0, 1, 1.f, 0.f, 0);
    cudaEventRecord(eV, sV);
    vnorm_kernel<<<CBT / 8, dim3(32, 8), 0, sV>>>(V, vn);
    cudaStreamWaitEvent(sV, eSn, 0);
    tgemm(sV, false, true, false, V, Sn, sim, nullptr, CBT, CK, CD, CD, CD, CK, 0, 0, 0, 1, 1.f, 0.f, 0);
    novelty_kernel<<<CBT / 8, dim3(32, 8), 0, sV>>>(sim, vn, nov);
    cudaEventRecord(eNov, sV);

    // ---- main stream: Q chain, attention, write path ------------------------
    wt_kernel<<<CT / 256, 256, 0, M0>>>(wt);
    tgemm(M0, false, true, true, x, Wq_w, Q, Wq_b, CBT, CD, CD, CD, CD, CD, 0, 0, 0, 1, 1.f, 0.f, 0);
    instr_kernel<<<CBT / 8, dim3(32, 8), 0, M0>>>(Q, Wm_w, Wm_b, instr);
    tgemm(M0, false, true, true, Q, S, logits, nullptr, CBT, CK, CD, CD, CD, CK, 0, 0, 0, 1, inv_sqrt_d, 0.f, 0);
    topk_ctx_kernel<<<CBT / 8, dim3(32, 8), 0, M0>>>(logits, S, ctx);
    tgemm(M0, false, true, false, Q, Q, scores, nullptr, CT, CT, CD, CD, CD, CT,
          (long long)CT * CD, (long long)CT * CD, (long long)CT * CT, CB, inv_sqrt_d, 0.f, 1);
    softmax_causal_kernel<<<dim3(CT, CB), 256, 0, M0>>>(scores);
    tgemm(M0, false, true, false, Q, Wn_w + 1, rw, nullptr, CBT, CK, CD, CD, CD + 1, CK, 0, 0, 0, 1, 1.f, 0.f, 0);
    cudaStreamWaitEvent(M0, eV, 0);
    tgemm(M0, false, false, false, scores, V, byp, nullptr, CT, CD, CT, CT, CD, CD,
          (long long)CT * CT, (long long)CT * CD, (long long)CT * CD, CB, 1.f, 0.f, 2);
    combine_kernel<<<(CBT * CD + 255) / 256, 256, 0, M0>>>(ctx, byp, instr, out);
    cudaStreamWaitEvent(M0, eNov, 0);
    rw_epi_kernel<<<(CBT * CK + 255) / 256, 256, 0, M0>>>(rw, nov, Wn_w, Wn_b, wt);
    tgemm(M0, true, false, false, rw, V, Vagg, nullptr, CK, CD, CT, CK, CD, CD,
          (long long)CT * CK, (long long)CT * CD, (long long)CK * CD, CB, 1.f, 0.f, 0);
    tgemm(M0, false, true, true, Vagg, S, T1, nullptr, CK, CK, CD, CD, CD, CK,
          (long long)CK * CD, 0, (long long)CK * CK, CB, 1.f, 0.f, 0);
    init_out2_kernel<<<(CB * CK * CD + 255) / 256, 256, 0, M0>>>(S, Vagg, out2);
    cudaStreamWaitEvent(M0, eMm, 0);
    tgemm(M0, false, false, true, T1, Mm, out2, nullptr, CK, CD, CK, CK, CD, CD,
          (long long)CK * CK, 0, (long long)CK * CD, CB, -0.1f, 1.f, 0);
}

// round 7
// speedup vs baseline: 3.0461x; 1.0049x over previous
#include <cuda_runtime.h>
#include <math.h>
#include <stdint.h>

#define CB 4
#define CT 2048
#define CD 1024
#define CK 512
#define CKR 16
#define CBT 8192   // CB*CT

// ---------------- scratch (static device globals; no allocs) ----------------
__device__ float g_Q[CBT*CD];
__device__ float g_V[CBT*CD];
__device__ float g_logits[CBT*CK];
__device__ float g_sim[CBT*CK];
__device__ float g_ctx[CBT*CD];
__device__ float g_scores[(size_t)CB*CT*CT];
__device__ float g_byp[CBT*CD];
__device__ float g_instr[CBT];
__device__ float g_nov[CBT];
__device__ float g_vnorm[CBT];
__device__ float g_rw[CBT*CK];
__device__ float g_Sn[CK*CD];
__device__ float g_Vagg[CB*CK*CD];
__device__ float g_T1[CB*CK*CK];
__device__ float g_cov[CK*CK];
__device__ float g_Mm[CK*CD];
__device__ float g_wt[CT];
__device__ float g_LT[4*128*128];       // transposed diagonal L blocks

// ---------------- tf32 helpers ----------------------------------------------
__device__ __forceinline__ uint32_t f2tf32(float x) {
    uint32_t r;
    asm("cvt.rna.tf32.f32 %0, %1;" : "=r"(r) : "f"(x));
    return r;
}

__device__ __forceinline__ void mma_tf32(float* c, const uint32_t* a, const uint32_t* b) {
    asm volatile(
        "mma.sync.aligned.m16n8k8.row.col.f32.tf32.tf32.f32 "
        "{%0,%1,%2,%3}, {%4,%5,%6,%7}, {%8,%9}, {%0,%1,%2,%3};"
        : "+f"(c[0]), "+f"(c[1]), "+f"(c[2]), "+f"(c[3])
        : "r"(a[0]), "r"(a[1]), "r"(a[2]), "r"(a[3]), "r"(b[0]), "r"(b[1]));
}

// ---------------- tensor-core GEMM: C = beta*C + alpha*op(A)op(B) (+bias) ---
template<bool TA, bool TB, bool PREC>
__global__ void __launch_bounds__(256) tgemm_kernel(
    const float* __restrict__ A, const float* __restrict__ B,
    float* __restrict__ C, const float* __restrict__ bias,
    int M, int N, int Kd, int lda, int ldb, int ldc,
    long long sA, long long sB, long long sC,
    float alpha, float beta, int causal)
{
    constexpr int PK = PREC ? 4 : 2;      // floats per pack
    const int bm = blockIdx.y * 128;
    const int bn = blockIdx.x * 128;
    if (causal == 1 && bn > bm + 127) return;
    A += sA * blockIdx.z;
    B += sB * blockIdx.z;
    C += sC * blockIdx.z;
    const int kend = (causal == 2) ? min(Kd, bm + 128) : Kd;

    extern __shared__ float sm[];
    float* Ap = sm;                        // [2 st][2 ks][128 m][4 tig][PK]
    float* Bp = sm + 2 * 2 * 128 * 4 * PK;

    const int tid = threadIdx.x;
    const int lane = tid & 31;
    const int wid = tid >> 5;
    const int warp_m = wid >> 2;
    const int warp_n = wid & 3;
    const int gid = lane >> 2;
    const int tig = lane & 3;
    const int mbase = warp_m * 64;
    const int nbase = warp_n * 32;

    float acc[4][4][4];
#pragma unroll
    for (int i = 0; i < 4; i++)
#pragma unroll
        for (int j = 0; j < 4; j++)
#pragma unroll
            for (int r = 0; r < 4; r++) acc[i][j][r] = 0.f;

    const float *pA[4], *pB[4];
    const int offA = (!TA) ? 4 : 4 * lda;
    const int offB = (!TB) ? 4 * ldb : 4;
    const long long stepA = (!TA) ? 16 : (long long)16 * lda;
    const long long stepB = (!TB) ? (long long)16 * ldb : 16;
#pragma unroll
    for (int i = 0; i < 4; i++) {
        int e = tid + 256 * i;
        int tg = e & 3, ks = (e >> 2) & 1, m = e >> 3;
        int k = ks * 8 + tg;
        pA[i] = (!TA) ? (A + (size_t)(bm + m) * lda + k) : (A + (size_t)k * lda + bm + m);
        pB[i] = (!TB) ? (B + (size_t)k * ldb + bn + m) : (B + (size_t)(bn + m) * ldb + k);
    }

    float ra[4][2], rb[4][2];

    auto gload = [&]() {
#pragma unroll
        for (int i = 0; i < 4; i++) {
            ra[i][0] = pA[i][0]; ra[i][1] = pA[i][offA]; pA[i] += stepA;
            rb[i][0] = pB[i][0]; rb[i][1] = pB[i][offB]; pB[i] += stepB;
        }
    };

    auto sstore = [&](int st) {
#pragma unroll
        for (int i = 0; i < 4; i++) {
            int e = tid + 256 * i;
            int tg = e & 3, ks = (e >> 2) & 1, m = e >> 3;
            int idx = (((st * 2 + ks) * 128 + m) * 4 + tg) * PK;
            uint32_t ah0 = f2tf32(ra[i][0]), ah1 = f2tf32(ra[i][1]);
            uint32_t bh0 = f2tf32(rb[i][0]), bh1 = f2tf32(rb[i][1]);
            if constexpr (PREC) {
                float4 va, vb;
                va.x = __uint_as_float(ah0); va.y = __uint_as_float(ah1);
                va.z = __uint_as_float(f2tf32(ra[i][0] - __uint_as_float(ah0)));
                va.w = __uint_as_float(f2tf32(ra[i][1] - __uint_as_float(ah1)));
                vb.x = __uint_as_float(bh0); vb.y = __uint_as_float(bh1);
                vb.z = __uint_as_float(f2tf32(rb[i][0] - __uint_as_float(bh0)));
                vb.w = __uint_as_float(f2tf32(rb[i][1] - __uint_as_float(bh1)));
                *reinterpret_cast<float4*>(Ap + idx) = va;
                *reinterpret_cast<float4*>(Bp + idx) = vb;
            } else {
                float2 va, vb;
                va.x = __uint_as_float(ah0); va.y = __uint_as_float(ah1);
                vb.x = __uint_as_float(bh0); vb.y = __uint_as_float(bh1);
                *reinterpret_cast<float2*>(Ap + idx) = va;
                *reinterpret_cast<float2*>(Bp + idx) = vb;
            }
        }
    };

    auto compute_stage = [&](int st) {
#pragma unroll
        for (int ks = 0; ks < 2; ks++) {
            uint32_t af[4][4], bf[4][2];
            uint32_t afl[4][4], bfl[4][2];
            const int base = (st * 2 + ks) * 128;
#pragma unroll
            for (int mi = 0; mi < 4; mi++) {
                int m0 = mbase + mi * 16 + gid;
                if constexpr (PREC) {
                    float4 v0 = reinterpret_cast<const float4*>(Ap)[(base + m0) * 4 + tig];
                    float4 v1 = reinterpret_cast<const float4*>(Ap)[(base + m0 + 8) * 4 + tig];
                    af[mi][0] = __float_as_uint(v0.x); af[mi][2] = __float_as_uint(v0.y);
                    afl[mi][0] = __float_as_uint(v0.z); afl[mi][2] = __float_as_uint(v0.w);
                    af[mi][1] = __float_as_uint(v1.x); af[mi][3] = __float_as_uint(v1.y);
                    afl[mi][1] = __float_as_uint(v1.z); afl[mi][3] = __float_as_uint(v1.w);
                } else {
                    float2 v0 = reinterpret_cast<const float2*>(Ap)[(base + m0) * 4 + tig];
                    float2 v1 = reinterpret_cast<const float2*>(Ap)[(base + m0 + 8) * 4 + tig];
                    af[mi][0] = __float_as_uint(v0.x); af[mi][2] = __float_as_uint(v0.y);
                    af[mi][1] = __float_as_uint(v1.x); af[mi][3] = __float_as_uint(v1.y);
                }
            }
#pragma unroll
            for (int ni = 0; ni < 4; ni++) {
                int n0 = nbase + ni * 8 + gid;
                if constexpr (PREC) {
                    float4 v = reinterpret_cast<const float4*>(Bp)[(base + n0) * 4 + tig];
                    bf[ni][0] = __float_as_uint(v.x); bf[ni][1] = __float_as_uint(v.y);
                    bfl[ni][0] = __float_as_uint(v.z); bfl[ni][1] = __float_as_uint(v.w);
                } else {
                    float2 v = reinterpret_cast<const float2*>(Bp)[(base + n0) * 4 + tig];
                    bf[ni][0] = __float_as_uint(v.x); bf[ni][1] = __float_as_uint(v.y);
                }
            }
#pragma unroll
            for (int mi = 0; mi < 4; mi++)
#pragma unroll
                for (int ni = 0; ni < 4; ni++) {
                    mma_tf32(acc[mi][ni], af[mi], bf[ni]);
                    if constexpr (PREC) {
                        mma_tf32(acc[mi][ni], af[mi], bfl[ni]);
                        mma_tf32(acc[mi][ni], afl[mi], bf[ni]);
                    }
                }
        }
    };

    const int niter = kend / 16;
    gload();
    int st = 0;
    for (int it = 0; it < niter; it++) {
        sstore(st);
        __syncthreads();
        if (it + 1 < niter) gload();
        compute_stage(st);
        __syncthreads();
        st ^= 1;
    }

#pragma unroll
    for (int mi = 0; mi < 4; mi++) {
        int row0 = bm + mbase + mi * 16 + gid;
        int row1 = row0 + 8;
#pragma unroll
        for (int ni = 0; ni < 4; ni++) {
            int col = bn + nbase + ni * 8 + 2 * tig;
            float v0 = alpha * acc[mi][ni][0];
            float v1 = alpha * acc[mi][ni][1];
            float v2 = alpha * acc[mi][ni][2];
            float v3 = alpha * acc[mi][ni][3];
            if (beta != 0.f) {
                v0 += beta * C[(size_t)row0 * ldc + col];
                v1 += beta * C[(size_t)row0 * ldc + col + 1];
                v2 += beta * C[(size_t)row1 * ldc + col];
                v3 += beta * C[(size_t)row1 * ldc + col + 1];
            }
            if (bias) {
                v0 += bias[col]; v1 += bias[col + 1];
                v2 += bias[col]; v3 += bias[col + 1];
            }
            C[(size_t)row0 * ldc + col]     = v0;
            C[(size_t)row0 * ldc + col + 1] = v1;
            C[(size_t)row1 * ldc + col]     = v2;
            C[(size_t)row1 * ldc + col + 1] = v3;
        }
    }
}

// ---------------- top-16 read + softmax + context (warp per row) ------------
__global__ void topk_ctx_kernel(const float* __restrict__ logits,
                                const float* __restrict__ S,
                                float* __restrict__ ctx)
{
    int m = blockIdx.x * 8 + threadIdx.y;
    int lane = threadIdx.x;
    const float* lrow = logits + (size_t)m * CK;
    float v[16];
#pragma unroll
    for (int i = 0; i < 16; i++) v[i] = lrow[i * 32 + lane];
    float topv[CKR]; int topi[CKR];
    for (int it = 0; it < CKR; it++) {
        float bv = -INFINITY; int bi = 0x7fffffff;
#pragma unroll
        for (int i = 0; i < 16; i++) {
            if (v[i] > bv) { bv = v[i]; bi = i * 32 + lane; }
        }
#pragma unroll
        for (int off = 16; off > 0; off >>= 1) {
            float ov = __shfl_xor_sync(0xffffffffu, bv, off);
            int   oi = __shfl_xor_sync(0xffffffffu, bi, off);
            if (ov > bv || (ov == bv && oi < bi)) { bv = ov; bi = oi; }
        }
        topv[it] = bv; topi[it] = bi;
        if ((bi & 31) == lane) v[bi >> 5] = -INFINITY;
    }
    float p[CKR]; float s = 0.f;
#pragma unroll
    for (int i = 0; i < CKR; i++) { p[i] = expf(topv[i] - topv[0]); s += p[i]; }
    float inv = 1.f / s;
    float* crow = ctx + (size_t)m * CD;
    for (int d = lane; d < CD; d += 32) {
        float acc = 0.f;
#pragma unroll
        for (int i = 0; i < CKR; i++)
            acc += p[i] * S[(size_t)topi[i] * CD + d];
        crow[d] = acc * inv;
    }
}

// ---------------- instruction gate ------------------------------------------
__global__ void instr_kernel(const float* __restrict__ Q,
                             const float* __restrict__ Wm,
                             const float* __restrict__ bm_,
                             float* __restrict__ instr)
{
    int m = blockIdx.x * 8 + threadIdx.y;
    int lane = threadIdx.x;
    const float* q = Q + (size_t)m * CD;
    float s = 0.f;
    for (int d = lane; d < CD; d += 32) s = fmaf(q[d], Wm[d], s);
#pragma unroll
    for (int off = 16; off > 0; off >>= 1) s += __shfl_xor_sync(0xffffffffu, s, off);
    if (lane == 0) instr[m] = 1.f / (1.f + expf(-(s + bm_[0])));
}

// ---------------- causal row softmax in place -------------------------------
__global__ void softmax_causal_kernel(float* __restrict__ P)
{
    int b = blockIdx.y, q = blockIdx.x;
    float* row = P + ((size_t)b * CT + q) * CT;
    int n = q + 1;
    int kmax = ((q >> 7) + 1) << 7;
    int tid = threadIdx.x;
    __shared__ float red[256];
    float mx = -INFINITY;
    for (int k = tid; k < n; k += 256) mx = fmaxf(mx, row[k]);
    red[tid] = mx; __syncthreads();
    for (int s = 128; s > 0; s >>= 1) { if (tid < s) red[tid] = fmaxf(red[tid], red[tid + s]); __syncthreads(); }
    mx = red[0]; __syncthreads();
    float sum = 0.f;
    for (int k = tid; k < n; k += 256) { float e = expf(row[k] - mx); row[k] = e; sum += e; }
    red[tid] = sum; __syncthreads();
    for (int s = 128; s > 0; s >>= 1) { if (tid < s) red[tid] += red[tid + s]; __syncthreads(); }
    float inv = 1.f / red[0];
    for (int k = tid; k < n; k += 256) row[k] *= inv;
    for (int k = n + tid; k < kmax; k += 256) row[k] = 0.f;
}

// ---------------- elementwise combine ---------------------------------------
__global__ void combine_kernel(const float* __restrict__ ctx, const float* __restrict__ byp,
                               const float* __restrict__ instr, float* __restrict__ out)
{
    size_t i = (size_t)blockIdx.x * blockDim.x + threadIdx.x;
    if (i >= (size_t)CBT * CD) return;
    float p = instr[i / CD];
    out[i] = (1.f - p) * ctx[i] + p * byp[i];
}

// ---------------- row-normalize S -> Sn -------------------------------------
__global__ void sn_kernel(const float* __restrict__ S, float* __restrict__ Sn)
{
    int r = blockIdx.x * 8 + threadIdx.y;
    int lane = threadIdx.x;
    const float* row = S + (size_t)r * CD;
    float s = 0.f;
    for (int d = lane; d < CD; d += 32) { float v = row[d]; s = fmaf(v, v, s); }
#pragma unroll
    for (int off = 16; off > 0; off >>= 1) s += __shfl_xor_sync(0xffffffffu, s, off);
    float inv = 1.f / fmaxf(sqrtf(s), 1e-8f);
    for (int d = lane; d < CD; d += 32) Sn[(size_t)r * CD + d] = row[d] * inv;
}

// ---------------- V row norms ------------------------------------------------
__global__ void vnorm_kernel(const float* __restrict__ V, float* __restrict__ vn)
{
    int m = blockIdx.x * 8 + threadIdx.y;
    int lane = threadIdx.x;
    const float* row = V + (size_t)m * CD;
    float s = 0.f;
    for (int d = lane; d < CD; d += 32) { float v = row[d]; s = fmaf(v, v, s); }
#pragma unroll
    for (int off = 16; off > 0; off >>= 1) s += __shfl_xor_sync(0xffffffffu, s, off);
    if (lane == 0) vn[m] = sqrtf(s);
}

// ---------------- novelty ----------------------------------------------------
__global__ void novelty_kernel(const float* __restrict__ sim, const float* __restrict__ vn,
                               float* __restrict__ nov)
{
    int m = blockIdx.x * 8 + threadIdx.y;
    int lane = threadIdx.x;
    const float* row = sim + (size_t)m * CK;
    float mx = -INFINITY;
    for (int k = lane; k < CK; k += 32) mx = fmaxf(mx, row[k]);
#pragma unroll
    for (int off = 16; off > 0; off >>= 1) mx = fmaxf(mx, __shfl_xor_sync(0xffffffffu, mx, off));
    if (lane == 0) nov[m] = 1.f - mx / fmaxf(vn[m], 1e-8f);
}

// ---------------- decay weights ---------------------------------------------
__global__ void wt_kernel(float* __restrict__ wt)
{
    int t = blockIdx.x * 256 + threadIdx.x;
    if (t >= CT) return;
    float denom = 1.f - powf(0.99f, (float)CT);
    wt[t] = powf(0.99f, (float)(CT - 1 - t)) * (0.01f / denom);
}

// ---------------- r_write epilogue ------------------------------------------
__global__ void rw_epi_kernel(float* __restrict__ rw, const float* __restrict__ nov,
                              const float* __restrict__ Wn, const float* __restrict__ bn,
                              const float* __restrict__ wt)
{
    size_t i = (size_t)blockIdx.x * blockDim.x + threadIdx.x;
    if (i >= (size_t)CBT * CK) return;
    int m = (int)(i / CK), k = (int)(i % CK);
    float x = rw[i] + nov[m] * Wn[(size_t)k * (CD + 1)] + bn[k];
    rw[i] = (1.f / (1.f + expf(-x))) * wt[m % CT];
}

// ---------------- add eps*I to S_cov ----------------------------------------
__global__ void diag_eps_kernel(float* __restrict__ cov)
{
    int k = blockIdx.x * 256 + threadIdx.x;
    if (k < CK) cov[(size_t)k * CK + k] += 1e-5f;
}

// ---------------- Cholesky diag 128x128: blocked-32 smem-resident ------------
__global__ void chol_diag_kernel(float* __restrict__ Am, int j)
{
    extern __shared__ float As[];           // 128*128
    float* A = Am + (size_t)(j * 128) * CK + j * 128;   // ld = CK
    const int tid = threadIdx.x;
    const int lane = tid & 31;
    const int wid = tid >> 5;
    for (int i = tid; i < 128 * 128; i += 256)
        As[i] = A[(size_t)(i >> 7) * CK + (i & 127)];
    __syncthreads();

#pragma unroll
    for (int jb = 0; jb < 4; jb++) {
        const int base = jb * 32;
        // --- 1. warp 0: factor 32x32 diagonal block via shfl (no barriers) ---
        if (wid == 0) {
            float a[32];
#pragma unroll
            for (int c = 0; c < 32; c++) a[c] = As[(base + lane) * 128 + base + c];
#pragma unroll
            for (int p = 0; p < 32; p++) {
                float d = sqrtf(__shfl_sync(0xffffffffu, a[p], p));
                if (lane > p) a[p] /= d;
                else if (lane == p) a[p] = d;
                float lp = a[p];
#pragma unroll
                for (int c = p + 1; c < 32; c++) {
                    float lcp = __shfl_sync(0xffffffffu, lp, c);
                    if (lane >= c) a[c] -= lp * lcp;
                }
            }
#pragma unroll
            for (int c = 0; c < 32; c++) As[(base + lane) * 128 + base + c] = a[c];
        }
        __syncthreads();

        if (jb < 3) {
            // --- 2. panel TRSM: rows base+32..127, 8 warps x 4 rows ILP ---
            for (int r0 = base + 32 + wid * 4; r0 < 128; r0 += 32) {
                float f0 = As[(r0 + 0) * 128 + base + lane];
                float f1 = As[(r0 + 1) * 128 + base + lane];
                float f2 = As[(r0 + 2) * 128 + base + lane];
                float f3 = As[(r0 + 3) * 128 + base + lane];
#pragma unroll
                for (int c = 0; c < 32; c++) {
                    float Lc = As[(base + c) * 128 + base + lane];
                    float dcc = __shfl_sync(0xffffffffu, Lc, c);
                    bool m = lane < c;
                    float s0 = m ? Lc * f0 : 0.f;
                    float s1 = m ? Lc * f1 : 0.f;
                    float s2 = m ? Lc * f2 : 0.f;
                    float s3 = m ? Lc * f3 : 0.f;
#pragma unroll
                    for (int off = 16; off > 0; off >>= 1) {
                        s0 += __shfl_xor_sync(0xffffffffu, s0, off);
                        s1 += __shfl_xor_sync(0xffffffffu, s1, off);
                        s2 += __shfl_xor_sync(0xffffffffu, s2, off);
                        s3 += __shfl_xor_sync(0xffffffffu, s3, off);
                    }
                    float v0 = (__shfl_sync(0xffffffffu, f0, c) - s0) / dcc;
                    float v1 = (__shfl_sync(0xffffffffu, f1, c) - s1) / dcc;
                    float v2 = (__shfl_sync(0xffffffffu, f2, c) - s2) / dcc;
                    float v3 = (__shfl_sync(0xffffffffu, f3, c) - s3) / dcc;
                    if (lane == c) { f0 = v0; f1 = v1; f2 = v2; f3 = v3; }
                }
                As[(r0 + 0) * 128 + base + lane] = f0;
                As[(r0 + 1) * 128 + base + lane] = f1;
                As[(r0 + 2) * 128 + base + lane] = f2;
                As[(r0 + 3) * 128 + base + lane] = f3;
            }
            __syncthreads();

            // --- 3. trailing update (4x4 register tiles, compile-time w) ---
            const int w = 96 - base;          // 96 / 64 / 32 (const per unrolled jb)
            const int wt = w / 4;
            for (int t = tid; t < wt * wt; t += 256) {
                int tr = t / wt, tc = t % wt;
                int r = base + 32 + tr * 4, c = base + 32 + tc * 4;
                float acc[4][4];
#pragma unroll
                for (int ii = 0; ii < 4; ii++)
#pragma unroll
                    for (int jj = 0; jj < 4; jj++) acc[ii][jj] = 0.f;
#pragma unroll
                for (int q = 0; q < 32; q++) {
                    float lr0 = As[(r + 0) * 128 + base + q];
                    float lr1 = As[(r + 1) * 128 + base + q];
                    float lr2 = As[(r + 2) * 128 + base + q];
                    float lr3 = As[(r + 3) * 128 + base + q];
                    float lc0 = As[(c + 0) * 128 + base + q];
                    float lc1 = As[(c + 1) * 128 + base + q];
                    float lc2 = As[(c + 2) * 128 + base + q];
                    float lc3 = As[(c + 3) * 128 + base + q];
                    acc[0][0] = fmaf(lr0, lc0, acc[0][0]); acc[0][1] = fmaf(lr0, lc1, acc[0][1]);
                    acc[0][2] = fmaf(lr0, lc2, acc[0][2]); acc[0][3] = fmaf(lr0, lc3, acc[0][3]);
                    acc[1][0] = fmaf(lr1, lc0, acc[1][0]); acc[1][1] = fmaf(lr1, lc1, acc[1][1]);
                    acc[1][2] = fmaf(lr1, lc2, acc[1][2]); acc[1][3] = fmaf(lr1, lc3, acc[1][3]);
                    acc[2][0] = fmaf(lr2, lc0, acc[2][0]); acc[2][1] = fmaf(lr2, lc1, acc[2][1]);
                    acc[2][2] = fmaf(lr2, lc2, acc[2][2]); acc[2][3] = fmaf(lr2, lc3, acc[2][3]);
                    acc[3][0] = fmaf(lr3, lc0, acc[3][0]); acc[3][1] = fmaf(lr3, lc1, acc[3][1]);
                    acc[3][2] = fmaf(lr3, lc2, acc[3][2]); acc[3][3] = fmaf(lr3, lc3, acc[3][3]);
                }
#pragma unroll
                for (int ii = 0; ii < 4; ii++)
#pragma unroll
                    for (int jj = 0; jj < 4; jj++)
                        As[(r + ii) * 128 + c + jj] -= acc[ii][jj];
            }
            __syncthreads();
        }
    }

    for (int i = tid; i < 128 * 128; i += 256)
        A[(size_t)(i >> 7) * CK + (i & 127)] = As[i];
}

// ---------------- warp-per-row panel solve (smem-cached L) ------------------
__global__ void chol_trsm_w(float* __restrict__ Am, int j)
{
    extern __shared__ float Ls[];           // 128*128
    const float* L = Am + (size_t)(j * 128) * CK + j * 128;
    int tid = threadIdx.x;
    for (int i = tid; i < 128 * 128; i += 256)
        Ls[i] = L[(size_t)(i >> 7) * CK + (i & 127)];
    __syncthreads();

    int w = blockIdx.x * (blockDim.x >> 5) + (tid >> 5);
    int lane = tid & 31;
    int i = (j + 1) * 128 + w;
    float* row = Am + (size_t)i * CK + j * 128;
    float f[4];
#pragma unroll
    for (int q = 0; q < 4; q++) f[q] = row[lane + 32 * q];
    for (int c = 0; c < 128; c++) {
        const float* Lr = Ls + c * 128;
        float s = 0.f;
#pragma unroll
        for (int q = 0; q < 4; q++) {
            int qq = lane + 32 * q;
            if (qq < c) s = fmaf(Lr[qq], f[q], s);
        }
#pragma unroll
        for (int off = 16; off > 0; off >>= 1) s += __shfl_xor_sync(0xffffffffu, s, off);
        float rc = __shfl_sync(0xffffffffu, f[c >> 5], c & 31);
        float v = (rc - s) / Lr[c];
        if (lane == (c & 31)) f[c >> 5] = v;
    }
#pragma unroll
    for (int q = 0; q < 4; q++) row[lane + 32 * q] = f[q];
}

// ---------------- transpose diagonal L blocks -------------------------------
__global__ void transpose_diag_kernel(const float* __restrict__ cov, float* __restrict__ LT)
{
    int j = blockIdx.y;
    int idx = blockIdx.x * 256 + threadIdx.x;
    int p = idx >> 7, q = idx & 127;
    LT[j * 16384 + idx] = cov[(size_t)(j * 128 + q) * CK + j * 128 + p];
}

// ---------------- warp-per-column forward substitution (smem L) -------------
__global__ void trisolve_fwd_w(const float* __restrict__ Am, float* __restrict__ Zm, int j)
{
    extern __shared__ float Ls[];           // 128*128
    const float* L = Am + (size_t)(j * 128) * CK + j * 128;
    int tid = threadIdx.x;
    for (int i = tid; i < 128 * 128; i += 256)
        Ls[i] = L[(size_t)(i >> 7) * CK + (i & 127)];
    __syncthreads();

    int w = blockIdx.x * (blockDim.x >> 5) + (tid >> 5);   // column
    int lane = tid & 31;
    float* Z = Zm + (size_t)(j * 128) * CD + w;
    float f[4];
#pragma unroll
    for (int q = 0; q < 4; q++) f[q] = Z[(size_t)(lane + 32 * q) * CD];
    for (int p = 0; p < 128; p++) {
        const float* Lr = Ls + p * 128;
        float s = 0.f;
#pragma unroll
        for (int q = 0; q < 4; q++) {
            int qq = lane + 32 * q;
            if (qq < p) s = fmaf(Lr[qq], f[q], s);
        }
#pragma unroll
        for (int off = 16; off > 0; off >>= 1) s += __shfl_xor_sync(0xffffffffu, s, off);
        float zp = __shfl_sync(0xffffffffu, f[p >> 5], p & 31);
        float v = (zp - s) / Lr[p];
        if (lane == (p & 31)) f[p >> 5] = v;
    }
#pragma unroll
    for (int q = 0; q < 4; q++) Z[(size_t)(lane + 32 * q) * CD] = f[q];
}

// ---------------- warp-per-column backward substitution (smem LT) -----------
__global__ void trisolve_bwd_w(const float* __restrict__ LT, float* __restrict__ Zm, int j)
{
    extern __shared__ float Ls[];           // 128*128
    const float* Lt = LT + j * 16384;
    int tid = threadIdx.x;
    for (int i = tid; i < 128 * 128; i += 256) Ls[i] = Lt[i];
    __syncthreads();

    int w = blockIdx.x * (blockDim.x >> 5) + (tid >> 5);   // column
    int lane = tid & 31;
    float* Z = Zm + (size_t)(j * 128) * CD + w;
    float f[4];
#pragma unroll
    for (int q = 0; q < 4; q++) f[q] = Z[(size_t)(lane + 32 * q) * CD];
    for (int p = 127; p >= 0; p--) {
        const float* Lr = Ls + p * 128;
        float s = 0.f;
#pragma unroll
        for (int q = 0; q < 4; q++) {
            int qq = lane + 32 * q;
            if (qq > p) s = fmaf(Lr[qq], f[q], s);
        }
#pragma unroll
        for (int off = 16; off > 0; off >>= 1) s += __shfl_xor_sync(0xffffffffu, s, off);
        float zp = __shfl_sync(0xffffffffu, f[p >> 5], p & 31);
        float v = (zp - s) / Lr[p];
        if (lane == (p & 31)) f[p >> 5] = v;
    }
#pragma unroll
    for (int q = 0; q < 4; q++) Z[(size_t)(lane + 32 * q) * CD] = f[q];
}

// ---------------- misc small kernels ----------------------------------------
__global__ void copy_kernel(const float* __restrict__ a, float* __restrict__ b, int n)
{
    int i = blockIdx.x * 256 + threadIdx.x;
    if (i < n) b[i] = a[i];
}

__global__ void init_out2_kernel(const float* __restrict__ S, const float* __restrict__ Vagg,
                                 float* __restrict__ out2)
{
    size_t i = (size_t)blockIdx.x * blockDim.x + threadIdx.x;
    if (i >= (size_t)CB * CK * CD) return;
    size_t kd = i % ((size_t)CK * CD);
    out2[i] = 0.99f * S[kd] + 0.1f * Vagg[i];
}

// ---------------- host launcher ---------------------------------------------
static void tgemm(cudaStream_t st, bool TA, bool TB, bool prec,
                  const float* A, const float* B, float* C, const float* bias,
                  int M, int N, int Kd, int lda, int ldb, int ldc,
                  long long sA, long long sB, long long sC, int batch,
                  float alpha, float beta, int causal)
{
    dim3 grid(N / 128, M / 128, batch), block(256);
    int smem = prec ? (2 * 2 * 2 * 128 * 4 * 4 * 4) : (2 * 2 * 2 * 128 * 4 * 2 * 4);
#define DISP(ta, tb, pr) do { \
    cudaFuncSetAttribute(tgemm_kernel<ta, tb, pr>, cudaFuncAttributeMaxDynamicSharedMemorySize, smem); \
    tgemm_kernel<ta, tb, pr><<<grid, block, smem, st>>>(A, B, C, bias, M, N, Kd, lda, ldb, ldc, sA, sB, sC, alpha, beta, causal); \
} while (0)
    if (!prec) {
        if (!TA && !TB) DISP(false, false, false);
        else if (!TA && TB) DISP(false, true, false);
        else if (TA && !TB) DISP(true, false, false);
        else DISP(true, true, false);
    } else {
        if (!TA && !TB) DISP(false, false, true);
        else if (!TA && TB) DISP(false, true, true);
        else if (TA && !TB) DISP(true, false, true);
        else DISP(true, true, true);
    }
#undef DISP
}

extern "C" void kernel_launch(void* const* d_in, const int* in_sizes, int n_in,
                              void* d_out, int out_size)
{
    const float* x    = (const float*)d_in[0];
    const float* S    = (const float*)d_in[1];
    const float* Wq_w = (const float*)d_in[2];
    const float* Wq_b = (const float*)d_in[3];
    const float* Wv_w = (const float*)d_in[4];
    const float* Wv_b = (const float*)d_in[5];
    const float* Wn_w = (const float*)d_in[6];
    const float* Wn_b = (const float*)d_in[7];
    const float* Wm_w = (const float*)d_in[8];
    const float* Wm_b = (const float*)d_in[9];
    float* out  = (float*)d_out;                 // [B,T,D]
    float* out2 = out + (size_t)CBT * CD;        // [B,K,D] = S_next

    float *Q, *V, *logits, *sim, *ctx, *scores, *byp, *instr, *nov, *vn, *rw, *Sn, *Vagg, *T1, *cov, *Mm, *wt, *LT;
    cudaGetSymbolAddress((void**)&Q,      g_Q);
    cudaGetSymbolAddress((void**)&V,      g_V);
    cudaGetSymbolAddress((void**)&logits, g_logits);
    cudaGetSymbolAddress((void**)&sim,    g_sim);
    cudaGetSymbolAddress((void**)&ctx,    g_ctx);
    cudaGetSymbolAddress((void**)&scores, g_scores);
    cudaGetSymbolAddress((void**)&byp,    g_byp);
    cudaGetSymbolAddress((void**)&instr,  g_instr);
    cudaGetSymbolAddress((void**)&nov,    g_nov);
    cudaGetSymbolAddress((void**)&vn,     g_vnorm);
    cudaGetSymbolAddress((void**)&rw,     g_rw);
    cudaGetSymbolAddress((void**)&Sn,     g_Sn);
    cudaGetSymbolAddress((void**)&Vagg,   g_Vagg);
    cudaGetSymbolAddress((void**)&T1,     g_T1);
    cudaGetSymbolAddress((void**)&cov,    g_cov);
    cudaGetSymbolAddress((void**)&Mm,     g_Mm);
    cudaGetSymbolAddress((void**)&wt,     g_wt);
    cudaGetSymbolAddress((void**)&LT,     g_LT);

    static cudaStream_t sV = nullptr, sS = nullptr;
    static cudaEvent_t eFork = nullptr, eV = nullptr, eSn = nullptr, eNov = nullptr, eMm = nullptr;
    if (!sV) {
        cudaStreamCreateWithFlags(&sV, cudaStreamNonBlocking);
        cudaStreamCreateWithFlags(&sS, cudaStreamNonBlocking);
        cudaEventCreateWithFlags(&eFork, cudaEventDisableTiming);
        cudaEventCreateWithFlags(&eV,    cudaEventDisableTiming);
        cudaEventCreateWithFlags(&eSn,   cudaEventDisableTiming);
        cudaEventCreateWithFlags(&eNov,  cudaEventDisableTiming);
        cudaEventCreateWithFlags(&eMm,   cudaEventDisableTiming);
    }

    const float inv_sqrt_d = 0.03125f;   // 1/sqrt(1024)
    const cudaStream_t M0 = 0;
    const int SOLVE_SMEM = 128 * 128 * 4;
    cudaFuncSetAttribute(chol_diag_kernel,  cudaFuncAttributeMaxDynamicSharedMemorySize, SOLVE_SMEM);
    cudaFuncSetAttribute(chol_trsm_w,       cudaFuncAttributeMaxDynamicSharedMemorySize, SOLVE_SMEM);
    cudaFuncSetAttribute(trisolve_fwd_w,    cudaFuncAttributeMaxDynamicSharedMemorySize, SOLVE_SMEM);
    cudaFuncSetAttribute(trisolve_bwd_w,    cudaFuncAttributeMaxDynamicSharedMemorySize, SOLVE_SMEM);

    // ================= fork =================
    cudaEventRecord(eFork, M0);
    cudaStreamWaitEvent(sV, eFork, 0);
    cudaStreamWaitEvent(sS, eFork, 0);

    // ---- stream sS: S-only chain (Sn, cov, chol, Mm) ------------------------
    sn_kernel<<<CK / 8, dim3(32, 8), 0, sS>>>(S, Sn);
    cudaEventRecord(eSn, sS);
    tgemm(sS, false, true, true, S, S, cov, nullptr, CK, CK, CD, CD, CD, CK, 0, 0, 0, 1, 1.f, 0.f, 0);
    diag_eps_kernel<<<2, 256, 0, sS>>>(cov);
    for (int j = 0; j < 4; j++) {
        chol_diag_kernel<<<1, 256, SOLVE_SMEM, sS>>>(cov, j);
        if (j < 3) {
            int rows = (3 - j) * 128;
            chol_trsm_w<<<rows / 8, 256, SOLVE_SMEM, sS>>>(cov, j);
            float* Ct = cov + (size_t)(j + 1) * 128 * CK + (j + 1) * 128;
            const float* P = cov + (size_t)(j + 1) * 128 * CK + j * 128;
            tgemm(sS, false, true, true, P, P, Ct, nullptr, rows, rows, 128, CK, CK, CK, 0, 0, 0, 1, -1.f, 1.f, 0);
        }
    }
    transpose_diag_kernel<<<dim3(64, 4), 256, 0, sS>>>(cov, LT);
    copy_kernel<<<(CK * CD + 255) / 256, 256, 0, sS>>>(S, Mm, CK * CD);
    for (int j = 0; j < 4; j++) {
        if (j > 0)
            tgemm(sS, false, false, true, cov + (size_t)j * 128 * CK, Mm, Mm + (size_t)j * 128 * CD, nullptr,
                  128, CD, j * 128, CK, CD, CD, 0, 0, 0, 1, -1.f, 1.f, 0);
        trisolve_fwd_w<<<CD / 8, 256, SOLVE_SMEM, sS>>>(cov, Mm, j);
    }
    for (int j = 3; j >= 0; j--) {
        if (j < 3) {
            int s = (3 - j) * 128;
            tgemm(sS, true, false, true, cov + (size_t)(j + 1) * 128 * CK + j * 128, Mm + (size_t)(j + 1) * 128 * CD,
                  Mm + (size_t)j * 128 * CD, nullptr, 128, CD, s, CK, CD, CD, 0, 0, 0, 1, -1.f, 1.f, 0);
        }
        trisolve_bwd_w<<<CD / 8, 256, SOLVE_SMEM, sS>>>(LT, Mm, j);
    }
    cudaEventRecord(eMm, sS);

    // ---- stream sV: V projection + novelty chain ----------------------------
    tgemm(sV, false, true, false, x, Wv_w, V, Wv_b, CBT, CD, CD, CD, CD, CD, 0, 0, 0, 1, 1.f, 0.f, 0);
    cudaEventRecord(eV, sV);
    vnorm_kernel<<<CBT / 8, dim3(32, 8), 0, sV>>>(V, vn);
    cudaStreamWaitEvent(sV, eSn, 0);
    tgemm(sV, false, true, false, V, Sn, sim, nullptr, CBT, CK, CD, CD, CD, CK, 0, 0, 0, 1, 1.f, 0.f, 0);
    novelty_kernel<<<CBT / 8, dim3(32, 8), 0, sV>>>(sim, vn, nov);
    cudaEventRecord(eNov, sV);

    // ---- main stream: Q chain, attention, write path ------------------------
    wt_kernel<<<CT / 256, 256, 0, M0>>>(wt);
    tgemm(M0, false, true, true, x, Wq_w, Q, Wq_b, CBT, CD, CD, CD, CD, CD, 0, 0, 0, 1, 1.f, 0.f, 0);
    instr_kernel<<<CBT / 8, dim3(32, 8), 0, M0>>>(Q, Wm_w, Wm_b, instr);
    tgemm(M0, false, true, true, Q, S, logits, nullptr, CBT, CK, CD, CD, CD, CK, 0, 0, 0, 1, inv_sqrt_d, 0.f, 0);
    topk_ctx_kernel<<<CBT / 8, dim3(32, 8), 0, M0>>>(logits, S, ctx);
    tgemm(M0, false, true, false, Q, Q, scores, nullptr, CT, CT, CD, CD, CD, CT,
          (long long)CT * CD, (long long)CT * CD, (long long)CT * CT, CB, inv_sqrt_d, 0.f, 1);
    softmax_causal_kernel<<<dim3(CT, CB), 256, 0, M0>>>(scores);
    tgemm(M0, false, true, false, Q, Wn_w + 1, rw, nullptr, CBT, CK, CD, CD, CD + 1, CK, 0, 0, 0, 1, 1.f, 0.f, 0);
    cudaStreamWaitEvent(M0, eV, 0);
    tgemm(M0, false, false, false, scores, V, byp, nullptr, CT, CD, CT, CT, CD, CD,
          (long long)CT * CT, (long long)CT * CD, (long long)CT * CD, CB, 1.f, 0.f, 2);
    combine_kernel<<<(CBT * CD + 255) / 256, 256, 0, M0>>>(ctx, byp, instr, out);
    cudaStreamWaitEvent(M0, eNov, 0);
    rw_epi_kernel<<<(CBT * CK + 255) / 256, 256, 0, M0>>>(rw, nov, Wn_w, Wn_b, wt);
    tgemm(M0, true, false, false, rw, V, Vagg, nullptr, CK, CD, CT, CK, CD, CD,
          (long long)CT * CK, (long long)CT * CD, (long long)CK * CD, CB, 1.f, 0.f, 0);
    tgemm(M0, false, true, true, Vagg, S, T1, nullptr, CK, CK, CD, CD, CD, CK,
          (long long)CK * CD, 0, (long long)CK * CK, CB, 1.f, 0.f, 0);
    init_out2_kernel<<<(CB * CK * CD + 255) / 256, 256, 0, M0>>>(S, Vagg, out2);
    cudaStreamWaitEvent(M0, eMm, 0);
    tgemm(M0, false, false, true, T1, Mm, out2, nullptr, CK, CD, CK, CK, CD, CD,
          (long long)CK * CK, 0, (long long)CK * CD, CB, -0.1f, 1.f, 0);
}

// round 8
// speedup vs baseline: 3.0465x; 1.0001x over previous
#include <cuda_runtime.h>
#include <math.h>
#include <stdint.h>

#define CB 4
#define CT 2048
#define CD 1024
#define CK 512
#define CKR 16
#define CBT 8192   // CB*CT

// ---------------- scratch (static device globals; no allocs) ----------------
__device__ float g_Q[CBT*CD];
__device__ float g_V[CBT*CD];
__device__ float g_logits[CBT*CK];
__device__ float g_sim[CBT*CK];
__device__ float g_ctx[CBT*CD];
__device__ float g_scores[(size_t)CB*CT*CT];
__device__ float g_byp[CBT*CD];
__device__ float g_instr[CBT];
__device__ float g_nov[CBT];
__device__ float g_vnorm[CBT];
__device__ float g_rw[CBT*CK];
__device__ float g_Sn[CK*CD];
__device__ float g_Vagg[CB*CK*CD];
__device__ float g_T1[CB*CK*CK];
__device__ float g_cov[CK*CK];
__device__ float g_Mm[CK*CD];
__device__ float g_wt[CT];
__device__ float g_LT[4*128*128];       // transposed diagonal L blocks

// ---------------- tf32 helpers ----------------------------------------------
__device__ __forceinline__ uint32_t f2tf32(float x) {
    uint32_t r;
    asm("cvt.rna.tf32.f32 %0, %1;" : "=r"(r) : "f"(x));
    return r;
}

__device__ __forceinline__ void mma_tf32(float* c, const uint32_t* a, const uint32_t* b) {
    asm volatile(
        "mma.sync.aligned.m16n8k8.row.col.f32.tf32.tf32.f32 "
        "{%0,%1,%2,%3}, {%4,%5,%6,%7}, {%8,%9}, {%0,%1,%2,%3};"
        : "+f"(c[0]), "+f"(c[1]), "+f"(c[2]), "+f"(c[3])
        : "r"(a[0]), "r"(a[1]), "r"(a[2]), "r"(a[3]), "r"(b[0]), "r"(b[1]));
}

// ---------------- tensor-core GEMM: C = beta*C + alpha*op(A)op(B) (+bias) ---
template<bool TA, bool TB, bool PREC>
__global__ void __launch_bounds__(256) tgemm_kernel(
    const float* __restrict__ A, const float* __restrict__ B,
    float* __restrict__ C, const float* __restrict__ bias,
    int M, int N, int Kd, int lda, int ldb, int ldc,
    long long sA, long long sB, long long sC,
    float alpha, float beta, int causal)
{
    constexpr int PK = PREC ? 4 : 2;      // floats per pack
    const int bm = blockIdx.y * 128;
    const int bn = blockIdx.x * 128;
    if (causal == 1 && bn > bm + 127) return;
    A += sA * blockIdx.z;
    B += sB * blockIdx.z;
    C += sC * blockIdx.z;
    const int kend = (causal == 2) ? min(Kd, bm + 128) : Kd;

    extern __shared__ float sm[];
    float* Ap = sm;                        // [2 st][2 ks][128 m][4 tig][PK]
    float* Bp = sm + 2 * 2 * 128 * 4 * PK;

    const int tid = threadIdx.x;
    const int lane = tid & 31;
    const int wid = tid >> 5;
    const int warp_m = wid >> 2;
    const int warp_n = wid & 3;
    const int gid = lane >> 2;
    const int tig = lane & 3;
    const int mbase = warp_m * 64;
    const int nbase = warp_n * 32;

    float acc[4][4][4];
#pragma unroll
    for (int i = 0; i < 4; i++)
#pragma unroll
        for (int j = 0; j < 4; j++)
#pragma unroll
            for (int r = 0; r < 4; r++) acc[i][j][r] = 0.f;

    const float *pA[4], *pB[4];
    const int offA = (!TA) ? 4 : 4 * lda;
    const int offB = (!TB) ? 4 * ldb : 4;
    const long long stepA = (!TA) ? 16 : (long long)16 * lda;
    const long long stepB = (!TB) ? (long long)16 * ldb : 16;
#pragma unroll
    for (int i = 0; i < 4; i++) {
        int e = tid + 256 * i;
        int tg = e & 3, ks = (e >> 2) & 1, m = e >> 3;
        int k = ks * 8 + tg;
        pA[i] = (!TA) ? (A + (size_t)(bm + m) * lda + k) : (A + (size_t)k * lda + bm + m);
        pB[i] = (!TB) ? (B + (size_t)k * ldb + bn + m) : (B + (size_t)(bn + m) * ldb + k);
    }

    float ra[4][2], rb[4][2];

    auto gload = [&]() {
#pragma unroll
        for (int i = 0; i < 4; i++) {
            ra[i][0] = pA[i][0]; ra[i][1] = pA[i][offA]; pA[i] += stepA;
            rb[i][0] = pB[i][0]; rb[i][1] = pB[i][offB]; pB[i] += stepB;
        }
    };

    auto sstore = [&](int st) {
#pragma unroll
        for (int i = 0; i < 4; i++) {
            int e = tid + 256 * i;
            int tg = e & 3, ks = (e >> 2) & 1, m = e >> 3;
            int idx = (((st * 2 + ks) * 128 + m) * 4 + tg) * PK;
            uint32_t ah0 = f2tf32(ra[i][0]), ah1 = f2tf32(ra[i][1]);
            uint32_t bh0 = f2tf32(rb[i][0]), bh1 = f2tf32(rb[i][1]);
            if constexpr (PREC) {
                float4 va, vb;
                va.x = __uint_as_float(ah0); va.y = __uint_as_float(ah1);
                va.z = __uint_as_float(f2tf32(ra[i][0] - __uint_as_float(ah0)));
                va.w = __uint_as_float(f2tf32(ra[i][1] - __uint_as_float(ah1)));
                vb.x = __uint_as_float(bh0); vb.y = __uint_as_float(bh1);
                vb.z = __uint_as_float(f2tf32(rb[i][0] - __uint_as_float(bh0)));
                vb.w = __uint_as_float(f2tf32(rb[i][1] - __uint_as_float(bh1)));
                *reinterpret_cast<float4*>(Ap + idx) = va;
                *reinterpret_cast<float4*>(Bp + idx) = vb;
            } else {
                float2 va, vb;
                va.x = __uint_as_float(ah0); va.y = __uint_as_float(ah1);
                vb.x = __uint_as_float(bh0); vb.y = __uint_as_float(bh1);
                *reinterpret_cast<float2*>(Ap + idx) = va;
                *reinterpret_cast<float2*>(Bp + idx) = vb;
            }
        }
    };

    auto compute_stage = [&](int st) {
#pragma unroll
        for (int ks = 0; ks < 2; ks++) {
            uint32_t af[4][4], bf[4][2];
            uint32_t afl[4][4], bfl[4][2];
            const int base = (st * 2 + ks) * 128;
#pragma unroll
            for (int mi = 0; mi < 4; mi++) {
                int m0 = mbase + mi * 16 + gid;
                if constexpr (PREC) {
                    float4 v0 = reinterpret_cast<const float4*>(Ap)[(base + m0) * 4 + tig];
                    float4 v1 = reinterpret_cast<const float4*>(Ap)[(base + m0 + 8) * 4 + tig];
                    af[mi][0] = __float_as_uint(v0.x); af[mi][2] = __float_as_uint(v0.y);
                    afl[mi][0] = __float_as_uint(v0.z); afl[mi][2] = __float_as_uint(v0.w);
                    af[mi][1] = __float_as_uint(v1.x); af[mi][3] = __float_as_uint(v1.y);
                    afl[mi][1] = __float_as_uint(v1.z); afl[mi][3] = __float_as_uint(v1.w);
                } else {
                    float2 v0 = reinterpret_cast<const float2*>(Ap)[(base + m0) * 4 + tig];
                    float2 v1 = reinterpret_cast<const float2*>(Ap)[(base + m0 + 8) * 4 + tig];
                    af[mi][0] = __float_as_uint(v0.x); af[mi][2] = __float_as_uint(v0.y);
                    af[mi][1] = __float_as_uint(v1.x); af[mi][3] = __float_as_uint(v1.y);
                }
            }
#pragma unroll
            for (int ni = 0; ni < 4; ni++) {
                int n0 = nbase + ni * 8 + gid;
                if constexpr (PREC) {
                    float4 v = reinterpret_cast<const float4*>(Bp)[(base + n0) * 4 + tig];
                    bf[ni][0] = __float_as_uint(v.x); bf[ni][1] = __float_as_uint(v.y);
                    bfl[ni][0] = __float_as_uint(v.z); bfl[ni][1] = __float_as_uint(v.w);
                } else {
                    float2 v = reinterpret_cast<const float2*>(Bp)[(base + n0) * 4 + tig];
                    bf[ni][0] = __float_as_uint(v.x); bf[ni][1] = __float_as_uint(v.y);
                }
            }
#pragma unroll
            for (int mi = 0; mi < 4; mi++)
#pragma unroll
                for (int ni = 0; ni < 4; ni++) {
                    mma_tf32(acc[mi][ni], af[mi], bf[ni]);
                    if constexpr (PREC) {
                        mma_tf32(acc[mi][ni], af[mi], bfl[ni]);
                        mma_tf32(acc[mi][ni], afl[mi], bf[ni]);
                    }
                }
        }
    };

    const int niter = kend / 16;
    gload();
    int st = 0;
    for (int it = 0; it < niter; it++) {
        sstore(st);
        __syncthreads();
        if (it + 1 < niter) gload();
        compute_stage(st);
        __syncthreads();
        st ^= 1;
    }

#pragma unroll
    for (int mi = 0; mi < 4; mi++) {
        int row0 = bm + mbase + mi * 16 + gid;
        int row1 = row0 + 8;
#pragma unroll
        for (int ni = 0; ni < 4; ni++) {
            int col = bn + nbase + ni * 8 + 2 * tig;
            float v0 = alpha * acc[mi][ni][0];
            float v1 = alpha * acc[mi][ni][1];
            float v2 = alpha * acc[mi][ni][2];
            float v3 = alpha * acc[mi][ni][3];
            if (beta != 0.f) {
                v0 += beta * C[(size_t)row0 * ldc + col];
                v1 += beta * C[(size_t)row0 * ldc + col + 1];
                v2 += beta * C[(size_t)row1 * ldc + col];
                v3 += beta * C[(size_t)row1 * ldc + col + 1];
            }
            if (bias) {
                v0 += bias[col]; v1 += bias[col + 1];
                v2 += bias[col]; v3 += bias[col + 1];
            }
            C[(size_t)row0 * ldc + col]     = v0;
            C[(size_t)row0 * ldc + col + 1] = v1;
            C[(size_t)row1 * ldc + col]     = v2;
            C[(size_t)row1 * ldc + col + 1] = v3;
        }
    }
}

// ---------------- top-16 read + softmax + context (warp per row) ------------
__global__ void topk_ctx_kernel(const float* __restrict__ logits,
                                const float* __restrict__ S,
                                float* __restrict__ ctx)
{
    int m = blockIdx.x * 8 + threadIdx.y;
    int lane = threadIdx.x;
    const float* lrow = logits + (size_t)m * CK;
    float v[16];
#pragma unroll
    for (int i = 0; i < 16; i++) v[i] = lrow[i * 32 + lane];
    float topv[CKR]; int topi[CKR];
    for (int it = 0; it < CKR; it++) {
        float bv = -INFINITY; int bi = 0x7fffffff;
#pragma unroll
        for (int i = 0; i < 16; i++) {
            if (v[i] > bv) { bv = v[i]; bi = i * 32 + lane; }
        }
#pragma unroll
        for (int off = 16; off > 0; off >>= 1) {
            float ov = __shfl_xor_sync(0xffffffffu, bv, off);
            int   oi = __shfl_xor_sync(0xffffffffu, bi, off);
            if (ov > bv || (ov == bv && oi < bi)) { bv = ov; bi = oi; }
        }
        topv[it] = bv; topi[it] = bi;
        if ((bi & 31) == lane) v[bi >> 5] = -INFINITY;
    }
    float p[CKR]; float s = 0.f;
#pragma unroll
    for (int i = 0; i < CKR; i++) { p[i] = expf(topv[i] - topv[0]); s += p[i]; }
    float inv = 1.f / s;
    float* crow = ctx + (size_t)m * CD;
    for (int d = lane; d < CD; d += 32) {
        float acc = 0.f;
#pragma unroll
        for (int i = 0; i < CKR; i++)
            acc += p[i] * S[(size_t)topi[i] * CD + d];
        crow[d] = acc * inv;
    }
}

// ---------------- instruction gate ------------------------------------------
__global__ void instr_kernel(const float* __restrict__ Q,
                             const float* __restrict__ Wm,
                             const float* __restrict__ bm_,
                             float* __restrict__ instr)
{
    int m = blockIdx.x * 8 + threadIdx.y;
    int lane = threadIdx.x;
    const float* q = Q + (size_t)m * CD;
    float s = 0.f;
    for (int d = lane; d < CD; d += 32) s = fmaf(q[d], Wm[d], s);
#pragma unroll
    for (int off = 16; off > 0; off >>= 1) s += __shfl_xor_sync(0xffffffffu, s, off);
    if (lane == 0) instr[m] = 1.f / (1.f + expf(-(s + bm_[0])));
}

// ---------------- causal row softmax in place -------------------------------
__global__ void softmax_causal_kernel(float* __restrict__ P)
{
    int b = blockIdx.y, q = blockIdx.x;
    float* row = P + ((size_t)b * CT + q) * CT;
    int n = q + 1;
    int kmax = ((q >> 7) + 1) << 7;
    int tid = threadIdx.x;
    __shared__ float red[256];
    float mx = -INFINITY;
    for (int k = tid; k < n; k += 256) mx = fmaxf(mx, row[k]);
    red[tid] = mx; __syncthreads();
    for (int s = 128; s > 0; s >>= 1) { if (tid < s) red[tid] = fmaxf(red[tid], red[tid + s]); __syncthreads(); }
    mx = red[0]; __syncthreads();
    float sum = 0.f;
    for (int k = tid; k < n; k += 256) { float e = expf(row[k] - mx); row[k] = e; sum += e; }
    red[tid] = sum; __syncthreads();
    for (int s = 128; s > 0; s >>= 1) { if (tid < s) red[tid] += red[tid + s]; __syncthreads(); }
    float inv = 1.f / red[0];
    for (int k = tid; k < n; k += 256) row[k] *= inv;
    for (int k = n + tid; k < kmax; k += 256) row[k] = 0.f;
}

// ---------------- elementwise combine ---------------------------------------
__global__ void combine_kernel(const float* __restrict__ ctx, const float* __restrict__ byp,
                               const float* __restrict__ instr, float* __restrict__ out)
{
    size_t i = (size_t)blockIdx.x * blockDim.x + threadIdx.x;
    if (i >= (size_t)CBT * CD) return;
    float p = instr[i / CD];
    out[i] = (1.f - p) * ctx[i] + p * byp[i];
}

// ---------------- row-normalize S -> Sn -------------------------------------
__global__ void sn_kernel(const float* __restrict__ S, float* __restrict__ Sn)
{
    int r = blockIdx.x * 8 + threadIdx.y;
    int lane = threadIdx.x;
    const float* row = S + (size_t)r * CD;
    float s = 0.f;
    for (int d = lane; d < CD; d += 32) { float v = row[d]; s = fmaf(v, v, s); }
#pragma unroll
    for (int off = 16; off > 0; off >>= 1) s += __shfl_xor_sync(0xffffffffu, s, off);
    float inv = 1.f / fmaxf(sqrtf(s), 1e-8f);
    for (int d = lane; d < CD; d += 32) Sn[(size_t)r * CD + d] = row[d] * inv;
}

// ---------------- V row norms ------------------------------------------------
__global__ void vnorm_kernel(const float* __restrict__ V, float* __restrict__ vn)
{
    int m = blockIdx.x * 8 + threadIdx.y;
    int lane = threadIdx.x;
    const float* row = V + (size_t)m * CD;
    float s = 0.f;
    for (int d = lane; d < CD; d += 32) { float v = row[d]; s = fmaf(v, v, s); }
#pragma unroll
    for (int off = 16; off > 0; off >>= 1) s += __shfl_xor_sync(0xffffffffu, s, off);
    if (lane == 0) vn[m] = sqrtf(s);
}

// ---------------- novelty ----------------------------------------------------
__global__ void novelty_kernel(const float* __restrict__ sim, const float* __restrict__ vn,
                               float* __restrict__ nov)
{
    int m = blockIdx.x * 8 + threadIdx.y;
    int lane = threadIdx.x;
    const float* row = sim + (size_t)m * CK;
    float mx = -INFINITY;
    for (int k = lane; k < CK; k += 32) mx = fmaxf(mx, row[k]);
#pragma unroll
    for (int off = 16; off > 0; off >>= 1) mx = fmaxf(mx, __shfl_xor_sync(0xffffffffu, mx, off));
    if (lane == 0) nov[m] = 1.f - mx / fmaxf(vn[m], 1e-8f);
}

// ---------------- decay weights ---------------------------------------------
__global__ void wt_kernel(float* __restrict__ wt)
{
    int t = blockIdx.x * 256 + threadIdx.x;
    if (t >= CT) return;
    float denom = 1.f - powf(0.99f, (float)CT);
    wt[t] = powf(0.99f, (float)(CT - 1 - t)) * (0.01f / denom);
}

// ---------------- r_write epilogue ------------------------------------------
__global__ void rw_epi_kernel(float* __restrict__ rw, const float* __restrict__ nov,
                              const float* __restrict__ Wn, const float* __restrict__ bn,
                              const float* __restrict__ wt)
{
    size_t i = (size_t)blockIdx.x * blockDim.x + threadIdx.x;
    if (i >= (size_t)CBT * CK) return;
    int m = (int)(i / CK), k = (int)(i % CK);
    float x = rw[i] + nov[m] * Wn[(size_t)k * (CD + 1)] + bn[k];
    rw[i] = (1.f / (1.f + expf(-x))) * wt[m % CT];
}

// ---------------- add eps*I to S_cov ----------------------------------------
__global__ void diag_eps_kernel(float* __restrict__ cov)
{
    int k = blockIdx.x * 256 + threadIdx.x;
    if (k < CK) cov[(size_t)k * CK + k] += 1e-5f;
}

// ---------------- Cholesky diag 128x128: blocked-32 smem-resident ------------
__global__ void chol_diag_kernel(float* __restrict__ Am, int j)
{
    extern __shared__ float As[];           // 128*128
    float* A = Am + (size_t)(j * 128) * CK + j * 128;   // ld = CK
    const int tid = threadIdx.x;
    const int lane = tid & 31;
    const int wid = tid >> 5;
    for (int i = tid; i < 128 * 128; i += 256)
        As[i] = A[(size_t)(i >> 7) * CK + (i & 127)];
    __syncthreads();

#pragma unroll
    for (int jb = 0; jb < 4; jb++) {
        const int base = jb * 32;
        // --- 1. warp 0: factor 32x32 diagonal block via shfl (no barriers) ---
        if (wid == 0) {
            float a[32];
#pragma unroll
            for (int c = 0; c < 32; c++) a[c] = As[(base + lane) * 128 + base + c];
#pragma unroll
            for (int p = 0; p < 32; p++) {
                float d = sqrtf(__shfl_sync(0xffffffffu, a[p], p));
                if (lane > p) a[p] /= d;
                else if (lane == p) a[p] = d;
                float lp = a[p];
#pragma unroll
                for (int c = p + 1; c < 32; c++) {
                    float lcp = __shfl_sync(0xffffffffu, lp, c);
                    if (lane >= c) a[c] -= lp * lcp;
                }
            }
#pragma unroll
            for (int c = 0; c < 32; c++) As[(base + lane) * 128 + base + c] = a[c];
        }
        __syncthreads();

        if (jb < 3) {
            // --- 2. panel TRSM: rows base+32..127, 8 warps x 4 rows ILP ---
            for (int r0 = base + 32 + wid * 4; r0 < 128; r0 += 32) {
                float f0 = As[(r0 + 0) * 128 + base + lane];
                float f1 = As[(r0 + 1) * 128 + base + lane];
                float f2 = As[(r0 + 2) * 128 + base + lane];
                float f3 = As[(r0 + 3) * 128 + base + lane];
#pragma unroll
                for (int c = 0; c < 32; c++) {
                    float Lc = As[(base + c) * 128 + base + lane];
                    float dcc = __shfl_sync(0xffffffffu, Lc, c);
                    bool m = lane < c;
                    float s0 = m ? Lc * f0 : 0.f;
                    float s1 = m ? Lc * f1 : 0.f;
                    float s2 = m ? Lc * f2 : 0.f;
                    float s3 = m ? Lc * f3 : 0.f;
#pragma unroll
                    for (int off = 16; off > 0; off >>= 1) {
                        s0 += __shfl_xor_sync(0xffffffffu, s0, off);
                        s1 += __shfl_xor_sync(0xffffffffu, s1, off);
                        s2 += __shfl_xor_sync(0xffffffffu, s2, off);
                        s3 += __shfl_xor_sync(0xffffffffu, s3, off);
                    }
                    float v0 = (__shfl_sync(0xffffffffu, f0, c) - s0) / dcc;
                    float v1 = (__shfl_sync(0xffffffffu, f1, c) - s1) / dcc;
                    float v2 = (__shfl_sync(0xffffffffu, f2, c) - s2) / dcc;
                    float v3 = (__shfl_sync(0xffffffffu, f3, c) - s3) / dcc;
                    if (lane == c) { f0 = v0; f1 = v1; f2 = v2; f3 = v3; }
                }
                As[(r0 + 0) * 128 + base + lane] = f0;
                As[(r0 + 1) * 128 + base + lane] = f1;
                As[(r0 + 2) * 128 + base + lane] = f2;
                As[(r0 + 3) * 128 + base + lane] = f3;
            }
            __syncthreads();

            // --- 3. trailing update (4x4 register tiles, compile-time w) ---
            const int w = 96 - base;          // 96 / 64 / 32 (const per unrolled jb)
            const int wt = w / 4;
            for (int t = tid; t < wt * wt; t += 256) {
                int tr = t / wt, tc = t % wt;
                int r = base + 32 + tr * 4, c = base + 32 + tc * 4;
                float acc[4][4];
#pragma unroll
                for (int ii = 0; ii < 4; ii++)
#pragma unroll
                    for (int jj = 0; jj < 4; jj++) acc[ii][jj] = 0.f;
#pragma unroll
                for (int q = 0; q < 32; q++) {
                    float lr0 = As[(r + 0) * 128 + base + q];
                    float lr1 = As[(r + 1) * 128 + base + q];
                    float lr2 = As[(r + 2) * 128 + base + q];
                    float lr3 = As[(r + 3) * 128 + base + q];
                    float lc0 = As[(c + 0) * 128 + base + q];
                    float lc1 = As[(c + 1) * 128 + base + q];
                    float lc2 = As[(c + 2) * 128 + base + q];
                    float lc3 = As[(c + 3) * 128 + base + q];
                    acc[0][0] = fmaf(lr0, lc0, acc[0][0]); acc[0][1] = fmaf(lr0, lc1, acc[0][1]);
                    acc[0][2] = fmaf(lr0, lc2, acc[0][2]); acc[0][3] = fmaf(lr0, lc3, acc[0][3]);
                    acc[1][0] = fmaf(lr1, lc0, acc[1][0]); acc[1][1] = fmaf(lr1, lc1, acc[1][1]);
                    acc[1][2] = fmaf(lr1, lc2, acc[1][2]); acc[1][3] = fmaf(lr1, lc3, acc[1][3]);
                    acc[2][0] = fmaf(lr2, lc0, acc[2][0]); acc[2][1] = fmaf(lr2, lc1, acc[2][1]);
                    acc[2][2] = fmaf(lr2, lc2, acc[2][2]); acc[2][3] = fmaf(lr2, lc3, acc[2][3]);
                    acc[3][0] = fmaf(lr3, lc0, acc[3][0]); acc[3][1] = fmaf(lr3, lc1, acc[3][1]);
                    acc[3][2] = fmaf(lr3, lc2, acc[3][2]); acc[3][3] = fmaf(lr3, lc3, acc[3][3]);
                }
#pragma unroll
                for (int ii = 0; ii < 4; ii++)
#pragma unroll
                    for (int jj = 0; jj < 4; jj++)
                        As[(r + ii) * 128 + c + jj] -= acc[ii][jj];
            }
            __syncthreads();
        }
    }

    for (int i = tid; i < 128 * 128; i += 256)
        A[(size_t)(i >> 7) * CK + (i & 127)] = As[i];
}

// ---------------- warp-per-row panel solve (smem-cached L) ------------------
__global__ void chol_trsm_w(float* __restrict__ Am, int j)
{
    extern __shared__ float Ls[];           // 128*128
    const float* L = Am + (size_t)(j * 128) * CK + j * 128;
    int tid = threadIdx.x;
    for (int i = tid; i < 128 * 128; i += 256)
        Ls[i] = L[(size_t)(i >> 7) * CK + (i & 127)];
    __syncthreads();

    int w = blockIdx.x * (blockDim.x >> 5) + (tid >> 5);
    int lane = tid & 31;
    int i = (j + 1) * 128 + w;
    float* row = Am + (size_t)i * CK + j * 128;
    float f[4];
#pragma unroll
    for (int q = 0; q < 4; q++) f[q] = row[lane + 32 * q];
    for (int c = 0; c < 128; c++) {
        const float* Lr = Ls + c * 128;
        float s = 0.f;
#pragma unroll
        for (int q = 0; q < 4; q++) {
            int qq = lane + 32 * q;
            if (qq < c) s = fmaf(Lr[qq], f[q], s);
        }
#pragma unroll
        for (int off = 16; off > 0; off >>= 1) s += __shfl_xor_sync(0xffffffffu, s, off);
        float rc = __shfl_sync(0xffffffffu, f[c >> 5], c & 31);
        float v = (rc - s) / Lr[c];
        if (lane == (c & 31)) f[c >> 5] = v;
    }
#pragma unroll
    for (int q = 0; q < 4; q++) row[lane + 32 * q] = f[q];
}

// ---------------- transpose diagonal L blocks -------------------------------
__global__ void transpose_diag_kernel(const float* __restrict__ cov, float* __restrict__ LT)
{
    int j = blockIdx.y;
    int idx = blockIdx.x * 256 + threadIdx.x;
    int p = idx >> 7, q = idx & 127;
    LT[j * 16384 + idx] = cov[(size_t)(j * 128 + q) * CK + j * 128 + p];
}

// ---------------- warp-per-column forward substitution (smem L) -------------
__global__ void trisolve_fwd_w(const float* __restrict__ Am, float* __restrict__ Zm, int j)
{
    extern __shared__ float Ls[];           // 128*128
    const float* L = Am + (size_t)(j * 128) * CK + j * 128;
    int tid = threadIdx.x;
    for (int i = tid; i < 128 * 128; i += 256)
        Ls[i] = L[(size_t)(i >> 7) * CK + (i & 127)];
    __syncthreads();

    int w = blockIdx.x * (blockDim.x >> 5) + (tid >> 5);   // column
    int lane = tid & 31;
    float* Z = Zm + (size_t)(j * 128) * CD + w;
    float f[4];
#pragma unroll
    for (int q = 0; q < 4; q++) f[q] = Z[(size_t)(lane + 32 * q) * CD];
    for (int p = 0; p < 128; p++) {
        const float* Lr = Ls + p * 128;
        float s = 0.f;
#pragma unroll
        for (int q = 0; q < 4; q++) {
            int qq = lane + 32 * q;
            if (qq < p) s = fmaf(Lr[qq], f[q], s);
        }
#pragma unroll
        for (int off = 16; off > 0; off >>= 1) s += __shfl_xor_sync(0xffffffffu, s, off);
        float zp = __shfl_sync(0xffffffffu, f[p >> 5], p & 31);
        float v = (zp - s) / Lr[p];
        if (lane == (p & 31)) f[p >> 5] = v;
    }
#pragma unroll
    for (int q = 0; q < 4; q++) Z[(size_t)(lane + 32 * q) * CD] = f[q];
}

// ---------------- warp-per-column backward substitution (smem LT) -----------
__global__ void trisolve_bwd_w(const float* __restrict__ LT, float* __restrict__ Zm, int j)
{
    extern __shared__ float Ls[];           // 128*128
    const float* Lt = LT + j * 16384;
    int tid = threadIdx.x;
    for (int i = tid; i < 128 * 128; i += 256) Ls[i] = Lt[i];
    __syncthreads();

    int w = blockIdx.x * (blockDim.x >> 5) + (tid >> 5);   // column
    int lane = tid & 31;
    float* Z = Zm + (size_t)(j * 128) * CD + w;
    float f[4];
#pragma unroll
    for (int q = 0; q < 4; q++) f[q] = Z[(size_t)(lane + 32 * q) * CD];
    for (int p = 127; p >= 0; p--) {
        const float* Lr = Ls + p * 128;
        float s = 0.f;
#pragma unroll
        for (int q = 0; q < 4; q++) {
            int qq = lane + 32 * q;
            if (qq > p) s = fmaf(Lr[qq], f[q], s);
        }
#pragma unroll
        for (int off = 16; off > 0; off >>= 1) s += __shfl_xor_sync(0xffffffffu, s, off);
        float zp = __shfl_sync(0xffffffffu, f[p >> 5], p & 31);
        float v = (zp - s) / Lr[p];
        if (lane == (p & 31)) f[p >> 5] = v;
    }
#pragma unroll
    for (int q = 0; q < 4; q++) Z[(size_t)(lane + 32 * q) * CD] = f[q];
}

// ---------------- misc small kernels ----------------------------------------
__global__ void copy_kernel(const float* __restrict__ a, float* __restrict__ b, int n)
{
    int i = blockIdx.x * 256 + threadIdx.x;
    if (i < n) b[i] = a[i];
}

__global__ void init_out2_kernel(const float* __restrict__ S, const float* __restrict__ Vagg,
                                 float* __restrict__ out2)
{
    size_t i = (size_t)blockIdx.x * blockDim.x + threadIdx.x;
    if (i >= (size_t)CB * CK * CD) return;
    size_t kd = i % ((size_t)CK * CD);
    out2[i] = 0.99f * S[kd] + 0.1f * Vagg[i];
}

// ---------------- host launcher ---------------------------------------------
static void tgemm(cudaStream_t st, bool TA, bool TB, bool prec,
                  const float* A, const float* B, float* C, const float* bias,
                  int M, int N, int Kd, int lda, int ldb, int ldc,
                  long long sA, long long sB, long long sC, int batch,
                  float alpha, float beta, int causal)
{
    dim3 grid(N / 128, M / 128, batch), block(256);
    int smem = prec ? (2 * 2 * 2 * 128 * 4 * 4 * 4) : (2 * 2 * 2 * 128 * 4 * 2 * 4);
#define DISP(ta, tb, pr) do { \
    cudaFuncSetAttribute(tgemm_kernel<ta, tb, pr>, cudaFuncAttributeMaxDynamicSharedMemorySize, smem); \
    tgemm_kernel<ta, tb, pr><<<grid, block, smem, st>>>(A, B, C, bias, M, N, Kd, lda, ldb, ldc, sA, sB, sC, alpha, beta, causal); \
} while (0)
    if (!prec) {
        if (!TA && !TB) DISP(false, false, false);
        else if (!TA && TB) DISP(false, true, false);
        else if (TA && !TB) DISP(true, false, false);
        else DISP(true, true, false);
    } else {
        if (!TA && !TB) DISP(false, false, true);
        else if (!TA && TB) DISP(false, true, true);
        else if (TA && !TB) DISP(true, false, true);
        else DISP(true, true, true);
    }
#undef DISP
}

extern "C" void kernel_launch(void* const* d_in, const int* in_sizes, int n_in,
                              void* d_out, int out_size)
{
    const float* x    = (const float*)d_in[0];
    const float* S    = (const float*)d_in[1];
    const float* Wq_w = (const float*)d_in[2];
    const float* Wq_b = (const float*)d_in[3];
    const float* Wv_w = (const float*)d_in[4];
    const float* Wv_b = (const float*)d_in[5];
    const float* Wn_w = (const float*)d_in[6];
    const float* Wn_b = (const float*)d_in[7];
    const float* Wm_w = (const float*)d_in[8];
    const float* Wm_b = (const float*)d_in[9];
    float* out  = (float*)d_out;                 // [B,T,D]
    float* out2 = out + (size_t)CBT * CD;        // [B,K,D] = S_next

    float *Q, *V, *logits, *sim, *ctx, *scores, *byp, *instr, *nov, *vn, *rw, *Sn, *Vagg, *T1, *cov, *Mm, *wt, *LT;
    cudaGetSymbolAddress((void**)&Q,      g_Q);
    cudaGetSymbolAddress((void**)&V,      g_V);
    cudaGetSymbolAddress((void**)&logits, g_logits);
    cudaGetSymbolAddress((void**)&sim,    g_sim);
    cudaGetSymbolAddress((void**)&ctx,    g_ctx);
    cudaGetSymbolAddress((void**)&scores, g_scores);
    cudaGetSymbolAddress((void**)&byp,    g_byp);
    cudaGetSymbolAddress((void**)&instr,  g_instr);
    cudaGetSymbolAddress((void**)&nov,    g_nov);
    cudaGetSymbolAddress((void**)&vn,     g_vnorm);
    cudaGetSymbolAddress((void**)&rw,     g_rw);
    cudaGetSymbolAddress((void**)&Sn,     g_Sn);
    cudaGetSymbolAddress((void**)&Vagg,   g_Vagg);
    cudaGetSymbolAddress((void**)&T1,     g_T1);
    cudaGetSymbolAddress((void**)&cov,    g_cov);
    cudaGetSymbolAddress((void**)&Mm,     g_Mm);
    cudaGetSymbolAddress((void**)&wt,     g_wt);
    cudaGetSymbolAddress((void**)&LT,     g_LT);

    static cudaStream_t sV = nullptr, sS = nullptr;
    static cudaEvent_t eFork = nullptr, eV = nullptr, eSn = nullptr, eNov = nullptr, eMm = nullptr;
    if (!sV) {
        cudaStreamCreateWithFlags(&sV, cudaStreamNonBlocking);
        cudaStreamCreateWithFlags(&sS, cudaStreamNonBlocking);
        cudaEventCreateWithFlags(&eFork, cudaEventDisableTiming);
        cudaEventCreateWithFlags(&eV,    cudaEventDisableTiming);
        cudaEventCreateWithFlags(&eSn,   cudaEventDisableTiming);
        cudaEventCreateWithFlags(&eNov,  cudaEventDisableTiming);
        cudaEventCreateWithFlags(&eMm,   cudaEventDisableTiming);
    }

    const float inv_sqrt_d = 0.03125f;   // 1/sqrt(1024)
    const cudaStream_t M0 = 0;
    const int SOLVE_SMEM = 128 * 128 * 4;
    cudaFuncSetAttribute(chol_diag_kernel,  cudaFuncAttributeMaxDynamicSharedMemorySize, SOLVE_SMEM);
    cudaFuncSetAttribute(chol_trsm_w,       cudaFuncAttributeMaxDynamicSharedMemorySize, SOLVE_SMEM);
    cudaFuncSetAttribute(trisolve_fwd_w,    cudaFuncAttributeMaxDynamicSharedMemorySize, SOLVE_SMEM);
    cudaFuncSetAttribute(trisolve_bwd_w,    cudaFuncAttributeMaxDynamicSharedMemorySize, SOLVE_SMEM);

    // ================= fork =================
    cudaEventRecord(eFork, M0);
    cudaStreamWaitEvent(sV, eFork, 0);
    cudaStreamWaitEvent(sS, eFork, 0);

    // ---- stream sS: S-only chain (Sn, cov, chol, Mm) ------------------------
    sn_kernel<<<CK / 8, dim3(32, 8), 0, sS>>>(S, Sn);
    cudaEventRecord(eSn, sS);
    tgemm(sS, false, true, true, S, S, cov, nullptr, CK, CK, CD, CD, CD, CK, 0, 0, 0, 1, 1.f, 0.f, 0);
    diag_eps_kernel<<<2, 256, 0, sS>>>(cov);
    for (int j = 0; j < 4; j++) {
        chol_diag_kernel<<<1, 256, SOLVE_SMEM, sS>>>(cov, j);
        if (j < 3) {
            int rows = (3 - j) * 128;
            chol_trsm_w<<<rows / 8, 256, SOLVE_SMEM, sS>>>(cov, j);
            float* Ct = cov + (size_t)(j + 1) * 128 * CK + (j + 1) * 128;
            const float* P = cov + (size_t)(j + 1) * 128 * CK + j * 128;
            tgemm(sS, false, true, true, P, P, Ct, nullptr, rows, rows, 128, CK, CK, CK, 0, 0, 0, 1, -1.f, 1.f, 0);
        }
    }
    transpose_diag_kernel<<<dim3(64, 4), 256, 0, sS>>>(cov, LT);
    copy_kernel<<<(CK * CD + 255) / 256, 256, 0, sS>>>(S, Mm, CK * CD);
    for (int j = 0; j < 4; j++) {
        if (j > 0)
            tgemm(sS, false, false, true, cov + (size_t)j * 128 * CK, Mm, Mm + (size_t)j * 128 * CD, nullptr,
                  128, CD, j * 128, CK, CD, CD, 0, 0, 0, 1, -1.f, 1.f, 0);
        trisolve_fwd_w<<<CD / 8, 256, SOLVE_SMEM, sS>>>(cov, Mm, j);
    }
    for (int j = 3; j >= 0; j--) {
        if (j < 3) {
            int s = (3 - j) * 128;
            tgemm(sS, true, false, true, cov + (size_t)(j + 1) * 128 * CK + j * 128, Mm + (size_t)(j + 1) * 128 * CD,
                  Mm + (size_t)j * 128 * CD, nullptr, 128, CD, s, CK, CD, CD, 0, 0, 0, 1, -1.f, 1.f, 0);
        }
        trisolve_bwd_w<<<CD / 8, 256, SOLVE_SMEM, sS>>>(LT, Mm, j);
    }
    cudaEventRecord(eMm, sS);

    // ---- stream sV: V projection + novelty chain ----------------------------
    tgemm(sV, false, true, false, x, Wv_w, V, Wv_b, CBT, CD, CD, CD, CD, CD, 0, 0, 0, 1, 1.f, 0.f, 0);
    cudaEventRecord(eV, sV);
    vnorm_kernel<<<CBT / 8, dim3(32, 8), 0, sV>>>(V, vn);
    cudaStreamWaitEvent(sV, eSn, 0);
    tgemm(sV, false, true, false, V, Sn, sim, nullptr, CBT, CK, CD, CD, CD, CK, 0, 0, 0, 1, 1.f, 0.f, 0);
    novelty_kernel<<<CBT / 8, dim3(32, 8), 0, sV>>>(sim, vn, nov);
    cudaEventRecord(eNov, sV);

    // ---- main stream: Q chain, attention, write path ------------------------
    wt_kernel<<<CT / 256, 256, 0, M0>>>(wt);
    tgemm(M0, false, true, true, x, Wq_w, Q, Wq_b, CBT, CD, CD, CD, CD, CD, 0, 0, 0, 1, 1.f, 0.f, 0);
    instr_kernel<<<CBT / 8, dim3(32, 8), 0, M0>>>(Q, Wm_w, Wm_b, instr);
    tgemm(M0, false, true, true, Q, S, logits, nullptr, CBT, CK, CD, CD, CD, CK, 0, 0, 0, 1, inv_sqrt_d, 0.f, 0);
    topk_ctx_kernel<<<CBT / 8, dim3(32, 8), 0, M0>>>(logits, S, ctx);
    tgemm(M0, false, true, false, Q, Q, scores, nullptr, CT, CT, CD, CD, CD, CT,
          (long long)CT * CD, (long long)CT * CD, (long long)CT * CT, CB, inv_sqrt_d, 0.f, 1);
    softmax_causal_kernel<<<dim3(CT, CB), 256, 0, M0>>>(scores);
    tgemm(M0, false, true, false, Q, Wn_w + 1, rw, nullptr, CBT, CK, CD, CD, CD + 1, CK, 0, 0, 0, 1, 1.f, 0.f, 0);
    cudaStreamWaitEvent(M0, eV, 0);
    tgemm(M0, false, false, false, scores, V, byp, nullptr, CT, CD, CT, CT, CD, CD,
          (long long)CT * CT, (long long)CT * CD, (long long)CT * CD, CB, 1.f, 0.f, 2);
    combine_kernel<<<(CBT * CD + 255) / 256, 256, 0, M0>>>(ctx, byp, instr, out);
    cudaStreamWaitEvent(M0, eNov, 0);
    rw_epi_kernel<<<(CBT * CK + 255) / 256, 256, 0, M0>>>(rw, nov, Wn_w, Wn_b, wt);
    tgemm(M0, true, false, false, rw, V, Vagg, nullptr, CK, CD, CT, CK, CD, CD,
          (long long)CT * CK, (long long)CT * CD, (long long)CK * CD, CB, 1.f, 0.f, 0);
    tgemm(M0, false, true, true, Vagg, S, T1, nullptr, CK, CK, CD, CD, CD, CK,
          (long long)CK * CD, 0, (long long)CK * CK, CB, 1.f, 0.f, 0);
    init_out2_kernel<<<(CB * CK * CD + 255) / 256, 256, 0, M0>>>(S, Vagg, out2);
    cudaStreamWaitEvent(M0, eMm, 0);
    tgemm(M0, false, false, true, T1, Mm, out2, nullptr, CK, CD, CK, CK, CD, CD,
          (long long)CK * CK, 0, (long long)CK * CD, CB, -0.1f, 1.f, 0);
}